// round 7
// baseline (speedup 1.0000x reference)
#include <cuda_runtime.h>
#include <cuda_bf16.h>
#include <math.h>

// ---------------------------------------------------------------------------
// SparseConvNet: 6 partial-conv layers. N=4, H=W=1024.
// Layers: (1,16,11)(16,16,7)(16,16,5)(16,16,3)(16,16,3)(16,1,1)
// Round 7: warp-level tensor cores (ldmatrix + mma.sync bf16, plain sm_103 —
// tcgen05 is sm_103a-gated and unavailable). Implicit-GEMM conv: one smem
// window serves all K*K taps by ldmatrix address offset; fp32 via 3-term
// bf16 hi/lo split. Layer 1 (cin=1) stays on the proven scalar FFMA2 path.
// ---------------------------------------------------------------------------

#define HW   (1024 * 1024)
#define IMW  1024
#define NPIX (4LL * HW)

__device__ float  g_h0[4 * 16 * HW];
__device__ float  g_h1[4 * 16 * HW];
__device__ float  g_m0[4 * HW];
__device__ float  g_m1[4 * HW];
__device__ double g_stats[6 * 32];
__device__ float2 g_affine[6 * 16];

typedef unsigned long long u64;
typedef unsigned int u32;
typedef unsigned short u16;

__device__ __forceinline__ u64 dup2(float v) {
    u64 r;
    asm("mov.b64 %0, {%1, %1};" : "=l"(r) : "f"(v));
    return r;
}
__device__ __forceinline__ void fma2(u64& d, u64 a, u64 b) {
    asm("fma.rn.f32x2 %0, %1, %2, %0;" : "+l"(d) : "l"(a), "l"(b));
}
__device__ __forceinline__ void unpk(float& lo, float& hi, u64 v) {
    asm("mov.b64 {%0, %1}, %2;" : "=f"(lo), "=f"(hi) : "l"(v));
}
__device__ __forceinline__ u32 smem_u32(const void* p) {
    u32 a;
    asm("{ .reg .u64 t; cvta.to.shared.u64 t, %1; cvt.u32.u64 %0, t; }"
        : "=r"(a) : "l"(p));
    return a;
}
__device__ __forceinline__ void ldsm4(u32& r0, u32& r1, u32& r2, u32& r3, u32 a) {
    asm volatile("ldmatrix.sync.aligned.m8n8.x4.shared.b16 {%0,%1,%2,%3}, [%4];"
                 : "=r"(r0), "=r"(r1), "=r"(r2), "=r"(r3) : "r"(a));
}
__device__ __forceinline__ void mma16816(float* d, u32 a0, u32 a1, u32 a2, u32 a3,
                                         u32 b0, u32 b1) {
    asm volatile(
        "mma.sync.aligned.m16n8k16.row.col.f32.bf16.bf16.f32 "
        "{%0,%1,%2,%3}, {%4,%5,%6,%7}, {%8,%9}, {%0,%1,%2,%3};"
        : "+f"(d[0]), "+f"(d[1]), "+f"(d[2]), "+f"(d[3])
        : "r"(a0), "r"(a1), "r"(a2), "r"(a3), "r"(b0), "r"(b1));
}
__device__ __forceinline__ void bsplit(float t, u16& h, u16& l) {
    __nv_bfloat16 bh = __float2bfloat16(t);
    float fh = __bfloat162float(bh);
    __nv_bfloat16 bl = __float2bfloat16(t - fh);
    h = __bfloat16_as_ushort(bh);
    l = __bfloat16_as_ushort(bl);
}
__device__ __forceinline__ uint4 pack8(const u16* s) {
    return make_uint4((u32)s[0] | ((u32)s[1] << 16), (u32)s[2] | ((u32)s[3] << 16),
                      (u32)s[4] | ((u32)s[5] << 16), (u32)s[6] | ((u32)s[7] << 16));
}

__global__ void zero_stats_k() {
    if (threadIdx.x < 6 * 32) g_stats[threadIdx.x] = 0.0;
}

__global__ void affine_k(const double* __restrict__ st,
                         const float* __restrict__ gam,
                         const float* __restrict__ bet,
                         float2* __restrict__ ab, int nch) {
    int c = threadIdx.x;
    if (c >= nch) return;
    double mean = st[c] / (double)NPIX;
    double var  = st[16 + c] / (double)NPIX - mean * mean;
    float inv = rsqrtf((float)var + 1e-5f);
    float a = gam[c] * inv;
    ab[c] = make_float2(a, bet[c] - (float)mean * a);
}

// ---------------------------------------------------------------------------
// Tensor-core partial-conv layer (cin=cout=16). Tile = 128 px * TY=2 rows,
// 256 threads / 8 warps; warp w owns 16-px segment w, loops y.
// A smem: [R rows][NPXW px][16 ci] bf16, hi & lo copies. Tap (dy,dx) MMA uses
// ldmatrix at base + dy*rowpitch + dx*32. B smem: per tap [co][ci] bf16 hi/lo.
// Per tap: 1 B-ldsm.x4 per half, per y: A-ldsm.x4 hi+lo, 6 mma (2 ntiles x 3).
// ---------------------------------------------------------------------------
template <int K, bool AFF>
__global__ void __launch_bounds__(256) tmma_conv_k(
    const float* __restrict__ in, long long inNS,
    const float* __restrict__ mk, long long mkNS,
    const float* __restrict__ wG, const float* __restrict__ bias,
    const float2* __restrict__ aff,
    float* __restrict__ outH, float* __restrict__ outM,
    double* __restrict__ stats) {
    constexpr int TY = 2, P = K / 2;
    constexpr int NPX = 128 + K - 1;
    constexpr int NPXW = (NPX + 7) & ~7;
    constexpr int R = K + TY - 1;
    constexpr int ROWB = NPXW * 32;              // bytes per A row
    constexpr int NT = K * K;
    constexpr int SR_OFF = 0;                    // 1024B stats reduce
    constexpr int MK_OFF = 1024;                 // mask floats
    constexpr int AH_OFF = ((MK_OFF + R * NPXW * 4 + 127) / 128) * 128;
    constexpr int AL_OFF = AH_OFF + R * ROWB;
    constexpr int BH_OFF = AL_OFF + R * ROWB;
    constexpr int BL_OFF = BH_OFF + NT * 512;

    extern __shared__ char smx[];
    float* sR  = (float*)(smx + SR_OFF);
    float* sMk = (float*)(smx + MK_OFF);
    const u32 sb = smem_u32(smx);

    const int tid = threadIdx.x;
    const int wid = tid >> 5;
    const int lane = tid & 31;
    const int n  = blockIdx.z;
    const int x0 = blockIdx.x * 128;
    const int y0 = blockIdx.y * TY;

    // ---- mask window ----
    const float* mkn = mk + (long long)n * mkNS;
    for (int i = tid; i < R * NPXW; i += 256) {
        int r = i / NPXW, p = i - r * NPXW;
        int gy = y0 - P + r, gx = x0 - P + p;
        float m = 0.f;
        if ((unsigned)gy < 1024u && (unsigned)gx < 1024u) m = mkn[gy * IMW + gx];
        sMk[i] = m;
    }
    __syncthreads();

    // ---- stage A (masked + affine + relu, bf16 hi/lo) ----
    float2 abr[16];
#pragma unroll
    for (int ci = 0; ci < 16; ci++)
        abr[ci] = AFF ? aff[ci] : make_float2(1.f, 0.f);
    const float* inn = in + (long long)n * inNS;
    for (int i = tid; i < R * NPX; i += 256) {
        int r = i / NPX, p = i - r * NPX;
        int gy = y0 - P + r, gx = x0 - P + p;
        bool ok = (unsigned)gy < 1024u && (unsigned)gx < 1024u;
        float m = sMk[r * NPXW + p];
        const float* ip = inn + (long long)gy * IMW + gx;
        u16 hs[16], ls[16];
#pragma unroll
        for (int ci = 0; ci < 16; ci++) {
            float v = ok ? ip[(long long)ci * HW] : 0.f;
            if (AFF) v = fmaxf(fmaf(v, abr[ci].x, abr[ci].y), 0.f);
            bsplit(v * m, hs[ci], ls[ci]);
        }
        char* ah = smx + AH_OFF + r * ROWB + p * 32;
        char* al = smx + AL_OFF + r * ROWB + p * 32;
        *(uint4*)ah = pack8(hs);
        *(uint4*)(ah + 16) = pack8(hs + 8);
        *(uint4*)al = pack8(ls);
        *(uint4*)(al + 16) = pack8(ls + 8);
    }
    // ---- stage B: per tap [co(16)][ci(16)] bf16, hi and lo ----
    for (int i = tid; i < NT * 256; i += 256) {
        int tap = i >> 8, rem = i & 255;
        int ci = rem >> 4, co = rem & 15;
        int dy = tap / K, dx = tap - dy * K;
        float w = wG[((co * 16 + ci) * K + dy) * K + dx];
        u16 wh, wl;
        bsplit(w, wh, wl);
        *(u16*)(smx + BH_OFF + tap * 512 + co * 32 + ci * 2) = wh;
        *(u16*)(smx + BL_OFF + tap * 512 + co * 32 + ci * 2) = wl;
    }
    __syncthreads();

    // ---- MMA mainloop ----
    const int seg = wid;                 // 16-px segment
    float D[TY][2][4];
#pragma unroll
    for (int y = 0; y < TY; y++)
#pragma unroll
        for (int t = 0; t < 2; t++)
#pragma unroll
            for (int j = 0; j < 4; j++) D[y][t][j] = 0.f;

    const u32 aoff = (u32)((seg * 16 + (lane & 15)) * 32 + (lane >> 4) * 16);
    const u32 aBaseH = sb + AH_OFF + aoff;
    const u32 aBaseL = sb + AL_OFF + aoff;
    const u32 boff = (u32)((((lane & 7) + ((lane >> 4) << 3)) * 32) +
                           (((lane >> 3) & 1) * 16));
    const u32 bBaseH = sb + BH_OFF + boff;
    const u32 bBaseL = sb + BL_OFF + boff;

#pragma unroll 1
    for (int tap = 0; tap < NT; tap++) {
        int dy = tap / K, dx = tap - dy * K;
        u32 bh0, bh1, bh2, bh3, bl0, bl1, bl2, bl3;
        ldsm4(bh0, bh1, bh2, bh3, bBaseH + tap * 512);
        ldsm4(bl0, bl1, bl2, bl3, bBaseL + tap * 512);
#pragma unroll
        for (int y = 0; y < TY; y++) {
            u32 ao = (u32)((y + dy) * ROWB + dx * 32);
            u32 h0, h1, h2, h3, l0, l1, l2, l3;
            ldsm4(h0, h1, h2, h3, aBaseH + ao);
            ldsm4(l0, l1, l2, l3, aBaseL + ao);
            mma16816(D[y][0], h0, h1, h2, h3, bh0, bh1);
            mma16816(D[y][1], h0, h1, h2, h3, bh2, bh3);
            mma16816(D[y][0], l0, l1, l2, l3, bh0, bh1);
            mma16816(D[y][1], l0, l1, l2, l3, bh2, bh3);
            mma16816(D[y][0], h0, h1, h2, h3, bl0, bl1);
            mma16816(D[y][1], h0, h1, h2, h3, bl2, bl3);
        }
    }

    // ---- mask-sum conv + maxpool: lane task (yl, pxl) ----
    const int yl = lane >> 4, pxl = lane & 15;
    float s = 0.f, mm = 0.f;
    {
        const float* mb = sMk + yl * NPXW + seg * 16 + pxl;
#pragma unroll 1
        for (int dy = 0; dy < K; dy++)
#pragma unroll
            for (int dx = 0; dx < K; dx++) {
                float m = mb[dy * NPXW + dx];
                s += m;
                mm = fmaxf(mm, m);
            }
    }
    float invv = 1.0f / (s + 1e-8f);
    outM[(long long)n * HW + (long long)(y0 + yl) * IMW + x0 + seg * 16 + pxl] = mm;

    // ---- epilogue: scale, bias, store, stats ----
    float bco[4][2];
#pragma unroll
    for (int t = 0; t < 2; t++)
#pragma unroll
        for (int j = 0; j < 2; j++)
            bco[t * 2 + j][0] = bias[t * 8 + (lane & 3) * 2 + j];
    float p1[4] = {0.f, 0.f, 0.f, 0.f}, p2[4] = {0.f, 0.f, 0.f, 0.f};
    const int pxa = seg * 16 + (lane >> 2);

#pragma unroll
    for (int y = 0; y < TY; y++) {
        float inva = __shfl_sync(0xffffffffu, invv, y * 16 + (lane >> 2));
        float invb = __shfl_sync(0xffffffffu, invv, y * 16 + (lane >> 2) + 8);
        int gy = y0 + y;
        float* hb = outH + (long long)n * 16 * HW + (long long)gy * IMW + x0;
#pragma unroll
        for (int t = 0; t < 2; t++) {
#pragma unroll
            for (int j = 0; j < 2; j++) {
                int co = t * 8 + (lane & 3) * 2 + j;
                float bc = bco[t * 2 + j][0];
                float v0 = fmaf(D[y][t][j], inva, bc);
                float v1 = fmaf(D[y][t][j + 2], invb, bc);
                hb[(long long)co * HW + pxa] = v0;
                hb[(long long)co * HW + pxa + 8] = v1;
                p1[t * 2 + j] += v0 + v1;
                p2[t * 2 + j] = fmaf(v0, v0, fmaf(v1, v1, p2[t * 2 + j]));
            }
        }
    }
#pragma unroll
    for (int k = 0; k < 4; k++) {
#pragma unroll
        for (int o = 4; o < 32; o <<= 1) {
            p1[k] += __shfl_xor_sync(0xffffffffu, p1[k], o);
            p2[k] += __shfl_xor_sync(0xffffffffu, p2[k], o);
        }
    }
    if (lane < 4) {
#pragma unroll
        for (int t = 0; t < 2; t++)
#pragma unroll
            for (int j = 0; j < 2; j++) {
                int co = t * 8 + lane * 2 + j;
                sR[(co * 2 + 0) * 8 + wid] = p1[t * 2 + j];
                sR[(co * 2 + 1) * 8 + wid] = p2[t * 2 + j];
            }
    }
    __syncthreads();
    if (tid < 32) {
        int co = tid >> 1, which = tid & 1;
        float v = 0.f;
#pragma unroll
        for (int w = 0; w < 8; w++) v += sR[tid * 8 + w];
        atomicAdd(&stats[which * 16 + co], (double)v);
    }
}

// ---------------------------------------------------------------------------
// Scalar FFMA2 partial-conv (R3-proven) — used for layer 1 (cin=1, K=11).
// ---------------------------------------------------------------------------
template <int K, int CIN, int CH, bool AFF>
__global__ void __launch_bounds__(128, 4) sconv_k(
    const float* __restrict__ in, long long inNS,
    const float* __restrict__ mk, long long mkNS,
    const float* __restrict__ wG, const float* __restrict__ bias,
    const float2* __restrict__ aff,
    float* __restrict__ outH, float* __restrict__ outM,
    double* __restrict__ stats) {
    constexpr int TX = 32, TY = 16, P = K / 2;
    constexpr int IW = TX + K - 1;
    constexpr int IH = TY + K - 1;
    constexpr int IHP = IH | 1;
    constexpr int SMN = IH * IW;
    constexpr int SXN = CH * IW * IHP;
    constexpr int SWOFF = ((SMN + SXN + 3) / 4) * 4;
    constexpr int SWN = CH * K * K * 16;

    extern __shared__ float sm[];
    float* sMk = sm;
    float* sX  = sm + SMN;
    float* sW  = sm + SWOFF;
    float* sR  = sm + SWOFF + SWN;

    const int tid = threadIdx.x;
    const int n = blockIdx.z;
    const int x0 = blockIdx.x * TX - P;
    const int y0 = blockIdx.y * TY - P;

    const float* mkn = mk + (long long)n * mkNS;
    for (int i = tid; i < SMN; i += 128) {
        int ly = i / IW, lx = i - ly * IW;
        int gy = y0 + ly, gx = x0 + lx;
        float m = 0.f;
        if ((unsigned)gy < 1024u && (unsigned)gx < 1024u) m = mkn[gy * IMW + gx];
        sMk[i] = m;
    }

    const int tx = tid & 31;
    const int tq = tid >> 5;
    const float* inn = in + (long long)n * inNS;

    u64 acc2[32];
#pragma unroll
    for (int i = 0; i < 32; i++) acc2[i] = 0ull;

    for (int c0 = 0; c0 < CIN; c0 += CH) {
        __syncthreads();
        float2 abr2[CH];
#pragma unroll
        for (int ci = 0; ci < CH; ci++)
            abr2[ci] = AFF ? aff[c0 + ci] : make_float2(1.f, 0.f);
        const float* ipc = inn + (long long)c0 * HW;
        for (int i = tid; i < SMN; i += 128) {
            int ly = i / IW, lx = i - ly * IW;
            int gy = y0 + ly, gx = x0 + lx;
            bool ok = (unsigned)gy < 1024u && (unsigned)gx < 1024u;
            float m = sMk[i];
            int so = lx * IHP + ly;
            const float* p = ipc + (long long)gy * IMW + gx;
            float v[CH];
#pragma unroll
            for (int ci = 0; ci < CH; ci++) {
                v[ci] = 0.f;
                if (ok) v[ci] = p[(long long)ci * HW];
            }
#pragma unroll
            for (int ci = 0; ci < CH; ci++) {
                float t = v[ci];
                if (AFF) t = fmaxf(fmaf(t, abr2[ci].x, abr2[ci].y), 0.f);
                sX[ci * SMN + so] = t * m;   // note: col-major slot below
            }
        }
        // fix: column-major layout uses IW*IHP per channel
        __syncthreads();
        __syncthreads();
        (void)0;
        // (kept structurally identical to R3: sX[ci*(IW*IHP)+so])
        // -- see staging above: SMN == IH*IW >= IW*IHP? use proper region --
        for (int i = tid; i < SWN; i += 128) {
            int co = i & 15;
            int rest = i >> 4;
            sW[i] = wG[co * (CIN * K * K) + c0 * (K * K) + rest];
        }
        __syncthreads();

#pragma unroll 1
        for (int ci = 0; ci < CH; ci++) {
            const float* colbase = sX + ci * SMN + tx * IHP + tq * 4;
            const float* wbase = sW + ci * (K * K * 16);
#pragma unroll 1
            for (int dx = 0; dx < K; dx++) {
                const float* colp = colbase + dx * IHP;
                u64 vv[K + 3];
#pragma unroll
                for (int j = 0; j < K + 3; j++) vv[j] = dup2(colp[j]);
#pragma unroll
                for (int dy = 0; dy < K; dy++) {
                    const ulonglong2* wq =
                        (const ulonglong2*)(wbase + (dy * K + dx) * 16);
                    ulonglong2 wa = wq[0];
                    ulonglong2 wb = wq[1];
                    ulonglong2 wc = wq[2];
                    ulonglong2 wd = wq[3];
#pragma unroll
                    for (int py = 0; py < 4; py++) {
                        u64 v = vv[dy + py];
                        fma2(acc2[0 * 4 + py], v, wa.x);
                        fma2(acc2[1 * 4 + py], v, wa.y);
                        fma2(acc2[2 * 4 + py], v, wb.x);
                        fma2(acc2[3 * 4 + py], v, wb.y);
                        fma2(acc2[4 * 4 + py], v, wc.x);
                        fma2(acc2[5 * 4 + py], v, wc.y);
                        fma2(acc2[6 * 4 + py], v, wd.x);
                        fma2(acc2[7 * 4 + py], v, wd.y);
                    }
                }
            }
        }
    }

    float s[4] = {0.f, 0.f, 0.f, 0.f};
    float mm[4] = {0.f, 0.f, 0.f, 0.f};
    {
        const float* mb = sMk + (tq * 4) * IW + tx;
#pragma unroll 1
        for (int dy = 0; dy < K; dy++)
#pragma unroll
            for (int dx = 0; dx < K; dx++)
#pragma unroll
                for (int py = 0; py < 4; py++) {
                    float m = mb[(dy + py) * IW + dx];
                    s[py] += m;
                    mm[py] = fmaxf(mm[py], m);
                }
    }
    float inv[4];
#pragma unroll
    for (int py = 0; py < 4; py++) inv[py] = 1.0f / (s[py] + 1e-8f);

    const int gy = blockIdx.y * TY + tq * 4;
    const int gx = blockIdx.x * TX + tx;

    float* mo = outM + (long long)n * HW + gy * IMW + gx;
#pragma unroll
    for (int py = 0; py < 4; py++) mo[py * IMW] = mm[py];

    float* ho = outH + ((long long)n * 16) * HW + gy * IMW + gx;
    const int lane = tid & 31;
    const int warp = tid >> 5;
#pragma unroll
    for (int cp = 0; cp < 8; cp++) {
        float b0 = bias[2 * cp], b1 = bias[2 * cp + 1];
        float p1a = 0.f, p2a = 0.f, p1b = 0.f, p2b = 0.f;
#pragma unroll
        for (int py = 0; py < 4; py++) {
            float a0, a1;
            unpk(a0, a1, acc2[cp * 4 + py]);
            float y0v = fmaf(a0, inv[py], b0);
            float y1v = fmaf(a1, inv[py], b1);
            ho[(long long)(2 * cp) * HW + py * IMW] = y0v;
            ho[(long long)(2 * cp + 1) * HW + py * IMW] = y1v;
            p1a += y0v; p2a = fmaf(y0v, y0v, p2a);
            p1b += y1v; p2b = fmaf(y1v, y1v, p2b);
        }
#pragma unroll
        for (int o = 16; o; o >>= 1) {
            p1a += __shfl_xor_sync(0xffffffffu, p1a, o);
            p2a += __shfl_xor_sync(0xffffffffu, p2a, o);
            p1b += __shfl_xor_sync(0xffffffffu, p1b, o);
            p2b += __shfl_xor_sync(0xffffffffu, p2b, o);
        }
        if (lane == 0) {
            sR[(2 * cp * 2 + 0) * 4 + warp] = p1a;
            sR[(2 * cp * 2 + 1) * 4 + warp] = p2a;
            sR[((2 * cp + 1) * 2 + 0) * 4 + warp] = p1b;
            sR[((2 * cp + 1) * 2 + 1) * 4 + warp] = p2b;
        }
    }
    __syncthreads();
    if (tid < 32) {
        float v = sR[tid * 4 + 0] + sR[tid * 4 + 1] + sR[tid * 4 + 2] + sR[tid * 4 + 3];
        int co = tid >> 1, which = tid & 1;
        atomicAdd(&stats[which * 16 + co], (double)v);
    }
}

// ---------------------------------------------------------------------------
__global__ void conv1x1_k(const float* __restrict__ h,
                          const float* __restrict__ mk,
                          const float* __restrict__ w6,
                          const float* __restrict__ b6,
                          const float2* __restrict__ aff,
                          float* __restrict__ y,
                          double* __restrict__ stats) {
    __shared__ float swv[16];
    __shared__ float2 sab[16];
    __shared__ float r1[8], r2[8];
    if (threadIdx.x < 16) {
        swv[threadIdx.x] = w6[threadIdx.x];
        sab[threadIdx.x] = aff[threadIdx.x];
    }
    __syncthreads();
    float bb = b6[0];
    float p1 = 0.f, p2 = 0.f;
    for (long long i = (long long)blockIdx.x * blockDim.x + threadIdx.x;
         i < 4LL * HW; i += (long long)gridDim.x * blockDim.x) {
        long long n = i >> 20;
        long long p = i & (HW - 1);
        float m = mk[i];
        float accv = 0.f;
#pragma unroll
        for (int c = 0; c < 16; c++) {
            float v = h[(n * 16 + c) * HW + p];
            float2 ab = sab[c];
            v = fmaxf(fmaf(v, ab.x, ab.y), 0.f);
            accv = fmaf(swv[c], v, accv);
        }
        float r = 1.0f / (m + 1e-8f);
        float yv = fmaf(accv * m, r, bb);
        y[i] = yv;
        p1 += yv;
        p2 = fmaf(yv, yv, p2);
    }
#pragma unroll
    for (int o = 16; o; o >>= 1) {
        p1 += __shfl_xor_sync(0xffffffffu, p1, o);
        p2 += __shfl_xor_sync(0xffffffffu, p2, o);
    }
    int warp = threadIdx.x >> 5, lane = threadIdx.x & 31;
    if (lane == 0) { r1[warp] = p1; r2[warp] = p2; }
    __syncthreads();
    if (threadIdx.x == 0) {
        float a = 0.f, b = 0.f;
        for (int w = 0; w < (int)(blockDim.x >> 5); w++) { a += r1[w]; b += r2[w]; }
        atomicAdd(&stats[0], (double)a);
        atomicAdd(&stats[16], (double)b);
    }
}

__global__ void final_k(const float* __restrict__ y,
                        const float2* __restrict__ ab,
                        float* __restrict__ o) {
    float2 t = ab[0];
    for (long long i = (long long)blockIdx.x * blockDim.x + threadIdx.x;
         i < 4LL * HW; i += (long long)gridDim.x * blockDim.x)
        o[i] = fmaf(y[i], t.x, t.y);
}

// ---------------------------------------------------------------------------
static constexpr int sconv_smem(int K, int CH) {
    int IW = 32 + K - 1, IH = 16 + K - 1;
    int IHP = IH | 1;
    int smn = IH * IW;
    int sxn = CH * IW * IHP;
    (void)IHP;
    int swoff = ((smn + ((sxn > smn * CH) ? sxn : smn * CH) + 3) / 4) * 4;
    return (swoff + CH * K * K * 16 + 128) * 4;
}
static constexpr int tmma_smem(int K) {
    int TY = 2, NPX = 128 + K - 1, NPXW = (NPX + 7) & ~7, R = K + TY - 1;
    int AH = ((1024 + R * NPXW * 4 + 127) / 128) * 128;
    return AH + 2 * R * NPXW * 32 + 2 * K * K * 512;
}

extern "C" void kernel_launch(void* const* d_in, const int* in_sizes, int n_in,
                              void* d_out, int out_size) {
    (void)in_sizes; (void)n_in; (void)out_size;
    const float* x = (const float*)d_in[0];
    const float *wp[6], *bp[6], *gp[6], *btp[6];
    for (int i = 0; i < 6; i++) {
        wp[i]  = (const float*)d_in[1 + 4 * i];
        bp[i]  = (const float*)d_in[2 + 4 * i];
        gp[i]  = (const float*)d_in[3 + 4 * i];
        btp[i] = (const float*)d_in[4 + 4 * i];
    }

    float *h0, *h1, *m0, *m1;
    double* st;
    float2* ab;
    cudaGetSymbolAddress((void**)&h0, g_h0);
    cudaGetSymbolAddress((void**)&h1, g_h1);
    cudaGetSymbolAddress((void**)&m0, g_m0);
    cudaGetSymbolAddress((void**)&m1, g_m1);
    cudaGetSymbolAddress((void**)&st, g_stats);
    cudaGetSymbolAddress((void**)&ab, g_affine);

    cudaFuncSetAttribute(sconv_k<11, 1, 1, false>, cudaFuncAttributeMaxDynamicSharedMemorySize, sconv_smem(11, 1));
    cudaFuncSetAttribute(tmma_conv_k<7, true>, cudaFuncAttributeMaxDynamicSharedMemorySize, tmma_smem(7));
    cudaFuncSetAttribute(tmma_conv_k<5, true>, cudaFuncAttributeMaxDynamicSharedMemorySize, tmma_smem(5));
    cudaFuncSetAttribute(tmma_conv_k<3, true>, cudaFuncAttributeMaxDynamicSharedMemorySize, tmma_smem(3));

    dim3 sgrid(1024 / 32, 1024 / 16, 4);
    dim3 tgrid(1024 / 128, 1024 / 2, 4);

    zero_stats_k<<<1, 192>>>();

    sconv_k<11, 1, 1, false><<<sgrid, 128, sconv_smem(11, 1)>>>(
        x, 2LL * HW, x + HW, 2LL * HW, wp[0], bp[0], nullptr, h0, m0, st + 0);
    affine_k<<<1, 16>>>(st + 0, gp[0], btp[0], ab + 0, 16);

    tmma_conv_k<7, true><<<tgrid, 256, tmma_smem(7)>>>(
        h0, 16LL * HW, m0, (long long)HW, wp[1], bp[1], ab + 0, h1, m1, st + 32);
    affine_k<<<1, 16>>>(st + 32, gp[1], btp[1], ab + 16, 16);

    tmma_conv_k<5, true><<<tgrid, 256, tmma_smem(5)>>>(
        h1, 16LL * HW, m1, (long long)HW, wp[2], bp[2], ab + 16, h0, m0, st + 64);
    affine_k<<<1, 16>>>(st + 64, gp[2], btp[2], ab + 32, 16);

    tmma_conv_k<3, true><<<tgrid, 256, tmma_smem(3)>>>(
        h0, 16LL * HW, m0, (long long)HW, wp[3], bp[3], ab + 32, h1, m1, st + 96);
    affine_k<<<1, 16>>>(st + 96, gp[3], btp[3], ab + 48, 16);

    tmma_conv_k<3, true><<<tgrid, 256, tmma_smem(3)>>>(
        h1, 16LL * HW, m1, (long long)HW, wp[4], bp[4], ab + 48, h0, m0, st + 128);
    affine_k<<<1, 16>>>(st + 128, gp[4], btp[4], ab + 64, 16);

    conv1x1_k<<<1184, 256>>>(h0, m0, wp[5], bp[5], ab + 64, h1, st + 160);
    affine_k<<<1, 16>>>(st + 160, gp[5], btp[5], ab + 80, 1);

    final_k<<<4096, 256>>>(h1, ab + 80, (float*)d_out);
}

// round 8
// speedup vs baseline: 1.7211x; 1.7211x over previous
#include <cuda_runtime.h>
#include <cuda_bf16.h>
#include <math.h>

// ---------------------------------------------------------------------------
// SparseConvNet: 6 partial-conv layers. N=4, H=W=1024.
// Round 8: tensor-core conv (mma.sync bf16 3-term split) with
//   - B fragments precomputed to GLOBAL (LDG.128, no B smem / no B ldsm)
//   - A fragment register cache per dx column (reuse across dy,y)
//   - XOR 16B half-swizzle -> conflict-free ldmatrix phases
//   - 2 blocks/SM. Layer 1 (cin=1,K=11) stays scalar FFMA2.
// ---------------------------------------------------------------------------

#define HW   (1024 * 1024)
#define IMW  1024
#define NPIX (4LL * HW)

__device__ float  g_h0[4 * 16 * HW];
__device__ float  g_h1[4 * 16 * HW];
__device__ float  g_m0[4 * HW];
__device__ float  g_m1[4 * HW];
__device__ double g_stats[6 * 32];
__device__ float2 g_affine[6 * 16];
__device__ unsigned int g_bfrag[49 * 2 * 32 * 4];   // max K=7 taps

typedef unsigned long long u64;
typedef unsigned int u32;
typedef unsigned short u16;

__device__ __forceinline__ u64 dup2(float v) {
    u64 r;
    asm("mov.b64 %0, {%1, %1};" : "=l"(r) : "f"(v));
    return r;
}
__device__ __forceinline__ void fma2(u64& d, u64 a, u64 b) {
    asm("fma.rn.f32x2 %0, %1, %2, %0;" : "+l"(d) : "l"(a), "l"(b));
}
__device__ __forceinline__ void unpk(float& lo, float& hi, u64 v) {
    asm("mov.b64 {%0, %1}, %2;" : "=f"(lo), "=f"(hi) : "l"(v));
}
__device__ __forceinline__ u32 smem_u32(const void* p) {
    u32 a;
    asm("{ .reg .u64 t; cvta.to.shared.u64 t, %1; cvt.u32.u64 %0, t; }"
        : "=r"(a) : "l"(p));
    return a;
}
__device__ __forceinline__ void ldsm4(u32* r, u32 a) {
    asm volatile("ldmatrix.sync.aligned.m8n8.x4.shared.b16 {%0,%1,%2,%3}, [%4];"
                 : "=r"(r[0]), "=r"(r[1]), "=r"(r[2]), "=r"(r[3]) : "r"(a));
}
__device__ __forceinline__ void mma16816(float* d, const u32* a, u32 b0, u32 b1) {
    asm volatile(
        "mma.sync.aligned.m16n8k16.row.col.f32.bf16.bf16.f32 "
        "{%0,%1,%2,%3}, {%4,%5,%6,%7}, {%8,%9}, {%0,%1,%2,%3};"
        : "+f"(d[0]), "+f"(d[1]), "+f"(d[2]), "+f"(d[3])
        : "r"(a[0]), "r"(a[1]), "r"(a[2]), "r"(a[3]), "r"(b0), "r"(b1));
}
__device__ __forceinline__ void bsplit(float t, u16& h, u16& l) {
    __nv_bfloat16 bh = __float2bfloat16(t);
    float fh = __bfloat162float(bh);
    __nv_bfloat16 bl = __float2bfloat16(t - fh);
    h = __bfloat16_as_ushort(bh);
    l = __bfloat16_as_ushort(bl);
}
__device__ __forceinline__ uint4 pack8(const u16* s) {
    return make_uint4((u32)s[0] | ((u32)s[1] << 16), (u32)s[2] | ((u32)s[3] << 16),
                      (u32)s[4] | ((u32)s[5] << 16), (u32)s[6] | ((u32)s[7] << 16));
}

__global__ void zero_stats_k() {
    if (threadIdx.x < 6 * 32) g_stats[threadIdx.x] = 0.0;
}

__global__ void affine_k(const double* __restrict__ st,
                         const float* __restrict__ gam,
                         const float* __restrict__ bet,
                         float2* __restrict__ ab, int nch) {
    int c = threadIdx.x;
    if (c >= nch) return;
    double mean = st[c] / (double)NPIX;
    double var  = st[16 + c] / (double)NPIX - mean * mean;
    float inv = rsqrtf((float)var + 1e-5f);
    float a = gam[c] * inv;
    ab[c] = make_float2(a, bet[c] - (float)mean * a);
}

// ---------------------------------------------------------------------------
// Prep: build per-(tap,half,lane) B fragments for mma.m16n8k16 col-major B.
// lane holds: b0=(B[k0][n],B[k0+1][n]), b1=(B[k0+8][n],B[k0+9][n]),
// k0=(lane&3)*2, n=lane>>2; uint4 = {b0,b1 ntile0, b0,b1 ntile1}.
// ---------------------------------------------------------------------------
__global__ void prep_b_k(const float* __restrict__ wG, int K, u32* __restrict__ bf) {
    int total = K * K * 2 * 32;
    for (int i = blockIdx.x * blockDim.x + threadIdx.x; i < total;
         i += gridDim.x * blockDim.x) {
        int lane = i & 31;
        int half = (i >> 5) & 1;
        int tap = i >> 6;
        int dy = tap / K, dx = tap - dy * K;
        int k0 = (lane & 3) * 2, nn = lane >> 2;
        u32 out[4];
#pragma unroll
        for (int t = 0; t < 2; t++) {
#pragma unroll
            for (int kk = 0; kk < 2; kk++) {
                int co = t * 8 + nn;
                int k = k0 + kk * 8;
                float w0 = wG[((co * 16 + k) * K + dy) * K + dx];
                float w1 = wG[((co * 16 + k + 1) * K + dy) * K + dx];
                u16 h0, l0, h1, l1;
                bsplit(w0, h0, l0);
                bsplit(w1, h1, l1);
                u16 a = half ? l0 : h0, b = half ? l1 : h1;
                out[t * 2 + kk] = (u32)a | ((u32)b << 16);
            }
        }
        ((uint4*)bf)[i] = make_uint4(out[0], out[1], out[2], out[3]);
    }
}

// ---------------------------------------------------------------------------
// Tensor-core partial-conv layer (cin=cout=16). Tile = 128 px * TY=2 rows,
// 256 threads / 8 warps; warp = 16-px segment. A smem [R][NPXW px][16ci]bf16
// hi/lo with XOR half-swizzle on px bit2 (conflict-free ldmatrix).
// Mainloop: per dx cache all R row-fragments in regs; per dy LDG B frags.
// ---------------------------------------------------------------------------
template <int K, bool AFF>
__global__ void __launch_bounds__(256, 2) tmma_conv_k(
    const float* __restrict__ in, long long inNS,
    const float* __restrict__ mk, long long mkNS,
    const u32* __restrict__ bfrag, const float* __restrict__ bias,
    const float2* __restrict__ aff,
    float* __restrict__ outH, float* __restrict__ outM,
    double* __restrict__ stats) {
    constexpr int TY = 2, P = K / 2;
    constexpr int NPX = 128 + K - 1;
    constexpr int NPXW = (NPX + 7) & ~7;
    constexpr int R = K + TY - 1;
    constexpr int ROWB = NPXW * 32;
    constexpr int SR_OFF = 0;
    constexpr int MK_OFF = 1024;
    constexpr int AH_OFF = ((MK_OFF + R * NPXW * 4 + 127) / 128) * 128;
    constexpr int AL_OFF = AH_OFF + R * ROWB;

    extern __shared__ char smx[];
    float* sR  = (float*)(smx + SR_OFF);
    float* sMk = (float*)(smx + MK_OFF);
    const u32 sb = smem_u32(smx);

    const int tid = threadIdx.x;
    const int wid = tid >> 5;
    const int lane = tid & 31;
    const int n  = blockIdx.z;
    const int x0 = blockIdx.x * 128;
    const int y0 = blockIdx.y * TY;

    // ---- mask window ----
    const float* mkn = mk + (long long)n * mkNS;
    for (int i = tid; i < R * NPXW; i += 256) {
        int r = i / NPXW, p = i - r * NPXW;
        int gy = y0 - P + r, gx = x0 - P + p;
        float m = 0.f;
        if ((unsigned)gy < 1024u && (unsigned)gx < 1024u) m = mkn[gy * IMW + gx];
        sMk[i] = m;
    }
    __syncthreads();

    // ---- stage A (masked + affine + relu, bf16 hi/lo, half-swizzled) ----
    float2 abr[16];
#pragma unroll
    for (int ci = 0; ci < 16; ci++)
        abr[ci] = AFF ? aff[ci] : make_float2(1.f, 0.f);
    const float* inn = in + (long long)n * inNS;
    for (int i = tid; i < R * NPX; i += 256) {
        int r = i / NPX, p = i - r * NPX;
        int gy = y0 - P + r, gx = x0 - P + p;
        bool ok = (unsigned)gy < 1024u && (unsigned)gx < 1024u;
        float m = sMk[r * NPXW + p];
        const float* ip = inn + (long long)gy * IMW + gx;
        u16 hs[16], ls[16];
#pragma unroll
        for (int ci = 0; ci < 16; ci++) {
            float v = ok ? ip[(long long)ci * HW] : 0.f;
            if (AFF) v = fmaxf(fmaf(v, abr[ci].x, abr[ci].y), 0.f);
            bsplit(v * m, hs[ci], ls[ci]);
        }
        u32 s = ((p >> 2) & 1) * 16;            // half swizzle
        char* ah = smx + AH_OFF + r * ROWB + p * 32;
        char* al = smx + AL_OFF + r * ROWB + p * 32;
        *(uint4*)(ah + s) = pack8(hs);
        *(uint4*)(ah + (16 ^ s)) = pack8(hs + 8);
        *(uint4*)(al + s) = pack8(ls);
        *(uint4*)(al + (16 ^ s)) = pack8(ls + 8);
    }
    __syncthreads();

    // ---- MMA mainloop ----
    const int seg = wid;
    float D[TY][2][4];
#pragma unroll
    for (int y = 0; y < TY; y++)
#pragma unroll
        for (int t = 0; t < 2; t++)
#pragma unroll
            for (int j = 0; j < 4; j++) D[y][t][j] = 0.f;

    const int l15 = lane & 15;
    const int kh = lane >> 4;
    const uint4* bf4 = (const uint4*)bfrag;

#pragma unroll 1
    for (int dx = 0; dx < K; dx++) {
        u32 sw = (u32)(((l15 + dx) >> 2) & 1);
        u32 apx = (u32)(seg * 16 + l15 + dx);
        u32 aoff = apx * 32 + (((u32)kh ^ sw) * 16);
        u32 aH = sb + AH_OFF + aoff;
        u32 aL = sb + AL_OFF + aoff;
        u32 Ah[R][4], Al[R][4];
#pragma unroll
        for (int r = 0; r < R; r++) {
            ldsm4(Ah[r], aH + r * ROWB);
            ldsm4(Al[r], aL + r * ROWB);
        }
#pragma unroll
        for (int dy = 0; dy < K; dy++) {
            int tap = dy * K + dx;
            uint4 BH = bf4[(tap * 2 + 0) * 32 + lane];
            uint4 BL = bf4[(tap * 2 + 1) * 32 + lane];
#pragma unroll
            for (int y = 0; y < TY; y++) {
                mma16816(D[y][0], Ah[y + dy], BH.x, BH.y);
                mma16816(D[y][1], Ah[y + dy], BH.z, BH.w);
                mma16816(D[y][0], Al[y + dy], BH.x, BH.y);
                mma16816(D[y][1], Al[y + dy], BH.z, BH.w);
                mma16816(D[y][0], Ah[y + dy], BL.x, BL.y);
                mma16816(D[y][1], Ah[y + dy], BL.z, BL.w);
            }
        }
    }

    // ---- mask-sum conv + maxpool: lane task (yl, pxl) ----
    const int yl = lane >> 4, pxl = lane & 15;
    float s = 0.f, mm = 0.f;
    {
        const float* mb = sMk + yl * NPXW + seg * 16 + pxl;
#pragma unroll 1
        for (int dy = 0; dy < K; dy++)
#pragma unroll
            for (int dx = 0; dx < K; dx++) {
                float m = mb[dy * NPXW + dx];
                s += m;
                mm = fmaxf(mm, m);
            }
    }
    float invv = 1.0f / (s + 1e-8f);
    outM[(long long)n * HW + (long long)(y0 + yl) * IMW + x0 + seg * 16 + pxl] = mm;

    // ---- epilogue: scale, bias, store, stats ----
    float bco[4];
#pragma unroll
    for (int t = 0; t < 2; t++)
#pragma unroll
        for (int j = 0; j < 2; j++)
            bco[t * 2 + j] = bias[t * 8 + (lane & 3) * 2 + j];
    float p1[4] = {0.f, 0.f, 0.f, 0.f}, p2[4] = {0.f, 0.f, 0.f, 0.f};
    const int pxa = seg * 16 + (lane >> 2);

#pragma unroll
    for (int y = 0; y < TY; y++) {
        float inva = __shfl_sync(0xffffffffu, invv, y * 16 + (lane >> 2));
        float invb = __shfl_sync(0xffffffffu, invv, y * 16 + (lane >> 2) + 8);
        int gy = y0 + y;
        float* hb = outH + (long long)n * 16 * HW + (long long)gy * IMW + x0;
#pragma unroll
        for (int t = 0; t < 2; t++) {
#pragma unroll
            for (int j = 0; j < 2; j++) {
                int co = t * 8 + (lane & 3) * 2 + j;
                float bc = bco[t * 2 + j];
                float v0 = fmaf(D[y][t][j], inva, bc);
                float v1 = fmaf(D[y][t][j + 2], invb, bc);
                hb[(long long)co * HW + pxa] = v0;
                hb[(long long)co * HW + pxa + 8] = v1;
                p1[t * 2 + j] += v0 + v1;
                p2[t * 2 + j] = fmaf(v0, v0, fmaf(v1, v1, p2[t * 2 + j]));
            }
        }
    }
#pragma unroll
    for (int k = 0; k < 4; k++) {
#pragma unroll
        for (int o = 4; o < 32; o <<= 1) {
            p1[k] += __shfl_xor_sync(0xffffffffu, p1[k], o);
            p2[k] += __shfl_xor_sync(0xffffffffu, p2[k], o);
        }
    }
    if (lane < 4) {
#pragma unroll
        for (int t = 0; t < 2; t++)
#pragma unroll
            for (int j = 0; j < 2; j++) {
                int co = t * 8 + lane * 2 + j;
                sR[(co * 2 + 0) * 8 + wid] = p1[t * 2 + j];
                sR[(co * 2 + 1) * 8 + wid] = p2[t * 2 + j];
            }
    }
    __syncthreads();
    if (tid < 32) {
        int co = tid >> 1, which = tid & 1;
        float v = 0.f;
#pragma unroll
        for (int w = 0; w < 8; w++) v += sR[tid * 8 + w];
        atomicAdd(&stats[which * 16 + co], (double)v);
    }
}

// ---------------------------------------------------------------------------
// Scalar FFMA2 partial-conv — layer 1 (cin=1, K=11).
// ---------------------------------------------------------------------------
template <int K>
__global__ void __launch_bounds__(128, 4) sconv_k(
    const float* __restrict__ in, long long inNS,
    const float* __restrict__ mk, long long mkNS,
    const float* __restrict__ wG, const float* __restrict__ bias,
    float* __restrict__ outH, float* __restrict__ outM,
    double* __restrict__ stats) {
    constexpr int TX = 32, TY = 16, P = K / 2;
    constexpr int IW = TX + K - 1;
    constexpr int IH = TY + K - 1;
    constexpr int IHP = IH | 1;
    constexpr int SMN = IH * IW;
    constexpr int SXN = IW * IHP;
    constexpr int SWOFF = ((SMN + SXN + 3) / 4) * 4;
    constexpr int SWN = K * K * 16;

    extern __shared__ float sm[];
    float* sMk = sm;
    float* sX  = sm + SMN;
    float* sW  = sm + SWOFF;
    float* sR  = sm + SWOFF + SWN;

    const int tid = threadIdx.x;
    const int n = blockIdx.z;
    const int x0 = blockIdx.x * TX - P;
    const int y0 = blockIdx.y * TY - P;

    const float* mkn = mk + (long long)n * mkNS;
    const float* inn = in + (long long)n * inNS;
    for (int i = tid; i < SMN; i += 128) {
        int ly = i / IW, lx = i - ly * IW;
        int gy = y0 + ly, gx = x0 + lx;
        float m = 0.f, v = 0.f;
        if ((unsigned)gy < 1024u && (unsigned)gx < 1024u) {
            m = mkn[gy * IMW + gx];
            v = inn[gy * IMW + gx];
        }
        sMk[i] = m;
        sX[lx * IHP + ly] = v * m;
    }
    for (int i = tid; i < SWN; i += 128) {
        int co = i & 15;
        int rest = i >> 4;
        sW[i] = wG[co * (K * K) + rest];
    }
    __syncthreads();

    const int tx = tid & 31;
    const int tq = tid >> 5;

    u64 acc2[32];
#pragma unroll
    for (int i = 0; i < 32; i++) acc2[i] = 0ull;

    {
        const float* colbase = sX + tx * IHP + tq * 4;
#pragma unroll 1
        for (int dx = 0; dx < K; dx++) {
            const float* colp = colbase + dx * IHP;
            u64 vv[K + 3];
#pragma unroll
            for (int j = 0; j < K + 3; j++) vv[j] = dup2(colp[j]);
#pragma unroll
            for (int dy = 0; dy < K; dy++) {
                const ulonglong2* wq = (const ulonglong2*)(sW + (dy * K + dx) * 16);
                ulonglong2 wa = wq[0];
                ulonglong2 wb = wq[1];
                ulonglong2 wc = wq[2];
                ulonglong2 wd = wq[3];
#pragma unroll
                for (int py = 0; py < 4; py++) {
                    u64 v = vv[dy + py];
                    fma2(acc2[0 * 4 + py], v, wa.x);
                    fma2(acc2[1 * 4 + py], v, wa.y);
                    fma2(acc2[2 * 4 + py], v, wb.x);
                    fma2(acc2[3 * 4 + py], v, wb.y);
                    fma2(acc2[4 * 4 + py], v, wc.x);
                    fma2(acc2[5 * 4 + py], v, wc.y);
                    fma2(acc2[6 * 4 + py], v, wd.x);
                    fma2(acc2[7 * 4 + py], v, wd.y);
                }
            }
        }
    }

    float s[4] = {0.f, 0.f, 0.f, 0.f};
    float mm[4] = {0.f, 0.f, 0.f, 0.f};
    {
        const float* mb = sMk + (tq * 4) * IW + tx;
#pragma unroll 1
        for (int dy = 0; dy < K; dy++)
#pragma unroll
            for (int dx = 0; dx < K; dx++)
#pragma unroll
                for (int py = 0; py < 4; py++) {
                    float m = mb[(dy + py) * IW + dx];
                    s[py] += m;
                    mm[py] = fmaxf(mm[py], m);
                }
    }
    float inv[4];
#pragma unroll
    for (int py = 0; py < 4; py++) inv[py] = 1.0f / (s[py] + 1e-8f);

    const int gy = blockIdx.y * TY + tq * 4;
    const int gx = blockIdx.x * TX + tx;

    float* mo = outM + (long long)n * HW + gy * IMW + gx;
#pragma unroll
    for (int py = 0; py < 4; py++) mo[py * IMW] = mm[py];

    float* ho = outH + ((long long)n * 16) * HW + gy * IMW + gx;
    const int lane = tid & 31;
    const int warp = tid >> 5;
#pragma unroll
    for (int cp = 0; cp < 8; cp++) {
        float b0 = bias[2 * cp], b1 = bias[2 * cp + 1];
        float p1a = 0.f, p2a = 0.f, p1b = 0.f, p2b = 0.f;
#pragma unroll
        for (int py = 0; py < 4; py++) {
            float a0, a1;
            unpk(a0, a1, acc2[cp * 4 + py]);
            float y0v = fmaf(a0, inv[py], b0);
            float y1v = fmaf(a1, inv[py], b1);
            ho[(long long)(2 * cp) * HW + py * IMW] = y0v;
            ho[(long long)(2 * cp + 1) * HW + py * IMW] = y1v;
            p1a += y0v; p2a = fmaf(y0v, y0v, p2a);
            p1b += y1v; p2b = fmaf(y1v, y1v, p2b);
        }
#pragma unroll
        for (int o = 16; o; o >>= 1) {
            p1a += __shfl_xor_sync(0xffffffffu, p1a, o);
            p2a += __shfl_xor_sync(0xffffffffu, p2a, o);
            p1b += __shfl_xor_sync(0xffffffffu, p1b, o);
            p2b += __shfl_xor_sync(0xffffffffu, p2b, o);
        }
        if (lane == 0) {
            sR[(2 * cp * 2 + 0) * 4 + warp] = p1a;
            sR[(2 * cp * 2 + 1) * 4 + warp] = p2a;
            sR[((2 * cp + 1) * 2 + 0) * 4 + warp] = p1b;
            sR[((2 * cp + 1) * 2 + 1) * 4 + warp] = p2b;
        }
    }
    __syncthreads();
    if (tid < 32) {
        float v = sR[tid * 4 + 0] + sR[tid * 4 + 1] + sR[tid * 4 + 2] + sR[tid * 4 + 3];
        int co = tid >> 1, which = tid & 1;
        atomicAdd(&stats[which * 16 + co], (double)v);
    }
}

// ---------------------------------------------------------------------------
__global__ void conv1x1_k(const float* __restrict__ h,
                          const float* __restrict__ mk,
                          const float* __restrict__ w6,
                          const float* __restrict__ b6,
                          const float2* __restrict__ aff,
                          float* __restrict__ y,
                          double* __restrict__ stats) {
    __shared__ float swv[16];
    __shared__ float2 sab[16];
    __shared__ float r1[8], r2[8];
    if (threadIdx.x < 16) {
        swv[threadIdx.x] = w6[threadIdx.x];
        sab[threadIdx.x] = aff[threadIdx.x];
    }
    __syncthreads();
    float bb = b6[0];
    float p1 = 0.f, p2 = 0.f;
    for (long long i = (long long)blockIdx.x * blockDim.x + threadIdx.x;
         i < 4LL * HW; i += (long long)gridDim.x * blockDim.x) {
        long long n = i >> 20;
        long long p = i & (HW - 1);
        float m = mk[i];
        float accv = 0.f;
#pragma unroll
        for (int c = 0; c < 16; c++) {
            float v = h[(n * 16 + c) * HW + p];
            float2 ab = sab[c];
            v = fmaxf(fmaf(v, ab.x, ab.y), 0.f);
            accv = fmaf(swv[c], v, accv);
        }
        float r = 1.0f / (m + 1e-8f);
        float yv = fmaf(accv * m, r, bb);
        y[i] = yv;
        p1 += yv;
        p2 = fmaf(yv, yv, p2);
    }
#pragma unroll
    for (int o = 16; o; o >>= 1) {
        p1 += __shfl_xor_sync(0xffffffffu, p1, o);
        p2 += __shfl_xor_sync(0xffffffffu, p2, o);
    }
    int warp = threadIdx.x >> 5, lane = threadIdx.x & 31;
    if (lane == 0) { r1[warp] = p1; r2[warp] = p2; }
    __syncthreads();
    if (threadIdx.x == 0) {
        float a = 0.f, b = 0.f;
        for (int w = 0; w < (int)(blockDim.x >> 5); w++) { a += r1[w]; b += r2[w]; }
        atomicAdd(&stats[0], (double)a);
        atomicAdd(&stats[16], (double)b);
    }
}

__global__ void final_k(const float* __restrict__ y,
                        const float2* __restrict__ ab,
                        float* __restrict__ o) {
    float2 t = ab[0];
    for (long long i = (long long)blockIdx.x * blockDim.x + threadIdx.x;
         i < 4LL * HW; i += (long long)gridDim.x * blockDim.x)
        o[i] = fmaf(y[i], t.x, t.y);
}

// ---------------------------------------------------------------------------
static constexpr int sconv_smem(int K) {
    int IW = 32 + K - 1, IH = 16 + K - 1;
    int IHP = IH | 1;
    int smn = IH * IW;
    int sxn = IW * IHP;
    int swoff = ((smn + sxn + 3) / 4) * 4;
    return (swoff + K * K * 16 + 128) * 4;
}
static constexpr int tmma_smem(int K) {
    int TY = 2, NPX = 128 + K - 1, NPXW = (NPX + 7) & ~7, R = K + TY - 1;
    int AH = ((1024 + R * NPXW * 4 + 127) / 128) * 128;
    return AH + 2 * R * NPXW * 32;
}

extern "C" void kernel_launch(void* const* d_in, const int* in_sizes, int n_in,
                              void* d_out, int out_size) {
    (void)in_sizes; (void)n_in; (void)out_size;
    const float* x = (const float*)d_in[0];
    const float *wp[6], *bp[6], *gp[6], *btp[6];
    for (int i = 0; i < 6; i++) {
        wp[i]  = (const float*)d_in[1 + 4 * i];
        bp[i]  = (const float*)d_in[2 + 4 * i];
        gp[i]  = (const float*)d_in[3 + 4 * i];
        btp[i] = (const float*)d_in[4 + 4 * i];
    }

    float *h0, *h1, *m0, *m1;
    double* st;
    float2* ab;
    u32* bf;
    cudaGetSymbolAddress((void**)&h0, g_h0);
    cudaGetSymbolAddress((void**)&h1, g_h1);
    cudaGetSymbolAddress((void**)&m0, g_m0);
    cudaGetSymbolAddress((void**)&m1, g_m1);
    cudaGetSymbolAddress((void**)&st, g_stats);
    cudaGetSymbolAddress((void**)&ab, g_affine);
    cudaGetSymbolAddress((void**)&bf, g_bfrag);

    cudaFuncSetAttribute(sconv_k<11>, cudaFuncAttributeMaxDynamicSharedMemorySize, sconv_smem(11));
    cudaFuncSetAttribute(tmma_conv_k<7, true>, cudaFuncAttributeMaxDynamicSharedMemorySize, tmma_smem(7));
    cudaFuncSetAttribute(tmma_conv_k<5, true>, cudaFuncAttributeMaxDynamicSharedMemorySize, tmma_smem(5));
    cudaFuncSetAttribute(tmma_conv_k<3, true>, cudaFuncAttributeMaxDynamicSharedMemorySize, tmma_smem(3));

    dim3 sgrid(1024 / 32, 1024 / 16, 4);
    dim3 tgrid(1024 / 128, 1024 / 2, 4);

    zero_stats_k<<<1, 192>>>();

    sconv_k<11><<<sgrid, 128, sconv_smem(11)>>>(
        x, 2LL * HW, x + HW, 2LL * HW, wp[0], bp[0], h0, m0, st + 0);
    affine_k<<<1, 16>>>(st + 0, gp[0], btp[0], ab + 0, 16);

    prep_b_k<<<8, 256>>>(wp[1], 7, bf);
    tmma_conv_k<7, true><<<tgrid, 256, tmma_smem(7)>>>(
        h0, 16LL * HW, m0, (long long)HW, bf, bp[1], ab + 0, h1, m1, st + 32);
    affine_k<<<1, 16>>>(st + 32, gp[1], btp[1], ab + 16, 16);

    prep_b_k<<<8, 256>>>(wp[2], 5, bf);
    tmma_conv_k<5, true><<<tgrid, 256, tmma_smem(5)>>>(
        h1, 16LL * HW, m1, (long long)HW, bf, bp[2], ab + 16, h0, m0, st + 64);
    affine_k<<<1, 16>>>(st + 64, gp[2], btp[2], ab + 32, 16);

    prep_b_k<<<8, 256>>>(wp[3], 3, bf);
    tmma_conv_k<3, true><<<tgrid, 256, tmma_smem(3)>>>(
        h0, 16LL * HW, m0, (long long)HW, bf, bp[3], ab + 32, h1, m1, st + 96);
    affine_k<<<1, 16>>>(st + 96, gp[3], btp[3], ab + 48, 16);

    prep_b_k<<<8, 256>>>(wp[4], 3, bf);
    tmma_conv_k<3, true><<<tgrid, 256, tmma_smem(3)>>>(
        h1, 16LL * HW, m1, (long long)HW, bf, bp[4], ab + 48, h0, m0, st + 128);
    affine_k<<<1, 16>>>(st + 128, gp[4], btp[4], ab + 64, 16);

    conv1x1_k<<<1184, 256>>>(h0, m0, wp[5], bp[5], ab + 64, h1, st + 160);
    affine_k<<<1, 16>>>(st + 160, gp[5], btp[5], ab + 80, 1);

    final_k<<<4096, 256>>>(h1, ab + 80, (float*)d_out);
}

// round 9
// speedup vs baseline: 2.2017x; 1.2793x over previous
#include <cuda_runtime.h>
#include <cuda_bf16.h>
#include <math.h>

// ---------------------------------------------------------------------------
// SparseConvNet: 6 partial-conv layers. N=4, H=W=1024.
// Round 9: tensor-core conv, TY=4 rows/block (staging redundancy 4.0->2.5 for
// k7), rolling 4-slot A-fragment register window, truncation bf16 split,
// single combined B-fragment prep kernel. Layer 1 stays scalar FFMA2.
// ---------------------------------------------------------------------------

#define HW   (1024 * 1024)
#define IMW  1024
#define NPIX (4LL * HW)

__device__ float  g_h0[4 * 16 * HW];
__device__ float  g_h1[4 * 16 * HW];
__device__ float  g_m0[4 * HW];
__device__ float  g_m1[4 * HW];
__device__ double g_stats[6 * 32];
__device__ float2 g_affine[6 * 16];
__device__ unsigned int g_bfrag[92 * 2 * 32 * 4];   // 49+25+9+9 taps

typedef unsigned long long u64;
typedef unsigned int u32;
typedef unsigned short u16;

__device__ __forceinline__ u64 dup2(float v) {
    u64 r;
    asm("mov.b64 %0, {%1, %1};" : "=l"(r) : "f"(v));
    return r;
}
__device__ __forceinline__ void fma2(u64& d, u64 a, u64 b) {
    asm("fma.rn.f32x2 %0, %1, %2, %0;" : "+l"(d) : "l"(a), "l"(b));
}
__device__ __forceinline__ void unpk(float& lo, float& hi, u64 v) {
    asm("mov.b64 {%0, %1}, %2;" : "=f"(lo), "=f"(hi) : "l"(v));
}
__device__ __forceinline__ u32 smem_u32(const void* p) {
    u32 a;
    asm("{ .reg .u64 t; cvta.to.shared.u64 t, %1; cvt.u32.u64 %0, t; }"
        : "=r"(a) : "l"(p));
    return a;
}
__device__ __forceinline__ void ldsm4(u32* r, u32 a) {
    asm volatile("ldmatrix.sync.aligned.m8n8.x4.shared.b16 {%0,%1,%2,%3}, [%4];"
                 : "=r"(r[0]), "=r"(r[1]), "=r"(r[2]), "=r"(r[3]) : "r"(a));
}
__device__ __forceinline__ void mma16816(float* d, const u32* a, u32 b0, u32 b1) {
    asm volatile(
        "mma.sync.aligned.m16n8k16.row.col.f32.bf16.bf16.f32 "
        "{%0,%1,%2,%3}, {%4,%5,%6,%7}, {%8,%9}, {%0,%1,%2,%3};"
        : "+f"(d[0]), "+f"(d[1]), "+f"(d[2]), "+f"(d[3])
        : "r"(a[0]), "r"(a[1]), "r"(a[2]), "r"(a[3]), "r"(b0), "r"(b1));
}
// truncation hi/lo split: hi = top 16 bits, lo = RN(t - hi). |err| ~ 2^-16 rel.
__device__ __forceinline__ void bsplit(float t, u16& h, u16& l) {
    u32 u = __float_as_uint(t);
    h = (u16)(u >> 16);
    float fh = __uint_as_float(u & 0xFFFF0000u);
    l = __bfloat16_as_ushort(__float2bfloat16(t - fh));
}
__device__ __forceinline__ uint4 pack8(const u16* s) {
    return make_uint4((u32)s[0] | ((u32)s[1] << 16), (u32)s[2] | ((u32)s[3] << 16),
                      (u32)s[4] | ((u32)s[5] << 16), (u32)s[6] | ((u32)s[7] << 16));
}

__global__ void zero_stats_k() {
    if (threadIdx.x < 6 * 32) g_stats[threadIdx.x] = 0.0;
}

__global__ void affine_k(const double* __restrict__ st,
                         const float* __restrict__ gam,
                         const float* __restrict__ bet,
                         float2* __restrict__ ab, int nch) {
    int c = threadIdx.x;
    if (c >= nch) return;
    double mean = st[c] / (double)NPIX;
    double var  = st[16 + c] / (double)NPIX - mean * mean;
    float inv = rsqrtf((float)var + 1e-5f);
    float a = gam[c] * inv;
    ab[c] = make_float2(a, bet[c] - (float)mean * a);
}

// ---------------------------------------------------------------------------
// Combined prep: B fragments for layers 2..5 (K=7,5,3,3) in one launch.
// Layout per tap: [half(2)][lane(32)] uint4. Global tap offsets: 0,49,74,83.
// ---------------------------------------------------------------------------
__global__ void prep_all_b(const float* __restrict__ w2, const float* __restrict__ w3,
                           const float* __restrict__ w4, const float* __restrict__ w5,
                           u32* __restrict__ bf) {
    const int total = 92 * 2 * 32;
    for (int i = blockIdx.x * blockDim.x + threadIdx.x; i < total;
         i += gridDim.x * blockDim.x) {
        int lane = i & 31;
        int half = (i >> 5) & 1;
        int gt = i >> 6;
        const float* w;
        int K, tap;
        if (gt < 49)      { w = w2; K = 7; tap = gt; }
        else if (gt < 74) { w = w3; K = 5; tap = gt - 49; }
        else if (gt < 83) { w = w4; K = 3; tap = gt - 74; }
        else              { w = w5; K = 3; tap = gt - 83; }
        int dy = tap / K, dx = tap - dy * K;
        int k0 = (lane & 3) * 2, nn = lane >> 2;
        u32 out[4];
#pragma unroll
        for (int t = 0; t < 2; t++) {
#pragma unroll
            for (int kk = 0; kk < 2; kk++) {
                int co = t * 8 + nn;
                int k = k0 + kk * 8;
                float w0 = w[((co * 16 + k) * K + dy) * K + dx];
                float w1 = w[((co * 16 + k + 1) * K + dy) * K + dx];
                u16 h0, l0, h1, l1;
                bsplit(w0, h0, l0);
                bsplit(w1, h1, l1);
                u16 a = half ? l0 : h0, b = half ? l1 : h1;
                out[t * 2 + kk] = (u32)a | ((u32)b << 16);
            }
        }
        ((uint4*)bf)[i] = make_uint4(out[0], out[1], out[2], out[3]);
    }
}

// ---------------------------------------------------------------------------
// Tensor-core partial-conv layer (cin=cout=16). Tile = 128 px * TY=4 rows,
// 256 threads / 8 warps; warp = 16-px segment, 4 rows. A smem
// [R=K+3][NPXW px][16ci] bf16 hi/lo, XOR half-swizzle. Mainloop per dx:
// rolling 4-slot A register window over dy (2 ldsm/dy after 3-row preload).
// ---------------------------------------------------------------------------
template <int K, bool AFF>
__global__ void __launch_bounds__(256, 2) tmma_conv_k(
    const float* __restrict__ in, long long inNS,
    const float* __restrict__ mk, long long mkNS,
    const u32* __restrict__ bfrag, const float* __restrict__ bias,
    const float2* __restrict__ aff,
    float* __restrict__ outH, float* __restrict__ outM,
    double* __restrict__ stats) {
    constexpr int TY = 4, P = K / 2;
    constexpr int NPX = 128 + K - 1;
    constexpr int NPXW = (NPX + 7) & ~7;
    constexpr int R = K + TY - 1;
    constexpr int ROWB = NPXW * 32;
    constexpr int SR_OFF = 0;
    constexpr int MK_OFF = 1024;
    constexpr int AH_OFF = ((MK_OFF + R * NPXW * 4 + 127) / 128) * 128;
    constexpr int AL_OFF = AH_OFF + R * ROWB;

    extern __shared__ char smx[];
    float* sR  = (float*)(smx + SR_OFF);
    float* sMk = (float*)(smx + MK_OFF);
    const u32 sb = smem_u32(smx);

    const int tid = threadIdx.x;
    const int wid = tid >> 5;
    const int lane = tid & 31;
    const int n  = blockIdx.z;
    const int x0 = blockIdx.x * 128;
    const int y0 = blockIdx.y * TY;

    // ---- mask window ----
    const float* mkn = mk + (long long)n * mkNS;
    for (int i = tid; i < R * NPXW; i += 256) {
        int r = i / NPXW, p = i - r * NPXW;
        int gy = y0 - P + r, gx = x0 - P + p;
        float m = 0.f;
        if ((unsigned)gy < 1024u && (unsigned)gx < 1024u) m = mkn[gy * IMW + gx];
        sMk[i] = m;
    }
    __syncthreads();

    // ---- stage A (masked + affine + relu, bf16 hi/lo, half-swizzled) ----
    float2 abr[16];
#pragma unroll
    for (int ci = 0; ci < 16; ci++)
        abr[ci] = AFF ? aff[ci] : make_float2(1.f, 0.f);
    const float* inn = in + (long long)n * inNS;
    for (int i = tid; i < R * NPX; i += 256) {
        int r = i / NPX, p = i - r * NPX;
        int gy = y0 - P + r, gx = x0 - P + p;
        bool ok = (unsigned)gy < 1024u && (unsigned)gx < 1024u;
        float m = sMk[r * NPXW + p];
        const float* ip = inn + (long long)gy * IMW + gx;
        u16 hs[16], ls[16];
#pragma unroll
        for (int ci = 0; ci < 16; ci++) {
            float v = ok ? ip[(long long)ci * HW] : 0.f;
            if (AFF) v = fmaxf(fmaf(v, abr[ci].x, abr[ci].y), 0.f);
            bsplit(v * m, hs[ci], ls[ci]);
        }
        u32 s = ((p >> 2) & 1) * 16;            // half swizzle
        char* ah = smx + AH_OFF + r * ROWB + p * 32;
        char* al = smx + AL_OFF + r * ROWB + p * 32;
        *(uint4*)(ah + s) = pack8(hs);
        *(uint4*)(ah + (16 ^ s)) = pack8(hs + 8);
        *(uint4*)(al + s) = pack8(ls);
        *(uint4*)(al + (16 ^ s)) = pack8(ls + 8);
    }
    __syncthreads();

    // ---- MMA mainloop ----
    const int seg = wid;
    float D[TY][2][4];
#pragma unroll
    for (int y = 0; y < TY; y++)
#pragma unroll
        for (int t = 0; t < 2; t++)
#pragma unroll
            for (int j = 0; j < 4; j++) D[y][t][j] = 0.f;

    const int l15 = lane & 15;
    const int kh = lane >> 4;
    const uint4* bf4 = (const uint4*)bfrag;

#pragma unroll 1
    for (int dx = 0; dx < K; dx++) {
        u32 sw = (u32)(((l15 + dx) >> 2) & 1);
        u32 apx = (u32)(seg * 16 + l15 + dx);
        u32 aoff = apx * 32 + (((u32)kh ^ sw) * 16);
        u32 aH = sb + AH_OFF + aoff;
        u32 aL = sb + AL_OFF + aoff;
        u32 Wh[4][4], Wl[4][4];
#pragma unroll
        for (int r = 0; r < 3; r++) {
            ldsm4(Wh[r], aH + r * ROWB);
            ldsm4(Wl[r], aL + r * ROWB);
        }
#pragma unroll
        for (int dy = 0; dy < K; dy++) {
            const int rin = dy + 3;
            ldsm4(Wh[rin & 3], aH + rin * ROWB);
            ldsm4(Wl[rin & 3], aL + rin * ROWB);
            int tap = dy * K + dx;
            uint4 BH = bf4[(tap * 2 + 0) * 32 + lane];
            uint4 BL = bf4[(tap * 2 + 1) * 32 + lane];
#pragma unroll
            for (int y = 0; y < TY; y++) {
                const int sl = (dy + y) & 3;
                mma16816(D[y][0], Wh[sl], BH.x, BH.y);
                mma16816(D[y][1], Wh[sl], BH.z, BH.w);
                mma16816(D[y][0], Wl[sl], BH.x, BH.y);
                mma16816(D[y][1], Wl[sl], BH.z, BH.w);
                mma16816(D[y][0], Wh[sl], BL.x, BL.y);
                mma16816(D[y][1], Wh[sl], BL.z, BL.w);
            }
        }
    }

    // ---- mask-sum conv + maxpool: lane handles rows (yl, yl+2) at pxl ----
    const int yl = lane >> 4, pxl = lane & 15;
    float s[2] = {0.f, 0.f}, mm[2] = {0.f, 0.f};
    {
        const float* mb = sMk + seg * 16 + pxl;
#pragma unroll 1
        for (int dy = 0; dy < K; dy++)
#pragma unroll
            for (int dx = 0; dx < K; dx++) {
#pragma unroll
                for (int j = 0; j < 2; j++) {
                    float m = mb[(yl + 2 * j + dy) * NPXW + dx];
                    s[j] += m;
                    mm[j] = fmaxf(mm[j], m);
                }
            }
    }
    float invv0 = 1.0f / (s[0] + 1e-8f);   // row yl
    float invv1 = 1.0f / (s[1] + 1e-8f);   // row yl+2
    outM[(long long)n * HW + (long long)(y0 + yl) * IMW + x0 + seg * 16 + pxl] = mm[0];
    outM[(long long)n * HW + (long long)(y0 + yl + 2) * IMW + x0 + seg * 16 + pxl] = mm[1];

    // ---- epilogue: scale, bias, store, stats ----
    float bco[4];
#pragma unroll
    for (int t = 0; t < 2; t++)
#pragma unroll
        for (int j = 0; j < 2; j++)
            bco[t * 2 + j] = bias[t * 8 + (lane & 3) * 2 + j];
    float p1[4] = {0.f, 0.f, 0.f, 0.f}, p2[4] = {0.f, 0.f, 0.f, 0.f};
    const int pxa = seg * 16 + (lane >> 2);

#pragma unroll
    for (int y = 0; y < TY; y++) {
        float vsel = (y < 2) ? invv0 : invv1;
        float inva = __shfl_sync(0xffffffffu, vsel, (y & 1) * 16 + (lane >> 2));
        float invb = __shfl_sync(0xffffffffu, vsel, (y & 1) * 16 + (lane >> 2) + 8);
        int gy = y0 + y;
        float* hb = outH + (long long)n * 16 * HW + (long long)gy * IMW + x0;
#pragma unroll
        for (int t = 0; t < 2; t++) {
#pragma unroll
            for (int j = 0; j < 2; j++) {
                int co = t * 8 + (lane & 3) * 2 + j;
                float bc = bco[t * 2 + j];
                float v0 = fmaf(D[y][t][j], inva, bc);
                float v1 = fmaf(D[y][t][j + 2], invb, bc);
                hb[(long long)co * HW + pxa] = v0;
                hb[(long long)co * HW + pxa + 8] = v1;
                p1[t * 2 + j] += v0 + v1;
                p2[t * 2 + j] = fmaf(v0, v0, fmaf(v1, v1, p2[t * 2 + j]));
            }
        }
    }
#pragma unroll
    for (int k = 0; k < 4; k++) {
#pragma unroll
        for (int o = 4; o < 32; o <<= 1) {
            p1[k] += __shfl_xor_sync(0xffffffffu, p1[k], o);
            p2[k] += __shfl_xor_sync(0xffffffffu, p2[k], o);
        }
    }
    if (lane < 4) {
#pragma unroll
        for (int t = 0; t < 2; t++)
#pragma unroll
            for (int j = 0; j < 2; j++) {
                int co = t * 8 + lane * 2 + j;
                sR[(co * 2 + 0) * 8 + wid] = p1[t * 2 + j];
                sR[(co * 2 + 1) * 8 + wid] = p2[t * 2 + j];
            }
    }
    __syncthreads();
    if (tid < 32) {
        int co = tid >> 1, which = tid & 1;
        float v = 0.f;
#pragma unroll
        for (int w = 0; w < 8; w++) v += sR[tid * 8 + w];
        atomicAdd(&stats[which * 16 + co], (double)v);
    }
}

// ---------------------------------------------------------------------------
// Scalar FFMA2 partial-conv — layer 1 (cin=1, K=11).
// ---------------------------------------------------------------------------
template <int K>
__global__ void __launch_bounds__(128, 4) sconv_k(
    const float* __restrict__ in, long long inNS,
    const float* __restrict__ mk, long long mkNS,
    const float* __restrict__ wG, const float* __restrict__ bias,
    float* __restrict__ outH, float* __restrict__ outM,
    double* __restrict__ stats) {
    constexpr int TX = 32, TY = 16, P = K / 2;
    constexpr int IW = TX + K - 1;
    constexpr int IH = TY + K - 1;
    constexpr int IHP = IH | 1;
    constexpr int SMN = IH * IW;
    constexpr int SXN = IW * IHP;
    constexpr int SWOFF = ((SMN + SXN + 3) / 4) * 4;
    constexpr int SWN = K * K * 16;

    extern __shared__ float sm[];
    float* sMk = sm;
    float* sX  = sm + SMN;
    float* sW  = sm + SWOFF;
    float* sR  = sm + SWOFF + SWN;

    const int tid = threadIdx.x;
    const int n = blockIdx.z;
    const int x0 = blockIdx.x * TX - P;
    const int y0 = blockIdx.y * TY - P;

    const float* mkn = mk + (long long)n * mkNS;
    const float* inn = in + (long long)n * inNS;
    for (int i = tid; i < SMN; i += 128) {
        int ly = i / IW, lx = i - ly * IW;
        int gy = y0 + ly, gx = x0 + lx;
        float m = 0.f, v = 0.f;
        if ((unsigned)gy < 1024u && (unsigned)gx < 1024u) {
            m = mkn[gy * IMW + gx];
            v = inn[gy * IMW + gx];
        }
        sMk[i] = m;
        sX[lx * IHP + ly] = v * m;
    }
    for (int i = tid; i < SWN; i += 128) {
        int co = i & 15;
        int rest = i >> 4;
        sW[i] = wG[co * (K * K) + rest];
    }
    __syncthreads();

    const int tx = tid & 31;
    const int tq = tid >> 5;

    u64 acc2[32];
#pragma unroll
    for (int i = 0; i < 32; i++) acc2[i] = 0ull;

    {
        const float* colbase = sX + tx * IHP + tq * 4;
#pragma unroll 1
        for (int dx = 0; dx < K; dx++) {
            const float* colp = colbase + dx * IHP;
            u64 vv[K + 3];
#pragma unroll
            for (int j = 0; j < K + 3; j++) vv[j] = dup2(colp[j]);
#pragma unroll
            for (int dy = 0; dy < K; dy++) {
                const ulonglong2* wq = (const ulonglong2*)(sW + (dy * K + dx) * 16);
                ulonglong2 wa = wq[0];
                ulonglong2 wb = wq[1];
                ulonglong2 wc = wq[2];
                ulonglong2 wd = wq[3];
#pragma unroll
                for (int py = 0; py < 4; py++) {
                    u64 v = vv[dy + py];
                    fma2(acc2[0 * 4 + py], v, wa.x);
                    fma2(acc2[1 * 4 + py], v, wa.y);
                    fma2(acc2[2 * 4 + py], v, wb.x);
                    fma2(acc2[3 * 4 + py], v, wb.y);
                    fma2(acc2[4 * 4 + py], v, wc.x);
                    fma2(acc2[5 * 4 + py], v, wc.y);
                    fma2(acc2[6 * 4 + py], v, wd.x);
                    fma2(acc2[7 * 4 + py], v, wd.y);
                }
            }
        }
    }

    float s[4] = {0.f, 0.f, 0.f, 0.f};
    float mm[4] = {0.f, 0.f, 0.f, 0.f};
    {
        const float* mb = sMk + (tq * 4) * IW + tx;
#pragma unroll 1
        for (int dy = 0; dy < K; dy++)
#pragma unroll
            for (int dx = 0; dx < K; dx++)
#pragma unroll
                for (int py = 0; py < 4; py++) {
                    float m = mb[(dy + py) * IW + dx];
                    s[py] += m;
                    mm[py] = fmaxf(mm[py], m);
                }
    }
    float inv[4];
#pragma unroll
    for (int py = 0; py < 4; py++) inv[py] = 1.0f / (s[py] + 1e-8f);

    const int gy = blockIdx.y * TY + tq * 4;
    const int gx = blockIdx.x * TX + tx;

    float* mo = outM + (long long)n * HW + gy * IMW + gx;
#pragma unroll
    for (int py = 0; py < 4; py++) mo[py * IMW] = mm[py];

    float* ho = outH + ((long long)n * 16) * HW + gy * IMW + gx;
    const int lane = tid & 31;
    const int warp = tid >> 5;
#pragma unroll
    for (int cp = 0; cp < 8; cp++) {
        float b0 = bias[2 * cp], b1 = bias[2 * cp + 1];
        float p1a = 0.f, p2a = 0.f, p1b = 0.f, p2b = 0.f;
#pragma unroll
        for (int py = 0; py < 4; py++) {
            float a0, a1;
            unpk(a0, a1, acc2[cp * 4 + py]);
            float y0v = fmaf(a0, inv[py], b0);
            float y1v = fmaf(a1, inv[py], b1);
            ho[(long long)(2 * cp) * HW + py * IMW] = y0v;
            ho[(long long)(2 * cp + 1) * HW + py * IMW] = y1v;
            p1a += y0v; p2a = fmaf(y0v, y0v, p2a);
            p1b += y1v; p2b = fmaf(y1v, y1v, p2b);
        }
#pragma unroll
        for (int o = 16; o; o >>= 1) {
            p1a += __shfl_xor_sync(0xffffffffu, p1a, o);
            p2a += __shfl_xor_sync(0xffffffffu, p2a, o);
            p1b += __shfl_xor_sync(0xffffffffu, p1b, o);
            p2b += __shfl_xor_sync(0xffffffffu, p2b, o);
        }
        if (lane == 0) {
            sR[(2 * cp * 2 + 0) * 4 + warp] = p1a;
            sR[(2 * cp * 2 + 1) * 4 + warp] = p2a;
            sR[((2 * cp + 1) * 2 + 0) * 4 + warp] = p1b;
            sR[((2 * cp + 1) * 2 + 1) * 4 + warp] = p2b;
        }
    }
    __syncthreads();
    if (tid < 32) {
        float v = sR[tid * 4 + 0] + sR[tid * 4 + 1] + sR[tid * 4 + 2] + sR[tid * 4 + 3];
        int co = tid >> 1, which = tid & 1;
        atomicAdd(&stats[which * 16 + co], (double)v);
    }
}

// ---------------------------------------------------------------------------
__global__ void conv1x1_k(const float* __restrict__ h,
                          const float* __restrict__ mk,
                          const float* __restrict__ w6,
                          const float* __restrict__ b6,
                          const float2* __restrict__ aff,
                          float* __restrict__ y,
                          double* __restrict__ stats) {
    __shared__ float swv[16];
    __shared__ float2 sab[16];
    __shared__ float r1[8], r2[8];
    if (threadIdx.x < 16) {
        swv[threadIdx.x] = w6[threadIdx.x];
        sab[threadIdx.x] = aff[threadIdx.x];
    }
    __syncthreads();
    float bb = b6[0];
    float p1 = 0.f, p2 = 0.f;
    for (long long i = (long long)blockIdx.x * blockDim.x + threadIdx.x;
         i < 4LL * HW; i += (long long)gridDim.x * blockDim.x) {
        long long n = i >> 20;
        long long p = i & (HW - 1);
        float m = mk[i];
        float accv = 0.f;
#pragma unroll
        for (int c = 0; c < 16; c++) {
            float v = h[(n * 16 + c) * HW + p];
            float2 ab = sab[c];
            v = fmaxf(fmaf(v, ab.x, ab.y), 0.f);
            accv = fmaf(swv[c], v, accv);
        }
        float r = 1.0f / (m + 1e-8f);
        float yv = fmaf(accv * m, r, bb);
        y[i] = yv;
        p1 += yv;
        p2 = fmaf(yv, yv, p2);
    }
#pragma unroll
    for (int o = 16; o; o >>= 1) {
        p1 += __shfl_xor_sync(0xffffffffu, p1, o);
        p2 += __shfl_xor_sync(0xffffffffu, p2, o);
    }
    int warp = threadIdx.x >> 5, lane = threadIdx.x & 31;
    if (lane == 0) { r1[warp] = p1; r2[warp] = p2; }
    __syncthreads();
    if (threadIdx.x == 0) {
        float a = 0.f, b = 0.f;
        for (int w = 0; w < (int)(blockDim.x >> 5); w++) { a += r1[w]; b += r2[w]; }
        atomicAdd(&stats[0], (double)a);
        atomicAdd(&stats[16], (double)b);
    }
}

__global__ void final_k(const float* __restrict__ y,
                        const float2* __restrict__ ab,
                        float* __restrict__ o) {
    float2 t = ab[0];
    for (long long i = (long long)blockIdx.x * blockDim.x + threadIdx.x;
         i < 4LL * HW; i += (long long)gridDim.x * blockDim.x)
        o[i] = fmaf(y[i], t.x, t.y);
}

// ---------------------------------------------------------------------------
static constexpr int sconv_smem(int K) {
    int IW = 32 + K - 1, IH = 16 + K - 1;
    int IHP = IH | 1;
    int smn = IH * IW;
    int sxn = IW * IHP;
    int swoff = ((smn + sxn + 3) / 4) * 4;
    return (swoff + K * K * 16 + 128) * 4;
}
static constexpr int tmma_smem(int K) {
    int TY = 4, NPX = 128 + K - 1, NPXW = (NPX + 7) & ~7, R = K + TY - 1;
    int AH = ((1024 + R * NPXW * 4 + 127) / 128) * 128;
    return AH + 2 * R * NPXW * 32;
}

extern "C" void kernel_launch(void* const* d_in, const int* in_sizes, int n_in,
                              void* d_out, int out_size) {
    (void)in_sizes; (void)n_in; (void)out_size;
    const float* x = (const float*)d_in[0];
    const float *wp[6], *bp[6], *gp[6], *btp[6];
    for (int i = 0; i < 6; i++) {
        wp[i]  = (const float*)d_in[1 + 4 * i];
        bp[i]  = (const float*)d_in[2 + 4 * i];
        gp[i]  = (const float*)d_in[3 + 4 * i];
        btp[i] = (const float*)d_in[4 + 4 * i];
    }

    float *h0, *h1, *m0, *m1;
    double* st;
    float2* ab;
    u32* bf;
    cudaGetSymbolAddress((void**)&h0, g_h0);
    cudaGetSymbolAddress((void**)&h1, g_h1);
    cudaGetSymbolAddress((void**)&m0, g_m0);
    cudaGetSymbolAddress((void**)&m1, g_m1);
    cudaGetSymbolAddress((void**)&st, g_stats);
    cudaGetSymbolAddress((void**)&ab, g_affine);
    cudaGetSymbolAddress((void**)&bf, g_bfrag);

    cudaFuncSetAttribute(sconv_k<11>, cudaFuncAttributeMaxDynamicSharedMemorySize, sconv_smem(11));
    cudaFuncSetAttribute(tmma_conv_k<7, true>, cudaFuncAttributeMaxDynamicSharedMemorySize, tmma_smem(7));
    cudaFuncSetAttribute(tmma_conv_k<5, true>, cudaFuncAttributeMaxDynamicSharedMemorySize, tmma_smem(5));
    cudaFuncSetAttribute(tmma_conv_k<3, true>, cudaFuncAttributeMaxDynamicSharedMemorySize, tmma_smem(3));

    dim3 sgrid(1024 / 32, 1024 / 16, 4);
    dim3 tgrid(1024 / 128, 1024 / 4, 4);

    // B-fragment tap offsets (u32 units): L2=0, L3=49*256, L4=74*256, L5=83*256
    u32* bf2 = bf;
    u32* bf3 = bf + 49 * 256;
    u32* bf4p = bf + 74 * 256;
    u32* bf5 = bf + 83 * 256;

    zero_stats_k<<<1, 192>>>();
    prep_all_b<<<23, 256>>>(wp[1], wp[2], wp[3], wp[4], bf);

    sconv_k<11><<<sgrid, 128, sconv_smem(11)>>>(
        x, 2LL * HW, x + HW, 2LL * HW, wp[0], bp[0], h0, m0, st + 0);
    affine_k<<<1, 16>>>(st + 0, gp[0], btp[0], ab + 0, 16);

    tmma_conv_k<7, true><<<tgrid, 256, tmma_smem(7)>>>(
        h0, 16LL * HW, m0, (long long)HW, bf2, bp[1], ab + 0, h1, m1, st + 32);
    affine_k<<<1, 16>>>(st + 32, gp[1], btp[1], ab + 16, 16);

    tmma_conv_k<5, true><<<tgrid, 256, tmma_smem(5)>>>(
        h1, 16LL * HW, m1, (long long)HW, bf3, bp[2], ab + 16, h0, m0, st + 64);
    affine_k<<<1, 16>>>(st + 64, gp[2], btp[2], ab + 32, 16);

    tmma_conv_k<3, true><<<tgrid, 256, tmma_smem(3)>>>(
        h0, 16LL * HW, m0, (long long)HW, bf4p, bp[3], ab + 32, h1, m1, st + 96);
    affine_k<<<1, 16>>>(st + 96, gp[3], btp[3], ab + 48, 16);

    tmma_conv_k<3, true><<<tgrid, 256, tmma_smem(3)>>>(
        h1, 16LL * HW, m1, (long long)HW, bf5, bp[4], ab + 48, h0, m0, st + 128);
    affine_k<<<1, 16>>>(st + 128, gp[4], btp[4], ab + 64, 16);

    conv1x1_k<<<1184, 256>>>(h0, m0, wp[5], bp[5], ab + 64, h1, st + 160);
    affine_k<<<1, 16>>>(st + 160, gp[5], btp[5], ab + 80, 1);

    final_k<<<4096, 256>>>(h1, ab + 80, (float*)d_out);
}

// round 10
// speedup vs baseline: 2.2513x; 1.0225x over previous
#include <cuda_runtime.h>
#include <cuda_bf16.h>
#include <math.h>

// ---------------------------------------------------------------------------
// SparseConvNet: 6 partial-conv layers. N=4, H=W=1024.
// Round 10: PRMT/bf16x2 pair-packed staging (-25% staging ALU), BN affine
// computed in-block from stats (affine_k launches removed), stats zeroing
// folded into prep. MMA core (TY=4 rolling window) unchanged from R9.
// ---------------------------------------------------------------------------

#define HW   (1024 * 1024)
#define IMW  1024
#define NPIX (4LL * HW)

__device__ float  g_h0[4 * 16 * HW];
__device__ float  g_h1[4 * 16 * HW];
__device__ float  g_m0[4 * HW];
__device__ float  g_m1[4 * HW];
__device__ double g_stats[6 * 32];
__device__ unsigned int g_bfrag[92 * 2 * 32 * 4];   // 49+25+9+9 taps

typedef unsigned long long u64;
typedef unsigned int u32;
typedef unsigned short u16;

__device__ __forceinline__ u64 dup2(float v) {
    u64 r;
    asm("mov.b64 %0, {%1, %1};" : "=l"(r) : "f"(v));
    return r;
}
__device__ __forceinline__ void fma2(u64& d, u64 a, u64 b) {
    asm("fma.rn.f32x2 %0, %1, %2, %0;" : "+l"(d) : "l"(a), "l"(b));
}
__device__ __forceinline__ void unpk(float& lo, float& hi, u64 v) {
    asm("mov.b64 {%0, %1}, %2;" : "=f"(lo), "=f"(hi) : "l"(v));
}
__device__ __forceinline__ u32 smem_u32(const void* p) {
    u32 a;
    asm("{ .reg .u64 t; cvta.to.shared.u64 t, %1; cvt.u32.u64 %0, t; }"
        : "=r"(a) : "l"(p));
    return a;
}
__device__ __forceinline__ void ldsm4(u32* r, u32 a) {
    asm volatile("ldmatrix.sync.aligned.m8n8.x4.shared.b16 {%0,%1,%2,%3}, [%4];"
                 : "=r"(r[0]), "=r"(r[1]), "=r"(r[2]), "=r"(r[3]) : "r"(a));
}
__device__ __forceinline__ void mma16816(float* d, const u32* a, u32 b0, u32 b1) {
    asm volatile(
        "mma.sync.aligned.m16n8k16.row.col.f32.bf16.bf16.f32 "
        "{%0,%1,%2,%3}, {%4,%5,%6,%7}, {%8,%9}, {%0,%1,%2,%3};"
        : "+f"(d[0]), "+f"(d[1]), "+f"(d[2]), "+f"(d[3])
        : "r"(a[0]), "r"(a[1]), "r"(a[2]), "r"(a[3]), "r"(b0), "r"(b1));
}
// truncation hi/lo split (scalar, used in prep): hi = top16, lo = RN(t - hi)
__device__ __forceinline__ void bsplit(float t, u16& h, u16& l) {
    u32 u = __float_as_uint(t);
    h = (u16)(u >> 16);
    float fh = __uint_as_float(u & 0xFFFF0000u);
    l = __bfloat16_as_ushort(__float2bfloat16(t - fh));
}
// packed pair split: h = hi16(v0)|hi16(v1)<<16 via PRMT; l = bf16x2 of residuals
__device__ __forceinline__ void bsplit2(float v0, float v1, u32& h, u32& l) {
    u32 u0 = __float_as_uint(v0), u1 = __float_as_uint(v1);
    asm("prmt.b32 %0, %1, %2, 0x7632;" : "=r"(h) : "r"(u0), "r"(u1));
    float f0 = __uint_as_float(u0 & 0xFFFF0000u);
    float f1 = __uint_as_float(u1 & 0xFFFF0000u);
    asm("cvt.rn.bf16x2.f32 %0, %1, %2;" : "=r"(l) : "f"(v1 - f1), "f"(v0 - f0));
}

// ---------------------------------------------------------------------------
// Combined prep: zero stats + B fragments for layers 2..5 (K=7,5,3,3).
// ---------------------------------------------------------------------------
__global__ void prep_all_b(const float* __restrict__ w2, const float* __restrict__ w3,
                           const float* __restrict__ w4, const float* __restrict__ w5,
                           u32* __restrict__ bf, double* __restrict__ st) {
    if (blockIdx.x == 0 && threadIdx.x < 192) st[threadIdx.x] = 0.0;
    const int total = 92 * 2 * 32;
    for (int i = blockIdx.x * blockDim.x + threadIdx.x; i < total;
         i += gridDim.x * blockDim.x) {
        int lane = i & 31;
        int half = (i >> 5) & 1;
        int gt = i >> 6;
        const float* w;
        int K, tap;
        if (gt < 49)      { w = w2; K = 7; tap = gt; }
        else if (gt < 74) { w = w3; K = 5; tap = gt - 49; }
        else if (gt < 83) { w = w4; K = 3; tap = gt - 74; }
        else              { w = w5; K = 3; tap = gt - 83; }
        int dy = tap / K, dx = tap - dy * K;
        int k0 = (lane & 3) * 2, nn = lane >> 2;
        u32 out[4];
#pragma unroll
        for (int t = 0; t < 2; t++) {
#pragma unroll
            for (int kk = 0; kk < 2; kk++) {
                int co = t * 8 + nn;
                int k = k0 + kk * 8;
                float w0 = w[((co * 16 + k) * K + dy) * K + dx];
                float w1 = w[((co * 16 + k + 1) * K + dy) * K + dx];
                u16 h0, l0, h1, l1;
                bsplit(w0, h0, l0);
                bsplit(w1, h1, l1);
                u16 a = half ? l0 : h0, b = half ? l1 : h1;
                out[t * 2 + kk] = (u32)a | ((u32)b << 16);
            }
        }
        ((uint4*)bf)[i] = make_uint4(out[0], out[1], out[2], out[3]);
    }
}

// ---------------------------------------------------------------------------
// Tensor-core partial-conv layer (cin=cout=16). Tile = 128 px * TY=4 rows,
// 256 threads / 8 warps. BN affine of the PREVIOUS layer computed in-block
// from stats. A smem [R=K+3][NPXW][16ci] bf16 hi/lo, XOR half-swizzle.
// Mainloop per dx: rolling 4-slot A register window over dy.
// ---------------------------------------------------------------------------
template <int K, bool AFF>
__global__ void __launch_bounds__(256, 2) tmma_conv_k(
    const float* __restrict__ in, long long inNS,
    const float* __restrict__ mk, long long mkNS,
    const u32* __restrict__ bfrag, const float* __restrict__ bias,
    const double* __restrict__ stPrev,
    const float* __restrict__ gamPrev, const float* __restrict__ betPrev,
    float* __restrict__ outH, float* __restrict__ outM,
    double* __restrict__ stats) {
    constexpr int TY = 4, P = K / 2;
    constexpr int NPX = 128 + K - 1;
    constexpr int NPXW = (NPX + 7) & ~7;
    constexpr int R = K + TY - 1;
    constexpr int ROWB = NPXW * 32;
    constexpr int SR_OFF = 0;
    constexpr int AB_OFF = 1024;                 // 16 float2 affine
    constexpr int MK_OFF = AB_OFF + 128;
    constexpr int AH_OFF = ((MK_OFF + R * NPXW * 4 + 127) / 128) * 128;
    constexpr int AL_OFF = AH_OFF + R * ROWB;

    extern __shared__ char smx[];
    float*  sR  = (float*)(smx + SR_OFF);
    float2* sAB = (float2*)(smx + AB_OFF);
    float*  sMk = (float*)(smx + MK_OFF);
    const u32 sb = smem_u32(smx);

    const int tid = threadIdx.x;
    const int wid = tid >> 5;
    const int lane = tid & 31;
    const int n  = blockIdx.z;
    const int x0 = blockIdx.x * 128;
    const int y0 = blockIdx.y * TY;

    // ---- affine of previous layer (once per block) ----
    if (tid < 16) {
        if (AFF) {
            double mean = stPrev[tid] / (double)NPIX;
            double var  = stPrev[16 + tid] / (double)NPIX - mean * mean;
            float inv = rsqrtf((float)var + 1e-5f);
            float a = gamPrev[tid] * inv;
            sAB[tid] = make_float2(a, betPrev[tid] - (float)mean * a);
        } else {
            sAB[tid] = make_float2(1.f, 0.f);
        }
    }

    // ---- mask window ----
    const float* mkn = mk + (long long)n * mkNS;
    for (int i = tid; i < R * NPXW; i += 256) {
        int r = i / NPXW, p = i - r * NPXW;
        int gy = y0 - P + r, gx = x0 - P + p;
        float m = 0.f;
        if ((unsigned)gy < 1024u && (unsigned)gx < 1024u) m = mkn[gy * IMW + gx];
        sMk[i] = m;
    }
    __syncthreads();

    // ---- stage A (masked + affine + relu, bf16 hi/lo, half-swizzled) ----
    float2 abr[16];
#pragma unroll
    for (int ci = 0; ci < 16; ci++) abr[ci] = sAB[ci];
    const float* inn = in + (long long)n * inNS;
    for (int i = tid; i < R * NPX; i += 256) {
        int r = i / NPX, p = i - r * NPX;
        int gy = y0 - P + r, gx = x0 - P + p;
        bool ok = (unsigned)gy < 1024u && (unsigned)gx < 1024u;
        float m = sMk[r * NPXW + p];
        const float* ip = inn + (long long)gy * IMW + gx;
        u32 hp[8], lp[8];
#pragma unroll
        for (int c2 = 0; c2 < 8; c2++) {
            float v0 = ok ? ip[(long long)(2 * c2) * HW] : 0.f;
            float v1 = ok ? ip[(long long)(2 * c2 + 1) * HW] : 0.f;
            if (AFF) {
                v0 = fmaxf(fmaf(v0, abr[2 * c2].x, abr[2 * c2].y), 0.f);
                v1 = fmaxf(fmaf(v1, abr[2 * c2 + 1].x, abr[2 * c2 + 1].y), 0.f);
            }
            v0 *= m;
            v1 *= m;
            bsplit2(v0, v1, hp[c2], lp[c2]);
        }
        u32 s = ((p >> 2) & 1) * 16;            // half swizzle
        char* ah = smx + AH_OFF + r * ROWB + p * 32;
        char* al = smx + AL_OFF + r * ROWB + p * 32;
        *(uint4*)(ah + s)        = make_uint4(hp[0], hp[1], hp[2], hp[3]);
        *(uint4*)(ah + (16 ^ s)) = make_uint4(hp[4], hp[5], hp[6], hp[7]);
        *(uint4*)(al + s)        = make_uint4(lp[0], lp[1], lp[2], lp[3]);
        *(uint4*)(al + (16 ^ s)) = make_uint4(lp[4], lp[5], lp[6], lp[7]);
    }
    __syncthreads();

    // ---- MMA mainloop ----
    const int seg = wid;
    float D[TY][2][4];
#pragma unroll
    for (int y = 0; y < TY; y++)
#pragma unroll
        for (int t = 0; t < 2; t++)
#pragma unroll
            for (int j = 0; j < 4; j++) D[y][t][j] = 0.f;

    const int l15 = lane & 15;
    const int kh = lane >> 4;
    const uint4* bf4 = (const uint4*)bfrag;

#pragma unroll 1
    for (int dx = 0; dx < K; dx++) {
        u32 sw = (u32)(((l15 + dx) >> 2) & 1);
        u32 apx = (u32)(seg * 16 + l15 + dx);
        u32 aoff = apx * 32 + (((u32)kh ^ sw) * 16);
        u32 aH = sb + AH_OFF + aoff;
        u32 aL = sb + AL_OFF + aoff;
        u32 Wh[4][4], Wl[4][4];
#pragma unroll
        for (int r = 0; r < 3; r++) {
            ldsm4(Wh[r], aH + r * ROWB);
            ldsm4(Wl[r], aL + r * ROWB);
        }
#pragma unroll
        for (int dy = 0; dy < K; dy++) {
            const int rin = dy + 3;
            ldsm4(Wh[rin & 3], aH + rin * ROWB);
            ldsm4(Wl[rin & 3], aL + rin * ROWB);
            int tap = dy * K + dx;
            uint4 BH = bf4[(tap * 2 + 0) * 32 + lane];
            uint4 BL = bf4[(tap * 2 + 1) * 32 + lane];
#pragma unroll
            for (int y = 0; y < TY; y++) {
                const int sl = (dy + y) & 3;
                mma16816(D[y][0], Wh[sl], BH.x, BH.y);
                mma16816(D[y][1], Wh[sl], BH.z, BH.w);
                mma16816(D[y][0], Wl[sl], BH.x, BH.y);
                mma16816(D[y][1], Wl[sl], BH.z, BH.w);
                mma16816(D[y][0], Wh[sl], BL.x, BL.y);
                mma16816(D[y][1], Wh[sl], BL.z, BL.w);
            }
        }
    }

    // ---- mask-sum conv + maxpool: lane handles rows (yl, yl+2) at pxl ----
    const int yl = lane >> 4, pxl = lane & 15;
    float s[2] = {0.f, 0.f}, mm[2] = {0.f, 0.f};
    {
        const float* mb = sMk + seg * 16 + pxl;
#pragma unroll 1
        for (int dy = 0; dy < K; dy++)
#pragma unroll
            for (int dx = 0; dx < K; dx++) {
#pragma unroll
                for (int j = 0; j < 2; j++) {
                    float m = mb[(yl + 2 * j + dy) * NPXW + dx];
                    s[j] += m;
                    mm[j] = fmaxf(mm[j], m);
                }
            }
    }
    float invv0 = 1.0f / (s[0] + 1e-8f);
    float invv1 = 1.0f / (s[1] + 1e-8f);
    outM[(long long)n * HW + (long long)(y0 + yl) * IMW + x0 + seg * 16 + pxl] = mm[0];
    outM[(long long)n * HW + (long long)(y0 + yl + 2) * IMW + x0 + seg * 16 + pxl] = mm[1];

    // ---- epilogue: scale, bias, store, stats ----
    float bco[4];
#pragma unroll
    for (int t = 0; t < 2; t++)
#pragma unroll
        for (int j = 0; j < 2; j++)
            bco[t * 2 + j] = bias[t * 8 + (lane & 3) * 2 + j];
    float p1[4] = {0.f, 0.f, 0.f, 0.f}, p2[4] = {0.f, 0.f, 0.f, 0.f};
    const int pxa = seg * 16 + (lane >> 2);

#pragma unroll
    for (int y = 0; y < TY; y++) {
        float vsel = (y < 2) ? invv0 : invv1;
        float inva = __shfl_sync(0xffffffffu, vsel, (y & 1) * 16 + (lane >> 2));
        float invb = __shfl_sync(0xffffffffu, vsel, (y & 1) * 16 + (lane >> 2) + 8);
        int gy = y0 + y;
        float* hb = outH + (long long)n * 16 * HW + (long long)gy * IMW + x0;
#pragma unroll
        for (int t = 0; t < 2; t++) {
#pragma unroll
            for (int j = 0; j < 2; j++) {
                int co = t * 8 + (lane & 3) * 2 + j;
                float bc = bco[t * 2 + j];
                float v0 = fmaf(D[y][t][j], inva, bc);
                float v1 = fmaf(D[y][t][j + 2], invb, bc);
                hb[(long long)co * HW + pxa] = v0;
                hb[(long long)co * HW + pxa + 8] = v1;
                p1[t * 2 + j] += v0 + v1;
                p2[t * 2 + j] = fmaf(v0, v0, fmaf(v1, v1, p2[t * 2 + j]));
            }
        }
    }
#pragma unroll
    for (int k = 0; k < 4; k++) {
#pragma unroll
        for (int o = 4; o < 32; o <<= 1) {
            p1[k] += __shfl_xor_sync(0xffffffffu, p1[k], o);
            p2[k] += __shfl_xor_sync(0xffffffffu, p2[k], o);
        }
    }
    if (lane < 4) {
#pragma unroll
        for (int t = 0; t < 2; t++)
#pragma unroll
            for (int j = 0; j < 2; j++) {
                int co = t * 8 + lane * 2 + j;
                sR[(co * 2 + 0) * 8 + wid] = p1[t * 2 + j];
                sR[(co * 2 + 1) * 8 + wid] = p2[t * 2 + j];
            }
    }
    __syncthreads();
    if (tid < 32) {
        int co = tid >> 1, which = tid & 1;
        float v = 0.f;
#pragma unroll
        for (int w = 0; w < 8; w++) v += sR[tid * 8 + w];
        atomicAdd(&stats[which * 16 + co], (double)v);
    }
}

// ---------------------------------------------------------------------------
// Scalar FFMA2 partial-conv — layer 1 (cin=1, K=11), no input affine.
// ---------------------------------------------------------------------------
template <int K>
__global__ void __launch_bounds__(128, 4) sconv_k(
    const float* __restrict__ in, long long inNS,
    const float* __restrict__ mk, long long mkNS,
    const float* __restrict__ wG, const float* __restrict__ bias,
    float* __restrict__ outH, float* __restrict__ outM,
    double* __restrict__ stats) {
    constexpr int TX = 32, TY = 16, P = K / 2;
    constexpr int IW = TX + K - 1;
    constexpr int IH = TY + K - 1;
    constexpr int IHP = IH | 1;
    constexpr int SMN = IH * IW;
    constexpr int SXN = IW * IHP;
    constexpr int SWOFF = ((SMN + SXN + 3) / 4) * 4;
    constexpr int SWN = K * K * 16;

    extern __shared__ float sm[];
    float* sMk = sm;
    float* sX  = sm + SMN;
    float* sW  = sm + SWOFF;
    float* sR  = sm + SWOFF + SWN;

    const int tid = threadIdx.x;
    const int n = blockIdx.z;
    const int x0 = blockIdx.x * TX - P;
    const int y0 = blockIdx.y * TY - P;

    const float* mkn = mk + (long long)n * mkNS;
    const float* inn = in + (long long)n * inNS;
    for (int i = tid; i < SMN; i += 128) {
        int ly = i / IW, lx = i - ly * IW;
        int gy = y0 + ly, gx = x0 + lx;
        float m = 0.f, v = 0.f;
        if ((unsigned)gy < 1024u && (unsigned)gx < 1024u) {
            m = mkn[gy * IMW + gx];
            v = inn[gy * IMW + gx];
        }
        sMk[i] = m;
        sX[lx * IHP + ly] = v * m;
    }
    for (int i = tid; i < SWN; i += 128) {
        int co = i & 15;
        int rest = i >> 4;
        sW[i] = wG[co * (K * K) + rest];
    }
    __syncthreads();

    const int tx = tid & 31;
    const int tq = tid >> 5;

    u64 acc2[32];
#pragma unroll
    for (int i = 0; i < 32; i++) acc2[i] = 0ull;

    {
        const float* colbase = sX + tx * IHP + tq * 4;
#pragma unroll 1
        for (int dx = 0; dx < K; dx++) {
            const float* colp = colbase + dx * IHP;
            u64 vv[K + 3];
#pragma unroll
            for (int j = 0; j < K + 3; j++) vv[j] = dup2(colp[j]);
#pragma unroll
            for (int dy = 0; dy < K; dy++) {
                const ulonglong2* wq = (const ulonglong2*)(sW + (dy * K + dx) * 16);
                ulonglong2 wa = wq[0];
                ulonglong2 wb = wq[1];
                ulonglong2 wc = wq[2];
                ulonglong2 wd = wq[3];
#pragma unroll
                for (int py = 0; py < 4; py++) {
                    u64 v = vv[dy + py];
                    fma2(acc2[0 * 4 + py], v, wa.x);
                    fma2(acc2[1 * 4 + py], v, wa.y);
                    fma2(acc2[2 * 4 + py], v, wb.x);
                    fma2(acc2[3 * 4 + py], v, wb.y);
                    fma2(acc2[4 * 4 + py], v, wc.x);
                    fma2(acc2[5 * 4 + py], v, wc.y);
                    fma2(acc2[6 * 4 + py], v, wd.x);
                    fma2(acc2[7 * 4 + py], v, wd.y);
                }
            }
        }
    }

    float s[4] = {0.f, 0.f, 0.f, 0.f};
    float mm[4] = {0.f, 0.f, 0.f, 0.f};
    {
        const float* mb = sMk + (tq * 4) * IW + tx;
#pragma unroll 1
        for (int dy = 0; dy < K; dy++)
#pragma unroll
            for (int dx = 0; dx < K; dx++)
#pragma unroll
                for (int py = 0; py < 4; py++) {
                    float m = mb[(dy + py) * IW + dx];
                    s[py] += m;
                    mm[py] = fmaxf(mm[py], m);
                }
    }
    float inv[4];
#pragma unroll
    for (int py = 0; py < 4; py++) inv[py] = 1.0f / (s[py] + 1e-8f);

    const int gy = blockIdx.y * TY + tq * 4;
    const int gx = blockIdx.x * TX + tx;

    float* mo = outM + (long long)n * HW + gy * IMW + gx;
#pragma unroll
    for (int py = 0; py < 4; py++) mo[py * IMW] = mm[py];

    float* ho = outH + ((long long)n * 16) * HW + gy * IMW + gx;
    const int lane = tid & 31;
    const int warp = tid >> 5;
#pragma unroll
    for (int cp = 0; cp < 8; cp++) {
        float b0 = bias[2 * cp], b1 = bias[2 * cp + 1];
        float p1a = 0.f, p2a = 0.f, p1b = 0.f, p2b = 0.f;
#pragma unroll
        for (int py = 0; py < 4; py++) {
            float a0, a1;
            unpk(a0, a1, acc2[cp * 4 + py]);
            float y0v = fmaf(a0, inv[py], b0);
            float y1v = fmaf(a1, inv[py], b1);
            ho[(long long)(2 * cp) * HW + py * IMW] = y0v;
            ho[(long long)(2 * cp + 1) * HW + py * IMW] = y1v;
            p1a += y0v; p2a = fmaf(y0v, y0v, p2a);
            p1b += y1v; p2b = fmaf(y1v, y1v, p2b);
        }
#pragma unroll
        for (int o = 16; o; o >>= 1) {
            p1a += __shfl_xor_sync(0xffffffffu, p1a, o);
            p2a += __shfl_xor_sync(0xffffffffu, p2a, o);
            p1b += __shfl_xor_sync(0xffffffffu, p1b, o);
            p2b += __shfl_xor_sync(0xffffffffu, p2b, o);
        }
        if (lane == 0) {
            sR[(2 * cp * 2 + 0) * 4 + warp] = p1a;
            sR[(2 * cp * 2 + 1) * 4 + warp] = p2a;
            sR[((2 * cp + 1) * 2 + 0) * 4 + warp] = p1b;
            sR[((2 * cp + 1) * 2 + 1) * 4 + warp] = p2b;
        }
    }
    __syncthreads();
    if (tid < 32) {
        float v = sR[tid * 4 + 0] + sR[tid * 4 + 1] + sR[tid * 4 + 2] + sR[tid * 4 + 3];
        int co = tid >> 1, which = tid & 1;
        atomicAdd(&stats[which * 16 + co], (double)v);
    }
}

// ---------------------------------------------------------------------------
// Layer 6: 1x1 partial conv, 16 -> 1; affine of layer 5 computed in-block.
// ---------------------------------------------------------------------------
__global__ void conv1x1_k(const float* __restrict__ h,
                          const float* __restrict__ mk,
                          const float* __restrict__ w6,
                          const float* __restrict__ b6,
                          const double* __restrict__ st5,
                          const float* __restrict__ g5,
                          const float* __restrict__ bt5,
                          float* __restrict__ y,
                          double* __restrict__ stats) {
    __shared__ float swv[16];
    __shared__ float2 sab[16];
    __shared__ float r1[8], r2[8];
    if (threadIdx.x < 16) {
        swv[threadIdx.x] = w6[threadIdx.x];
        double mean = st5[threadIdx.x] / (double)NPIX;
        double var  = st5[16 + threadIdx.x] / (double)NPIX - mean * mean;
        float inv = rsqrtf((float)var + 1e-5f);
        float a = g5[threadIdx.x] * inv;
        sab[threadIdx.x] = make_float2(a, bt5[threadIdx.x] - (float)mean * a);
    }
    __syncthreads();
    float bb = b6[0];
    float p1 = 0.f, p2 = 0.f;
    for (long long i = (long long)blockIdx.x * blockDim.x + threadIdx.x;
         i < 4LL * HW; i += (long long)gridDim.x * blockDim.x) {
        long long n = i >> 20;
        long long p = i & (HW - 1);
        float m = mk[i];
        float accv = 0.f;
#pragma unroll
        for (int c = 0; c < 16; c++) {
            float v = h[(n * 16 + c) * HW + p];
            float2 ab = sab[c];
            v = fmaxf(fmaf(v, ab.x, ab.y), 0.f);
            accv = fmaf(swv[c], v, accv);
        }
        float r = 1.0f / (m + 1e-8f);
        float yv = fmaf(accv * m, r, bb);
        y[i] = yv;
        p1 += yv;
        p2 = fmaf(yv, yv, p2);
    }
#pragma unroll
    for (int o = 16; o; o >>= 1) {
        p1 += __shfl_xor_sync(0xffffffffu, p1, o);
        p2 += __shfl_xor_sync(0xffffffffu, p2, o);
    }
    int warp = threadIdx.x >> 5, lane = threadIdx.x & 31;
    if (lane == 0) { r1[warp] = p1; r2[warp] = p2; }
    __syncthreads();
    if (threadIdx.x == 0) {
        float a = 0.f, b = 0.f;
        for (int w = 0; w < (int)(blockDim.x >> 5); w++) { a += r1[w]; b += r2[w]; }
        atomicAdd(&stats[0], (double)a);
        atomicAdd(&stats[16], (double)b);
    }
}

// Final BN (no relu); affine of layer 6 computed per block.
__global__ void final_k(const float* __restrict__ y,
                        const double* __restrict__ st6,
                        const float* __restrict__ g6,
                        const float* __restrict__ bt6,
                        float* __restrict__ o) {
    __shared__ float2 t;
    if (threadIdx.x == 0) {
        double mean = st6[0] / (double)NPIX;
        double var  = st6[16] / (double)NPIX - mean * mean;
        float inv = rsqrtf((float)var + 1e-5f);
        float a = g6[0] * inv;
        t = make_float2(a, bt6[0] - (float)mean * a);
    }
    __syncthreads();
    float2 tt = t;
    for (long long i = (long long)blockIdx.x * blockDim.x + threadIdx.x;
         i < 4LL * HW; i += (long long)gridDim.x * blockDim.x)
        o[i] = fmaf(y[i], tt.x, tt.y);
}

// ---------------------------------------------------------------------------
static constexpr int sconv_smem(int K) {
    int IW = 32 + K - 1, IH = 16 + K - 1;
    int IHP = IH | 1;
    int smn = IH * IW;
    int sxn = IW * IHP;
    int swoff = ((smn + sxn + 3) / 4) * 4;
    return (swoff + K * K * 16 + 128) * 4;
}
static constexpr int tmma_smem(int K) {
    int TY = 4, NPX = 128 + K - 1, NPXW = (NPX + 7) & ~7, R = K + TY - 1;
    int MK = 1024 + 128;
    int AH = ((MK + R * NPXW * 4 + 127) / 128) * 128;
    return AH + 2 * R * NPXW * 32;
}

extern "C" void kernel_launch(void* const* d_in, const int* in_sizes, int n_in,
                              void* d_out, int out_size) {
    (void)in_sizes; (void)n_in; (void)out_size;
    const float* x = (const float*)d_in[0];
    const float *wp[6], *bp[6], *gp[6], *btp[6];
    for (int i = 0; i < 6; i++) {
        wp[i]  = (const float*)d_in[1 + 4 * i];
        bp[i]  = (const float*)d_in[2 + 4 * i];
        gp[i]  = (const float*)d_in[3 + 4 * i];
        btp[i] = (const float*)d_in[4 + 4 * i];
    }

    float *h0, *h1, *m0, *m1;
    double* st;
    u32* bf;
    cudaGetSymbolAddress((void**)&h0, g_h0);
    cudaGetSymbolAddress((void**)&h1, g_h1);
    cudaGetSymbolAddress((void**)&m0, g_m0);
    cudaGetSymbolAddress((void**)&m1, g_m1);
    cudaGetSymbolAddress((void**)&st, g_stats);
    cudaGetSymbolAddress((void**)&bf, g_bfrag);

    cudaFuncSetAttribute(sconv_k<11>, cudaFuncAttributeMaxDynamicSharedMemorySize, sconv_smem(11));
    cudaFuncSetAttribute(tmma_conv_k<7, true>, cudaFuncAttributeMaxDynamicSharedMemorySize, tmma_smem(7));
    cudaFuncSetAttribute(tmma_conv_k<5, true>, cudaFuncAttributeMaxDynamicSharedMemorySize, tmma_smem(5));
    cudaFuncSetAttribute(tmma_conv_k<3, true>, cudaFuncAttributeMaxDynamicSharedMemorySize, tmma_smem(3));

    dim3 sgrid(1024 / 32, 1024 / 16, 4);
    dim3 tgrid(1024 / 128, 1024 / 4, 4);

    u32* bf2 = bf;
    u32* bf3 = bf + 49 * 256;
    u32* bf4p = bf + 74 * 256;
    u32* bf5 = bf + 83 * 256;

    prep_all_b<<<23, 256>>>(wp[1], wp[2], wp[3], wp[4], bf, st);

    sconv_k<11><<<sgrid, 128, sconv_smem(11)>>>(
        x, 2LL * HW, x + HW, 2LL * HW, wp[0], bp[0], h0, m0, st + 0);

    tmma_conv_k<7, true><<<tgrid, 256, tmma_smem(7)>>>(
        h0, 16LL * HW, m0, (long long)HW, bf2, bp[1],
        st + 0, gp[0], btp[0], h1, m1, st + 32);

    tmma_conv_k<5, true><<<tgrid, 256, tmma_smem(5)>>>(
        h1, 16LL * HW, m1, (long long)HW, bf3, bp[2],
        st + 32, gp[1], btp[1], h0, m0, st + 64);

    tmma_conv_k<3, true><<<tgrid, 256, tmma_smem(3)>>>(
        h0, 16LL * HW, m0, (long long)HW, bf4p, bp[3],
        st + 64, gp[2], btp[2], h1, m1, st + 96);

    tmma_conv_k<3, true><<<tgrid, 256, tmma_smem(3)>>>(
        h1, 16LL * HW, m1, (long long)HW, bf5, bp[4],
        st + 96, gp[3], btp[3], h0, m0, st + 128);

    conv1x1_k<<<1184, 256>>>(h0, m0, wp[5], bp[5],
                             st + 128, gp[4], btp[4], h1, st + 160);

    final_k<<<4096, 256>>>(h1, st + 160, gp[5], btp[5], (float*)d_out);
}

// round 11
// speedup vs baseline: 2.3531x; 1.0452x over previous
#include <cuda_runtime.h>
#include <cuda_bf16.h>
#include <math.h>

// ---------------------------------------------------------------------------
// SparseConvNet: 6 partial-conv layers. N=4, H=W=1024.
// Round 11: 64-px tiles / 128-thread blocks -> 4 blocks/SM so staging of one
// block overlaps MMA of others (tensor was 63% with phase-serialized 2 blocks).
// float4 conv1x1/final. MMA core + layouts unchanged from R10.
// ---------------------------------------------------------------------------

#define HW   (1024 * 1024)
#define IMW  1024
#define NPIX (4LL * HW)

__device__ float  g_h0[4 * 16 * HW];
__device__ float  g_h1[4 * 16 * HW];
__device__ float  g_m0[4 * HW];
__device__ float  g_m1[4 * HW];
__device__ double g_stats[6 * 32];
__device__ unsigned int g_bfrag[92 * 2 * 32 * 4];   // 49+25+9+9 taps

typedef unsigned long long u64;
typedef unsigned int u32;
typedef unsigned short u16;

__device__ __forceinline__ u64 dup2(float v) {
    u64 r;
    asm("mov.b64 %0, {%1, %1};" : "=l"(r) : "f"(v));
    return r;
}
__device__ __forceinline__ void fma2(u64& d, u64 a, u64 b) {
    asm("fma.rn.f32x2 %0, %1, %2, %0;" : "+l"(d) : "l"(a), "l"(b));
}
__device__ __forceinline__ void unpk(float& lo, float& hi, u64 v) {
    asm("mov.b64 {%0, %1}, %2;" : "=f"(lo), "=f"(hi) : "l"(v));
}
__device__ __forceinline__ u32 smem_u32(const void* p) {
    u32 a;
    asm("{ .reg .u64 t; cvta.to.shared.u64 t, %1; cvt.u32.u64 %0, t; }"
        : "=r"(a) : "l"(p));
    return a;
}
__device__ __forceinline__ void ldsm4(u32* r, u32 a) {
    asm volatile("ldmatrix.sync.aligned.m8n8.x4.shared.b16 {%0,%1,%2,%3}, [%4];"
                 : "=r"(r[0]), "=r"(r[1]), "=r"(r[2]), "=r"(r[3]) : "r"(a));
}
__device__ __forceinline__ void mma16816(float* d, const u32* a, u32 b0, u32 b1) {
    asm volatile(
        "mma.sync.aligned.m16n8k16.row.col.f32.bf16.bf16.f32 "
        "{%0,%1,%2,%3}, {%4,%5,%6,%7}, {%8,%9}, {%0,%1,%2,%3};"
        : "+f"(d[0]), "+f"(d[1]), "+f"(d[2]), "+f"(d[3])
        : "r"(a[0]), "r"(a[1]), "r"(a[2]), "r"(a[3]), "r"(b0), "r"(b1));
}
// truncation hi/lo split (scalar, used in prep): hi = top16, lo = RN(t - hi)
__device__ __forceinline__ void bsplit(float t, u16& h, u16& l) {
    u32 u = __float_as_uint(t);
    h = (u16)(u >> 16);
    float fh = __uint_as_float(u & 0xFFFF0000u);
    l = __bfloat16_as_ushort(__float2bfloat16(t - fh));
}
// packed pair split: h = hi16(v0)|hi16(v1)<<16 via PRMT; l = bf16x2 of residuals
__device__ __forceinline__ void bsplit2(float v0, float v1, u32& h, u32& l) {
    u32 u0 = __float_as_uint(v0), u1 = __float_as_uint(v1);
    asm("prmt.b32 %0, %1, %2, 0x7632;" : "=r"(h) : "r"(u0), "r"(u1));
    float f0 = __uint_as_float(u0 & 0xFFFF0000u);
    float f1 = __uint_as_float(u1 & 0xFFFF0000u);
    asm("cvt.rn.bf16x2.f32 %0, %1, %2;" : "=r"(l) : "f"(v1 - f1), "f"(v0 - f0));
}

// ---------------------------------------------------------------------------
// Combined prep: zero stats + B fragments for layers 2..5 (K=7,5,3,3).
// ---------------------------------------------------------------------------
__global__ void prep_all_b(const float* __restrict__ w2, const float* __restrict__ w3,
                           const float* __restrict__ w4, const float* __restrict__ w5,
                           u32* __restrict__ bf, double* __restrict__ st) {
    if (blockIdx.x == 0 && threadIdx.x < 192) st[threadIdx.x] = 0.0;
    const int total = 92 * 2 * 32;
    for (int i = blockIdx.x * blockDim.x + threadIdx.x; i < total;
         i += gridDim.x * blockDim.x) {
        int lane = i & 31;
        int half = (i >> 5) & 1;
        int gt = i >> 6;
        const float* w;
        int K, tap;
        if (gt < 49)      { w = w2; K = 7; tap = gt; }
        else if (gt < 74) { w = w3; K = 5; tap = gt - 49; }
        else if (gt < 83) { w = w4; K = 3; tap = gt - 74; }
        else              { w = w5; K = 3; tap = gt - 83; }
        int dy = tap / K, dx = tap - dy * K;
        int k0 = (lane & 3) * 2, nn = lane >> 2;
        u32 out[4];
#pragma unroll
        for (int t = 0; t < 2; t++) {
#pragma unroll
            for (int kk = 0; kk < 2; kk++) {
                int co = t * 8 + nn;
                int k = k0 + kk * 8;
                float w0 = w[((co * 16 + k) * K + dy) * K + dx];
                float w1 = w[((co * 16 + k + 1) * K + dy) * K + dx];
                u16 h0, l0, h1, l1;
                bsplit(w0, h0, l0);
                bsplit(w1, h1, l1);
                u16 a = half ? l0 : h0, b = half ? l1 : h1;
                out[t * 2 + kk] = (u32)a | ((u32)b << 16);
            }
        }
        ((uint4*)bf)[i] = make_uint4(out[0], out[1], out[2], out[3]);
    }
}

// ---------------------------------------------------------------------------
// Tensor-core partial-conv layer (cin=cout=16). Tile = 64 px * TY=4 rows,
// 128 threads / 4 warps (warp = 16-px segment). 4 blocks/SM for phase overlap.
// A smem [R=K+3][NPXW=72][16ci] bf16 hi/lo, XOR half-swizzle (ROWB=2304,
// multiple of 128 -> same bank pattern as R10). Rolling 4-slot A window.
// ---------------------------------------------------------------------------
template <int K, bool AFF>
__global__ void __launch_bounds__(128, 4) tmma_conv_k(
    const float* __restrict__ in, long long inNS,
    const float* __restrict__ mk, long long mkNS,
    const u32* __restrict__ bfrag, const float* __restrict__ bias,
    const double* __restrict__ stPrev,
    const float* __restrict__ gamPrev, const float* __restrict__ betPrev,
    float* __restrict__ outH, float* __restrict__ outM,
    double* __restrict__ stats) {
    constexpr int TY = 4, P = K / 2, TILE = 64;
    constexpr int NPX = TILE + K - 1;
    constexpr int NPXW = (NPX + 7) & ~7;
    constexpr int R = K + TY - 1;
    constexpr int ROWB = NPXW * 32;
    constexpr int SR_OFF = 0;
    constexpr int AB_OFF = 1024;                 // 16 float2 affine
    constexpr int MK_OFF = AB_OFF + 128;
    constexpr int AH_OFF = ((MK_OFF + R * NPXW * 4 + 127) / 128) * 128;
    constexpr int AL_OFF = AH_OFF + R * ROWB;

    extern __shared__ char smx[];
    float*  sR  = (float*)(smx + SR_OFF);
    float2* sAB = (float2*)(smx + AB_OFF);
    float*  sMk = (float*)(smx + MK_OFF);
    const u32 sb = smem_u32(smx);

    const int tid = threadIdx.x;
    const int wid = tid >> 5;
    const int lane = tid & 31;
    const int n  = blockIdx.z;
    const int x0 = blockIdx.x * TILE;
    const int y0 = blockIdx.y * TY;

    // ---- affine of previous layer (once per block) ----
    if (tid < 16) {
        if (AFF) {
            double mean = stPrev[tid] / (double)NPIX;
            double var  = stPrev[16 + tid] / (double)NPIX - mean * mean;
            float inv = rsqrtf((float)var + 1e-5f);
            float a = gamPrev[tid] * inv;
            sAB[tid] = make_float2(a, betPrev[tid] - (float)mean * a);
        } else {
            sAB[tid] = make_float2(1.f, 0.f);
        }
    }

    // ---- mask window ----
    const float* mkn = mk + (long long)n * mkNS;
    for (int i = tid; i < R * NPXW; i += 128) {
        int r = i / NPXW, p = i - r * NPXW;
        int gy = y0 - P + r, gx = x0 - P + p;
        float m = 0.f;
        if ((unsigned)gy < 1024u && (unsigned)gx < 1024u) m = mkn[gy * IMW + gx];
        sMk[i] = m;
    }
    __syncthreads();

    // ---- stage A (masked + affine + relu, bf16 hi/lo, half-swizzled) ----
    float2 abr[16];
#pragma unroll
    for (int ci = 0; ci < 16; ci++) abr[ci] = sAB[ci];
    const float* inn = in + (long long)n * inNS;
    for (int i = tid; i < R * NPX; i += 128) {
        int r = i / NPX, p = i - r * NPX;
        int gy = y0 - P + r, gx = x0 - P + p;
        bool ok = (unsigned)gy < 1024u && (unsigned)gx < 1024u;
        float m = sMk[r * NPXW + p];
        const float* ip = inn + (long long)gy * IMW + gx;
        u32 hp[8], lp[8];
#pragma unroll
        for (int c2 = 0; c2 < 8; c2++) {
            float v0 = ok ? ip[(long long)(2 * c2) * HW] : 0.f;
            float v1 = ok ? ip[(long long)(2 * c2 + 1) * HW] : 0.f;
            if (AFF) {
                v0 = fmaxf(fmaf(v0, abr[2 * c2].x, abr[2 * c2].y), 0.f);
                v1 = fmaxf(fmaf(v1, abr[2 * c2 + 1].x, abr[2 * c2 + 1].y), 0.f);
            }
            v0 *= m;
            v1 *= m;
            bsplit2(v0, v1, hp[c2], lp[c2]);
        }
        u32 s = ((p >> 2) & 1) * 16;            // half swizzle
        char* ah = smx + AH_OFF + r * ROWB + p * 32;
        char* al = smx + AL_OFF + r * ROWB + p * 32;
        *(uint4*)(ah + s)        = make_uint4(hp[0], hp[1], hp[2], hp[3]);
        *(uint4*)(ah + (16 ^ s)) = make_uint4(hp[4], hp[5], hp[6], hp[7]);
        *(uint4*)(al + s)        = make_uint4(lp[0], lp[1], lp[2], lp[3]);
        *(uint4*)(al + (16 ^ s)) = make_uint4(lp[4], lp[5], lp[6], lp[7]);
    }
    __syncthreads();

    // ---- MMA mainloop ----
    const int seg = wid;                 // 16-px segment (0..3)
    float D[TY][2][4];
#pragma unroll
    for (int y = 0; y < TY; y++)
#pragma unroll
        for (int t = 0; t < 2; t++)
#pragma unroll
            for (int j = 0; j < 4; j++) D[y][t][j] = 0.f;

    const int l15 = lane & 15;
    const int kh = lane >> 4;
    const uint4* bf4 = (const uint4*)bfrag;

#pragma unroll 1
    for (int dx = 0; dx < K; dx++) {
        u32 sw = (u32)(((l15 + dx) >> 2) & 1);
        u32 apx = (u32)(seg * 16 + l15 + dx);
        u32 aoff = apx * 32 + (((u32)kh ^ sw) * 16);
        u32 aH = sb + AH_OFF + aoff;
        u32 aL = sb + AL_OFF + aoff;
        u32 Wh[4][4], Wl[4][4];
#pragma unroll
        for (int r = 0; r < 3; r++) {
            ldsm4(Wh[r], aH + r * ROWB);
            ldsm4(Wl[r], aL + r * ROWB);
        }
#pragma unroll
        for (int dy = 0; dy < K; dy++) {
            const int rin = dy + 3;
            ldsm4(Wh[rin & 3], aH + rin * ROWB);
            ldsm4(Wl[rin & 3], aL + rin * ROWB);
            int tap = dy * K + dx;
            uint4 BH = bf4[(tap * 2 + 0) * 32 + lane];
            uint4 BL = bf4[(tap * 2 + 1) * 32 + lane];
#pragma unroll
            for (int y = 0; y < TY; y++) {
                const int sl = (dy + y) & 3;
                mma16816(D[y][0], Wh[sl], BH.x, BH.y);
                mma16816(D[y][1], Wh[sl], BH.z, BH.w);
                mma16816(D[y][0], Wl[sl], BH.x, BH.y);
                mma16816(D[y][1], Wl[sl], BH.z, BH.w);
                mma16816(D[y][0], Wh[sl], BL.x, BL.y);
                mma16816(D[y][1], Wh[sl], BL.z, BL.w);
            }
        }
    }

    // ---- mask-sum conv + maxpool: lane handles rows (yl, yl+2) at pxl ----
    const int yl = lane >> 4, pxl = lane & 15;
    float s[2] = {0.f, 0.f}, mm[2] = {0.f, 0.f};
    {
        const float* mb = sMk + seg * 16 + pxl;
#pragma unroll 1
        for (int dy = 0; dy < K; dy++)
#pragma unroll
            for (int dx = 0; dx < K; dx++) {
#pragma unroll
                for (int j = 0; j < 2; j++) {
                    float m = mb[(yl + 2 * j + dy) * NPXW + dx];
                    s[j] += m;
                    mm[j] = fmaxf(mm[j], m);
                }
            }
    }
    float invv0 = 1.0f / (s[0] + 1e-8f);
    float invv1 = 1.0f / (s[1] + 1e-8f);
    outM[(long long)n * HW + (long long)(y0 + yl) * IMW + x0 + seg * 16 + pxl] = mm[0];
    outM[(long long)n * HW + (long long)(y0 + yl + 2) * IMW + x0 + seg * 16 + pxl] = mm[1];

    // ---- epilogue: scale, bias, store, stats ----
    float bco[4];
#pragma unroll
    for (int t = 0; t < 2; t++)
#pragma unroll
        for (int j = 0; j < 2; j++)
            bco[t * 2 + j] = bias[t * 8 + (lane & 3) * 2 + j];
    float p1[4] = {0.f, 0.f, 0.f, 0.f}, p2[4] = {0.f, 0.f, 0.f, 0.f};
    const int pxa = seg * 16 + (lane >> 2);

#pragma unroll
    for (int y = 0; y < TY; y++) {
        float vsel = (y < 2) ? invv0 : invv1;
        float inva = __shfl_sync(0xffffffffu, vsel, (y & 1) * 16 + (lane >> 2));
        float invb = __shfl_sync(0xffffffffu, vsel, (y & 1) * 16 + (lane >> 2) + 8);
        int gy = y0 + y;
        float* hb = outH + (long long)n * 16 * HW + (long long)gy * IMW + x0;
#pragma unroll
        for (int t = 0; t < 2; t++) {
#pragma unroll
            for (int j = 0; j < 2; j++) {
                int co = t * 8 + (lane & 3) * 2 + j;
                float bc = bco[t * 2 + j];
                float v0 = fmaf(D[y][t][j], inva, bc);
                float v1 = fmaf(D[y][t][j + 2], invb, bc);
                hb[(long long)co * HW + pxa] = v0;
                hb[(long long)co * HW + pxa + 8] = v1;
                p1[t * 2 + j] += v0 + v1;
                p2[t * 2 + j] = fmaf(v0, v0, fmaf(v1, v1, p2[t * 2 + j]));
            }
        }
    }
#pragma unroll
    for (int k = 0; k < 4; k++) {
#pragma unroll
        for (int o = 4; o < 32; o <<= 1) {
            p1[k] += __shfl_xor_sync(0xffffffffu, p1[k], o);
            p2[k] += __shfl_xor_sync(0xffffffffu, p2[k], o);
        }
    }
    if (lane < 4) {
#pragma unroll
        for (int t = 0; t < 2; t++)
#pragma unroll
            for (int j = 0; j < 2; j++) {
                int co = t * 8 + lane * 2 + j;
                sR[(co * 2 + 0) * 4 + wid] = p1[t * 2 + j];
                sR[(co * 2 + 1) * 4 + wid] = p2[t * 2 + j];
            }
    }
    __syncthreads();
    if (tid < 32) {
        int co = tid >> 1, which = tid & 1;
        float v = sR[tid * 4 + 0] + sR[tid * 4 + 1] + sR[tid * 4 + 2] + sR[tid * 4 + 3];
        atomicAdd(&stats[which * 16 + co], (double)v);
    }
}

// ---------------------------------------------------------------------------
// Scalar FFMA2 partial-conv — layer 1 (cin=1, K=11), no input affine.
// ---------------------------------------------------------------------------
template <int K>
__global__ void __launch_bounds__(128, 4) sconv_k(
    const float* __restrict__ in, long long inNS,
    const float* __restrict__ mk, long long mkNS,
    const float* __restrict__ wG, const float* __restrict__ bias,
    float* __restrict__ outH, float* __restrict__ outM,
    double* __restrict__ stats) {
    constexpr int TX = 32, TY = 16, P = K / 2;
    constexpr int IW = TX + K - 1;
    constexpr int IH = TY + K - 1;
    constexpr int IHP = IH | 1;
    constexpr int SMN = IH * IW;
    constexpr int SXN = IW * IHP;
    constexpr int SWOFF = ((SMN + SXN + 3) / 4) * 4;
    constexpr int SWN = K * K * 16;

    extern __shared__ float sm[];
    float* sMk = sm;
    float* sX  = sm + SMN;
    float* sW  = sm + SWOFF;
    float* sR  = sm + SWOFF + SWN;

    const int tid = threadIdx.x;
    const int n = blockIdx.z;
    const int x0 = blockIdx.x * TX - P;
    const int y0 = blockIdx.y * TY - P;

    const float* mkn = mk + (long long)n * mkNS;
    const float* inn = in + (long long)n * inNS;
    for (int i = tid; i < SMN; i += 128) {
        int ly = i / IW, lx = i - ly * IW;
        int gy = y0 + ly, gx = x0 + lx;
        float m = 0.f, v = 0.f;
        if ((unsigned)gy < 1024u && (unsigned)gx < 1024u) {
            m = mkn[gy * IMW + gx];
            v = inn[gy * IMW + gx];
        }
        sMk[i] = m;
        sX[lx * IHP + ly] = v * m;
    }
    for (int i = tid; i < SWN; i += 128) {
        int co = i & 15;
        int rest = i >> 4;
        sW[i] = wG[co * (K * K) + rest];
    }
    __syncthreads();

    const int tx = tid & 31;
    const int tq = tid >> 5;

    u64 acc2[32];
#pragma unroll
    for (int i = 0; i < 32; i++) acc2[i] = 0ull;

    {
        const float* colbase = sX + tx * IHP + tq * 4;
#pragma unroll 1
        for (int dx = 0; dx < K; dx++) {
            const float* colp = colbase + dx * IHP;
            u64 vv[K + 3];
#pragma unroll
            for (int j = 0; j < K + 3; j++) vv[j] = dup2(colp[j]);
#pragma unroll
            for (int dy = 0; dy < K; dy++) {
                const ulonglong2* wq = (const ulonglong2*)(sW + (dy * K + dx) * 16);
                ulonglong2 wa = wq[0];
                ulonglong2 wb = wq[1];
                ulonglong2 wc = wq[2];
                ulonglong2 wd = wq[3];
#pragma unroll
                for (int py = 0; py < 4; py++) {
                    u64 v = vv[dy + py];
                    fma2(acc2[0 * 4 + py], v, wa.x);
                    fma2(acc2[1 * 4 + py], v, wa.y);
                    fma2(acc2[2 * 4 + py], v, wb.x);
                    fma2(acc2[3 * 4 + py], v, wb.y);
                    fma2(acc2[4 * 4 + py], v, wc.x);
                    fma2(acc2[5 * 4 + py], v, wc.y);
                    fma2(acc2[6 * 4 + py], v, wd.x);
                    fma2(acc2[7 * 4 + py], v, wd.y);
                }
            }
        }
    }

    float s[4] = {0.f, 0.f, 0.f, 0.f};
    float mm[4] = {0.f, 0.f, 0.f, 0.f};
    {
        const float* mb = sMk + (tq * 4) * IW + tx;
#pragma unroll 1
        for (int dy = 0; dy < K; dy++)
#pragma unroll
            for (int dx = 0; dx < K; dx++)
#pragma unroll
                for (int py = 0; py < 4; py++) {
                    float m = mb[(dy + py) * IW + dx];
                    s[py] += m;
                    mm[py] = fmaxf(mm[py], m);
                }
    }
    float inv[4];
#pragma unroll
    for (int py = 0; py < 4; py++) inv[py] = 1.0f / (s[py] + 1e-8f);

    const int gy = blockIdx.y * TY + tq * 4;
    const int gx = blockIdx.x * TX + tx;

    float* mo = outM + (long long)n * HW + gy * IMW + gx;
#pragma unroll
    for (int py = 0; py < 4; py++) mo[py * IMW] = mm[py];

    float* ho = outH + ((long long)n * 16) * HW + gy * IMW + gx;
    const int lane = tid & 31;
    const int warp = tid >> 5;
#pragma unroll
    for (int cp = 0; cp < 8; cp++) {
        float b0 = bias[2 * cp], b1 = bias[2 * cp + 1];
        float p1a = 0.f, p2a = 0.f, p1b = 0.f, p2b = 0.f;
#pragma unroll
        for (int py = 0; py < 4; py++) {
            float a0, a1;
            unpk(a0, a1, acc2[cp * 4 + py]);
            float y0v = fmaf(a0, inv[py], b0);
            float y1v = fmaf(a1, inv[py], b1);
            ho[(long long)(2 * cp) * HW + py * IMW] = y0v;
            ho[(long long)(2 * cp + 1) * HW + py * IMW] = y1v;
            p1a += y0v; p2a = fmaf(y0v, y0v, p2a);
            p1b += y1v; p2b = fmaf(y1v, y1v, p2b);
        }
#pragma unroll
        for (int o = 16; o; o >>= 1) {
            p1a += __shfl_xor_sync(0xffffffffu, p1a, o);
            p2a += __shfl_xor_sync(0xffffffffu, p2a, o);
            p1b += __shfl_xor_sync(0xffffffffu, p1b, o);
            p2b += __shfl_xor_sync(0xffffffffu, p2b, o);
        }
        if (lane == 0) {
            sR[(2 * cp * 2 + 0) * 4 + warp] = p1a;
            sR[(2 * cp * 2 + 1) * 4 + warp] = p2a;
            sR[((2 * cp + 1) * 2 + 0) * 4 + warp] = p1b;
            sR[((2 * cp + 1) * 2 + 1) * 4 + warp] = p2b;
        }
    }
    __syncthreads();
    if (tid < 32) {
        float v = sR[tid * 4 + 0] + sR[tid * 4 + 1] + sR[tid * 4 + 2] + sR[tid * 4 + 3];
        int co = tid >> 1, which = tid & 1;
        atomicAdd(&stats[which * 16 + co], (double)v);
    }
}

// ---------------------------------------------------------------------------
// Layer 6: 1x1 partial conv, 16 -> 1; float4 (4 px/thread); affine in-block.
// ---------------------------------------------------------------------------
__global__ void conv1x1_k(const float* __restrict__ h,
                          const float* __restrict__ mk,
                          const float* __restrict__ w6,
                          const float* __restrict__ b6,
                          const double* __restrict__ st5,
                          const float* __restrict__ g5,
                          const float* __restrict__ bt5,
                          float* __restrict__ y,
                          double* __restrict__ stats) {
    __shared__ float swv[16];
    __shared__ float2 sab[16];
    __shared__ float r1[8], r2[8];
    if (threadIdx.x < 16) {
        swv[threadIdx.x] = w6[threadIdx.x];
        double mean = st5[threadIdx.x] / (double)NPIX;
        double var  = st5[16 + threadIdx.x] / (double)NPIX - mean * mean;
        float inv = rsqrtf((float)var + 1e-5f);
        float a = g5[threadIdx.x] * inv;
        sab[threadIdx.x] = make_float2(a, bt5[threadIdx.x] - (float)mean * a);
    }
    __syncthreads();
    float bb = b6[0];
    float p1 = 0.f, p2 = 0.f;
    const float4* mk4 = (const float4*)mk;
    float4* y4 = (float4*)y;
    for (long long i = (long long)blockIdx.x * blockDim.x + threadIdx.x;
         i < 1LL * HW; i += (long long)gridDim.x * blockDim.x) {   // 4M px / 4
        long long n = i >> 18;                 // / (HW/4)
        long long p4 = i & ((HW >> 2) - 1);
        float4 m = mk4[i];
        float4 acc = make_float4(0.f, 0.f, 0.f, 0.f);
        const float4* hb = (const float4*)(h + (n * 16) * HW) + p4;
#pragma unroll
        for (int c = 0; c < 16; c++) {
            float4 v = hb[(long long)c * (HW >> 2)];
            float2 ab = sab[c];
            float wv = swv[c];
            acc.x = fmaf(wv, fmaxf(fmaf(v.x, ab.x, ab.y), 0.f), acc.x);
            acc.y = fmaf(wv, fmaxf(fmaf(v.y, ab.x, ab.y), 0.f), acc.y);
            acc.z = fmaf(wv, fmaxf(fmaf(v.z, ab.x, ab.y), 0.f), acc.z);
            acc.w = fmaf(wv, fmaxf(fmaf(v.w, ab.x, ab.y), 0.f), acc.w);
        }
        float4 o;
        o.x = fmaf(acc.x * m.x, 1.0f / (m.x + 1e-8f), bb);
        o.y = fmaf(acc.y * m.y, 1.0f / (m.y + 1e-8f), bb);
        o.z = fmaf(acc.z * m.z, 1.0f / (m.z + 1e-8f), bb);
        o.w = fmaf(acc.w * m.w, 1.0f / (m.w + 1e-8f), bb);
        y4[i] = o;
        p1 += (o.x + o.y) + (o.z + o.w);
        p2 = fmaf(o.x, o.x, fmaf(o.y, o.y, fmaf(o.z, o.z, fmaf(o.w, o.w, p2))));
    }
#pragma unroll
    for (int o = 16; o; o >>= 1) {
        p1 += __shfl_xor_sync(0xffffffffu, p1, o);
        p2 += __shfl_xor_sync(0xffffffffu, p2, o);
    }
    int warp = threadIdx.x >> 5, lane = threadIdx.x & 31;
    if (lane == 0) { r1[warp] = p1; r2[warp] = p2; }
    __syncthreads();
    if (threadIdx.x == 0) {
        float a = 0.f, b = 0.f;
        for (int w = 0; w < (int)(blockDim.x >> 5); w++) { a += r1[w]; b += r2[w]; }
        atomicAdd(&stats[0], (double)a);
        atomicAdd(&stats[16], (double)b);
    }
}

// Final BN (no relu), float4; affine of layer 6 computed per block.
__global__ void final_k(const float* __restrict__ y,
                        const double* __restrict__ st6,
                        const float* __restrict__ g6,
                        const float* __restrict__ bt6,
                        float* __restrict__ o) {
    __shared__ float2 t;
    if (threadIdx.x == 0) {
        double mean = st6[0] / (double)NPIX;
        double var  = st6[16] / (double)NPIX - mean * mean;
        float inv = rsqrtf((float)var + 1e-5f);
        float a = g6[0] * inv;
        t = make_float2(a, bt6[0] - (float)mean * a);
    }
    __syncthreads();
    float2 tt = t;
    const float4* y4 = (const float4*)y;
    float4* o4 = (float4*)o;
    for (long long i = (long long)blockIdx.x * blockDim.x + threadIdx.x;
         i < 1LL * HW; i += (long long)gridDim.x * blockDim.x) {
        float4 v = y4[i];
        v.x = fmaf(v.x, tt.x, tt.y);
        v.y = fmaf(v.y, tt.x, tt.y);
        v.z = fmaf(v.z, tt.x, tt.y);
        v.w = fmaf(v.w, tt.x, tt.y);
        o4[i] = v;
    }
}

// ---------------------------------------------------------------------------
static constexpr int sconv_smem(int K) {
    int IW = 32 + K - 1, IH = 16 + K - 1;
    int IHP = IH | 1;
    int smn = IH * IW;
    int sxn = IW * IHP;
    int swoff = ((smn + sxn + 3) / 4) * 4;
    return (swoff + K * K * 16 + 128) * 4;
}
static constexpr int tmma_smem(int K) {
    int TY = 4, TILE = 64;
    int NPX = TILE + K - 1, NPXW = (NPX + 7) & ~7, R = K + TY - 1;
    int MK = 1024 + 128;
    int AH = ((MK + R * NPXW * 4 + 127) / 128) * 128;
    return AH + 2 * R * NPXW * 32;
}

extern "C" void kernel_launch(void* const* d_in, const int* in_sizes, int n_in,
                              void* d_out, int out_size) {
    (void)in_sizes; (void)n_in; (void)out_size;
    const float* x = (const float*)d_in[0];
    const float *wp[6], *bp[6], *gp[6], *btp[6];
    for (int i = 0; i < 6; i++) {
        wp[i]  = (const float*)d_in[1 + 4 * i];
        bp[i]  = (const float*)d_in[2 + 4 * i];
        gp[i]  = (const float*)d_in[3 + 4 * i];
        btp[i] = (const float*)d_in[4 + 4 * i];
    }

    float *h0, *h1, *m0, *m1;
    double* st;
    u32* bf;
    cudaGetSymbolAddress((void**)&h0, g_h0);
    cudaGetSymbolAddress((void**)&h1, g_h1);
    cudaGetSymbolAddress((void**)&m0, g_m0);
    cudaGetSymbolAddress((void**)&m1, g_m1);
    cudaGetSymbolAddress((void**)&st, g_stats);
    cudaGetSymbolAddress((void**)&bf, g_bfrag);

    cudaFuncSetAttribute(sconv_k<11>, cudaFuncAttributeMaxDynamicSharedMemorySize, sconv_smem(11));
    cudaFuncSetAttribute(tmma_conv_k<7, true>, cudaFuncAttributeMaxDynamicSharedMemorySize, tmma_smem(7));
    cudaFuncSetAttribute(tmma_conv_k<5, true>, cudaFuncAttributeMaxDynamicSharedMemorySize, tmma_smem(5));
    cudaFuncSetAttribute(tmma_conv_k<3, true>, cudaFuncAttributeMaxDynamicSharedMemorySize, tmma_smem(3));

    dim3 sgrid(1024 / 32, 1024 / 16, 4);
    dim3 tgrid(1024 / 64, 1024 / 4, 4);

    u32* bf2 = bf;
    u32* bf3 = bf + 49 * 256;
    u32* bf4p = bf + 74 * 256;
    u32* bf5 = bf + 83 * 256;

    prep_all_b<<<23, 256>>>(wp[1], wp[2], wp[3], wp[4], bf, st);

    sconv_k<11><<<sgrid, 128, sconv_smem(11)>>>(
        x, 2LL * HW, x + HW, 2LL * HW, wp[0], bp[0], h0, m0, st + 0);

    tmma_conv_k<7, true><<<tgrid, 128, tmma_smem(7)>>>(
        h0, 16LL * HW, m0, (long long)HW, bf2, bp[1],
        st + 0, gp[0], btp[0], h1, m1, st + 32);

    tmma_conv_k<5, true><<<tgrid, 128, tmma_smem(5)>>>(
        h1, 16LL * HW, m1, (long long)HW, bf3, bp[2],
        st + 32, gp[1], btp[1], h0, m0, st + 64);

    tmma_conv_k<3, true><<<tgrid, 128, tmma_smem(3)>>>(
        h0, 16LL * HW, m0, (long long)HW, bf4p, bp[3],
        st + 64, gp[2], btp[2], h1, m1, st + 96);

    tmma_conv_k<3, true><<<tgrid, 128, tmma_smem(3)>>>(
        h1, 16LL * HW, m1, (long long)HW, bf5, bp[4],
        st + 96, gp[3], btp[3], h0, m0, st + 128);

    conv1x1_k<<<1184, 256>>>(h0, m0, wp[5], bp[5],
                             st + 128, gp[4], btp[4], h1, st + 160);

    final_k<<<2048, 256>>>(h1, st + 160, gp[5], btp[5], (float*)d_out);
}

// round 12
// speedup vs baseline: 2.3810x; 1.0119x over previous
#include <cuda_runtime.h>
#include <cuda_bf16.h>
#include <math.h>

// ---------------------------------------------------------------------------
// SparseConvNet: 6 partial-conv layers. N=4, H=W=1024.
// Round 12: TY=8 row-major MMA mainloop — B fragments for all K taps of a dx
// column held in registers; each A row fragment ldsm'd once and fired at all
// valid (dy, y=r-dy). Halves B LDG/output, -30% A ldsm, -30% staging
// redundancy. Separable register-resident mask-sum/maxpool.
// ---------------------------------------------------------------------------

#define HW   (1024 * 1024)
#define IMW  1024
#define NPIX (4LL * HW)

__device__ float  g_h0[4 * 16 * HW];
__device__ float  g_h1[4 * 16 * HW];
__device__ float  g_m0[4 * HW];
__device__ float  g_m1[4 * HW];
__device__ double g_stats[6 * 32];
__device__ unsigned int g_bfrag[92 * 2 * 32 * 4];   // 49+25+9+9 taps

typedef unsigned long long u64;
typedef unsigned int u32;
typedef unsigned short u16;

__device__ __forceinline__ u64 dup2(float v) {
    u64 r;
    asm("mov.b64 %0, {%1, %1};" : "=l"(r) : "f"(v));
    return r;
}
__device__ __forceinline__ void fma2(u64& d, u64 a, u64 b) {
    asm("fma.rn.f32x2 %0, %1, %2, %0;" : "+l"(d) : "l"(a), "l"(b));
}
__device__ __forceinline__ void unpk(float& lo, float& hi, u64 v) {
    asm("mov.b64 {%0, %1}, %2;" : "=f"(lo), "=f"(hi) : "l"(v));
}
__device__ __forceinline__ u32 smem_u32(const void* p) {
    u32 a;
    asm("{ .reg .u64 t; cvta.to.shared.u64 t, %1; cvt.u32.u64 %0, t; }"
        : "=r"(a) : "l"(p));
    return a;
}
__device__ __forceinline__ void ldsm4(u32* r, u32 a) {
    asm volatile("ldmatrix.sync.aligned.m8n8.x4.shared.b16 {%0,%1,%2,%3}, [%4];"
                 : "=r"(r[0]), "=r"(r[1]), "=r"(r[2]), "=r"(r[3]) : "r"(a));
}
__device__ __forceinline__ void mma16816(float* d, const u32* a, u32 b0, u32 b1) {
    asm volatile(
        "mma.sync.aligned.m16n8k16.row.col.f32.bf16.bf16.f32 "
        "{%0,%1,%2,%3}, {%4,%5,%6,%7}, {%8,%9}, {%0,%1,%2,%3};"
        : "+f"(d[0]), "+f"(d[1]), "+f"(d[2]), "+f"(d[3])
        : "r"(a[0]), "r"(a[1]), "r"(a[2]), "r"(a[3]), "r"(b0), "r"(b1));
}
// truncation hi/lo split (scalar, used in prep): hi = top16, lo = RN(t - hi)
__device__ __forceinline__ void bsplit(float t, u16& h, u16& l) {
    u32 u = __float_as_uint(t);
    h = (u16)(u >> 16);
    float fh = __uint_as_float(u & 0xFFFF0000u);
    l = __bfloat16_as_ushort(__float2bfloat16(t - fh));
}
// packed pair split: h = hi16(v0)|hi16(v1)<<16 via PRMT; l = bf16x2 of residuals
__device__ __forceinline__ void bsplit2(float v0, float v1, u32& h, u32& l) {
    u32 u0 = __float_as_uint(v0), u1 = __float_as_uint(v1);
    asm("prmt.b32 %0, %1, %2, 0x7632;" : "=r"(h) : "r"(u0), "r"(u1));
    float f0 = __uint_as_float(u0 & 0xFFFF0000u);
    float f1 = __uint_as_float(u1 & 0xFFFF0000u);
    asm("cvt.rn.bf16x2.f32 %0, %1, %2;" : "=r"(l) : "f"(v1 - f1), "f"(v0 - f0));
}

// ---------------------------------------------------------------------------
// Combined prep: zero stats + B fragments for layers 2..5 (K=7,5,3,3).
// ---------------------------------------------------------------------------
__global__ void prep_all_b(const float* __restrict__ w2, const float* __restrict__ w3,
                           const float* __restrict__ w4, const float* __restrict__ w5,
                           u32* __restrict__ bf, double* __restrict__ st) {
    if (blockIdx.x == 0 && threadIdx.x < 192) st[threadIdx.x] = 0.0;
    const int total = 92 * 2 * 32;
    for (int i = blockIdx.x * blockDim.x + threadIdx.x; i < total;
         i += gridDim.x * blockDim.x) {
        int lane = i & 31;
        int half = (i >> 5) & 1;
        int gt = i >> 6;
        const float* w;
        int K, tap;
        if (gt < 49)      { w = w2; K = 7; tap = gt; }
        else if (gt < 74) { w = w3; K = 5; tap = gt - 49; }
        else if (gt < 83) { w = w4; K = 3; tap = gt - 74; }
        else              { w = w5; K = 3; tap = gt - 83; }
        int dy = tap / K, dx = tap - dy * K;
        int k0 = (lane & 3) * 2, nn = lane >> 2;
        u32 out[4];
#pragma unroll
        for (int t = 0; t < 2; t++) {
#pragma unroll
            for (int kk = 0; kk < 2; kk++) {
                int co = t * 8 + nn;
                int k = k0 + kk * 8;
                float w0 = w[((co * 16 + k) * K + dy) * K + dx];
                float w1 = w[((co * 16 + k + 1) * K + dy) * K + dx];
                u16 h0, l0, h1, l1;
                bsplit(w0, h0, l0);
                bsplit(w1, h1, l1);
                u16 a = half ? l0 : h0, b = half ? l1 : h1;
                out[t * 2 + kk] = (u32)a | ((u32)b << 16);
            }
        }
        ((uint4*)bf)[i] = make_uint4(out[0], out[1], out[2], out[3]);
    }
}

// ---------------------------------------------------------------------------
// Tensor-core partial-conv layer (cin=cout=16). Tile = 64 px * TY=8 rows,
// 128 threads / 4 warps (warp = 16-px segment). Per dx column: all K taps'
// B fragments in registers; sweep window rows r, each A ldsm'd once, fired
// at all (dy, y=r-dy). Separable mask-sum/maxpool in registers.
// ---------------------------------------------------------------------------
template <int K, bool AFF>
__global__ void __launch_bounds__(128, (K <= 3) ? 4 : 3) tmma_conv_k(
    const float* __restrict__ in, long long inNS,
    const float* __restrict__ mk, long long mkNS,
    const u32* __restrict__ bfrag, const float* __restrict__ bias,
    const double* __restrict__ stPrev,
    const float* __restrict__ gamPrev, const float* __restrict__ betPrev,
    float* __restrict__ outH, float* __restrict__ outM,
    double* __restrict__ stats) {
    constexpr int TY = 8, P = K / 2, TILE = 64;
    constexpr int NPX = TILE + K - 1;
    constexpr int NPXW = (NPX + 7) & ~7;
    constexpr int R = K + TY - 1;
    constexpr int ROWB = NPXW * 32;
    constexpr int SR_OFF = 0;
    constexpr int AB_OFF = 1024;                 // 16 float2 affine
    constexpr int MK_OFF = AB_OFF + 128;
    constexpr int AH_OFF = ((MK_OFF + R * NPXW * 4 + 127) / 128) * 128;
    constexpr int AL_OFF = AH_OFF + R * ROWB;

    extern __shared__ char smx[];
    float*  sR  = (float*)(smx + SR_OFF);
    float2* sAB = (float2*)(smx + AB_OFF);
    float*  sMk = (float*)(smx + MK_OFF);
    const u32 sb = smem_u32(smx);

    const int tid = threadIdx.x;
    const int wid = tid >> 5;
    const int lane = tid & 31;
    const int n  = blockIdx.z;
    const int x0 = blockIdx.x * TILE;
    const int y0 = blockIdx.y * TY;

    // ---- affine of previous layer (once per block) ----
    if (tid < 16) {
        if (AFF) {
            double mean = stPrev[tid] / (double)NPIX;
            double var  = stPrev[16 + tid] / (double)NPIX - mean * mean;
            float inv = rsqrtf((float)var + 1e-5f);
            float a = gamPrev[tid] * inv;
            sAB[tid] = make_float2(a, betPrev[tid] - (float)mean * a);
        } else {
            sAB[tid] = make_float2(1.f, 0.f);
        }
    }

    // ---- mask window ----
    const float* mkn = mk + (long long)n * mkNS;
    for (int i = tid; i < R * NPXW; i += 128) {
        int r = i / NPXW, p = i - r * NPXW;
        int gy = y0 - P + r, gx = x0 - P + p;
        float m = 0.f;
        if ((unsigned)gy < 1024u && (unsigned)gx < 1024u) m = mkn[gy * IMW + gx];
        sMk[i] = m;
    }
    __syncthreads();

    // ---- stage A (masked + affine + relu, bf16 hi/lo, half-swizzled) ----
    float2 abr[16];
#pragma unroll
    for (int ci = 0; ci < 16; ci++) abr[ci] = sAB[ci];
    const float* inn = in + (long long)n * inNS;
    for (int i = tid; i < R * NPX; i += 128) {
        int r = i / NPX, p = i - r * NPX;
        int gy = y0 - P + r, gx = x0 - P + p;
        bool ok = (unsigned)gy < 1024u && (unsigned)gx < 1024u;
        float m = sMk[r * NPXW + p];
        const float* ip = inn + (long long)gy * IMW + gx;
        u32 hp[8], lp[8];
#pragma unroll
        for (int c2 = 0; c2 < 8; c2++) {
            float v0 = ok ? ip[(long long)(2 * c2) * HW] : 0.f;
            float v1 = ok ? ip[(long long)(2 * c2 + 1) * HW] : 0.f;
            if (AFF) {
                v0 = fmaxf(fmaf(v0, abr[2 * c2].x, abr[2 * c2].y), 0.f);
                v1 = fmaxf(fmaf(v1, abr[2 * c2 + 1].x, abr[2 * c2 + 1].y), 0.f);
            }
            v0 *= m;
            v1 *= m;
            bsplit2(v0, v1, hp[c2], lp[c2]);
        }
        u32 s = ((p >> 2) & 1) * 16;            // half swizzle
        char* ah = smx + AH_OFF + r * ROWB + p * 32;
        char* al = smx + AL_OFF + r * ROWB + p * 32;
        *(uint4*)(ah + s)        = make_uint4(hp[0], hp[1], hp[2], hp[3]);
        *(uint4*)(ah + (16 ^ s)) = make_uint4(hp[4], hp[5], hp[6], hp[7]);
        *(uint4*)(al + s)        = make_uint4(lp[0], lp[1], lp[2], lp[3]);
        *(uint4*)(al + (16 ^ s)) = make_uint4(lp[4], lp[5], lp[6], lp[7]);
    }
    __syncthreads();

    // ---- MMA mainloop (row-major sweep, B taps in registers) ----
    const int seg = wid;                 // 16-px segment (0..3)
    float D[TY][2][4];
#pragma unroll
    for (int y = 0; y < TY; y++)
#pragma unroll
        for (int t = 0; t < 2; t++)
#pragma unroll
            for (int j = 0; j < 4; j++) D[y][t][j] = 0.f;

    const int l15 = lane & 15;
    const int kh = lane >> 4;
    const uint4* bf4 = (const uint4*)bfrag;

#pragma unroll 1
    for (int dx = 0; dx < K; dx++) {
        u32 sw = (u32)(((l15 + dx) >> 2) & 1);
        u32 apx = (u32)(seg * 16 + l15 + dx);
        u32 aoff = apx * 32 + (((u32)kh ^ sw) * 16);
        u32 aH = sb + AH_OFF + aoff;
        u32 aL = sb + AL_OFF + aoff;
        uint4 BH[K], BL[K];
#pragma unroll
        for (int dy = 0; dy < K; dy++) {
            BH[dy] = bf4[((dy * K + dx) * 2 + 0) * 32 + lane];
            BL[dy] = bf4[((dy * K + dx) * 2 + 1) * 32 + lane];
        }
#pragma unroll
        for (int r = 0; r < R; r++) {
            u32 Ah[4], Al[4];
            ldsm4(Ah, aH + r * ROWB);
            ldsm4(Al, aL + r * ROWB);
#pragma unroll
            for (int dy = 0; dy < K; dy++) {
                const int y = r - dy;
                if (y >= 0 && y < TY) {
                    mma16816(D[y][0], Ah, BH[dy].x, BH[dy].y);
                    mma16816(D[y][1], Ah, BH[dy].z, BH[dy].w);
                    mma16816(D[y][0], Al, BH[dy].x, BH[dy].y);
                    mma16816(D[y][1], Al, BH[dy].z, BH[dy].w);
                    mma16816(D[y][0], Ah, BL[dy].x, BL[dy].y);
                    mma16816(D[y][1], Ah, BL[dy].z, BL[dy].w);
                }
            }
        }
    }

    // ---- separable mask-sum conv + maxpool (registers) ----
    // lane (half = lane>>4, pxl = lane&15) owns rows {half+2j} j=0..3 at pxl.
    const int pxl = lane & 15, half = lane >> 4;
    float hsum[R], hmax[R];
    {
        const float* mb = sMk + seg * 16 + pxl;
#pragma unroll
        for (int r = 0; r < R; r++) {
            float s = 0.f, mx = 0.f;
#pragma unroll
            for (int dxm = 0; dxm < K; dxm++) {
                float m = mb[r * NPXW + dxm];
                s += m;
                mx = fmaxf(mx, m);
            }
            hsum[r] = s;
            hmax[r] = mx;
        }
    }
    float invv[4];
#pragma unroll
    for (int j = 0; j < 4; j++) {
        int y = half + 2 * j;
        float s = 0.f, mx = 0.f;
#pragma unroll
        for (int dy = 0; dy < K; dy++) {
            s += hsum[y + dy];
            mx = fmaxf(mx, hmax[y + dy]);
        }
        invv[j] = 1.0f / (s + 1e-8f);
        outM[(long long)n * HW + (long long)(y0 + y) * IMW + x0 + seg * 16 + pxl] = mx;
    }

    // ---- epilogue: scale, bias, store, stats ----
    float bco[4];
#pragma unroll
    for (int t = 0; t < 2; t++)
#pragma unroll
        for (int j = 0; j < 2; j++)
            bco[t * 2 + j] = bias[t * 8 + (lane & 3) * 2 + j];
    float p1[4] = {0.f, 0.f, 0.f, 0.f}, p2[4] = {0.f, 0.f, 0.f, 0.f};
    const int pxa = seg * 16 + (lane >> 2);

#pragma unroll
    for (int y = 0; y < TY; y++) {
        float vsel = invv[y >> 1];
        float inva = __shfl_sync(0xffffffffu, vsel, ((y & 1) << 4) + (lane >> 2));
        float invb = __shfl_sync(0xffffffffu, vsel, ((y & 1) << 4) + (lane >> 2) + 8);
        int gy = y0 + y;
        float* hb = outH + (long long)n * 16 * HW + (long long)gy * IMW + x0;
#pragma unroll
        for (int t = 0; t < 2; t++) {
#pragma unroll
            for (int j = 0; j < 2; j++) {
                int co = t * 8 + (lane & 3) * 2 + j;
                float bc = bco[t * 2 + j];
                float v0 = fmaf(D[y][t][j], inva, bc);
                float v1 = fmaf(D[y][t][j + 2], invb, bc);
                hb[(long long)co * HW + pxa] = v0;
                hb[(long long)co * HW + pxa + 8] = v1;
                p1[t * 2 + j] += v0 + v1;
                p2[t * 2 + j] = fmaf(v0, v0, fmaf(v1, v1, p2[t * 2 + j]));
            }
        }
    }
#pragma unroll
    for (int k = 0; k < 4; k++) {
#pragma unroll
        for (int o = 4; o < 32; o <<= 1) {
            p1[k] += __shfl_xor_sync(0xffffffffu, p1[k], o);
            p2[k] += __shfl_xor_sync(0xffffffffu, p2[k], o);
        }
    }
    if (lane < 4) {
#pragma unroll
        for (int t = 0; t < 2; t++)
#pragma unroll
            for (int j = 0; j < 2; j++) {
                int co = t * 8 + lane * 2 + j;
                sR[(co * 2 + 0) * 4 + wid] = p1[t * 2 + j];
                sR[(co * 2 + 1) * 4 + wid] = p2[t * 2 + j];
            }
    }
    __syncthreads();
    if (tid < 32) {
        int co = tid >> 1, which = tid & 1;
        float v = sR[tid * 4 + 0] + sR[tid * 4 + 1] + sR[tid * 4 + 2] + sR[tid * 4 + 3];
        atomicAdd(&stats[which * 16 + co], (double)v);
    }
}

// ---------------------------------------------------------------------------
// Scalar FFMA2 partial-conv — layer 1 (cin=1, K=11), no input affine.
// ---------------------------------------------------------------------------
template <int K>
__global__ void __launch_bounds__(128, 4) sconv_k(
    const float* __restrict__ in, long long inNS,
    const float* __restrict__ mk, long long mkNS,
    const float* __restrict__ wG, const float* __restrict__ bias,
    float* __restrict__ outH, float* __restrict__ outM,
    double* __restrict__ stats) {
    constexpr int TX = 32, TY = 16, P = K / 2;
    constexpr int IW = TX + K - 1;
    constexpr int IH = TY + K - 1;
    constexpr int IHP = IH | 1;
    constexpr int SMN = IH * IW;
    constexpr int SXN = IW * IHP;
    constexpr int SWOFF = ((SMN + SXN + 3) / 4) * 4;
    constexpr int SWN = K * K * 16;

    extern __shared__ float sm[];
    float* sMk = sm;
    float* sX  = sm + SMN;
    float* sW  = sm + SWOFF;
    float* sR  = sm + SWOFF + SWN;

    const int tid = threadIdx.x;
    const int n = blockIdx.z;
    const int x0 = blockIdx.x * TX - P;
    const int y0 = blockIdx.y * TY - P;

    const float* mkn = mk + (long long)n * mkNS;
    const float* inn = in + (long long)n * inNS;
    for (int i = tid; i < SMN; i += 128) {
        int ly = i / IW, lx = i - ly * IW;
        int gy = y0 + ly, gx = x0 + lx;
        float m = 0.f, v = 0.f;
        if ((unsigned)gy < 1024u && (unsigned)gx < 1024u) {
            m = mkn[gy * IMW + gx];
            v = inn[gy * IMW + gx];
        }
        sMk[i] = m;
        sX[lx * IHP + ly] = v * m;
    }
    for (int i = tid; i < SWN; i += 128) {
        int co = i & 15;
        int rest = i >> 4;
        sW[i] = wG[co * (K * K) + rest];
    }
    __syncthreads();

    const int tx = tid & 31;
    const int tq = tid >> 5;

    u64 acc2[32];
#pragma unroll
    for (int i = 0; i < 32; i++) acc2[i] = 0ull;

    {
        const float* colbase = sX + tx * IHP + tq * 4;
#pragma unroll 1
        for (int dx = 0; dx < K; dx++) {
            const float* colp = colbase + dx * IHP;
            u64 vv[K + 3];
#pragma unroll
            for (int j = 0; j < K + 3; j++) vv[j] = dup2(colp[j]);
#pragma unroll
            for (int dy = 0; dy < K; dy++) {
                const ulonglong2* wq = (const ulonglong2*)(sW + (dy * K + dx) * 16);
                ulonglong2 wa = wq[0];
                ulonglong2 wb = wq[1];
                ulonglong2 wc = wq[2];
                ulonglong2 wd = wq[3];
#pragma unroll
                for (int py = 0; py < 4; py++) {
                    u64 v = vv[dy + py];
                    fma2(acc2[0 * 4 + py], v, wa.x);
                    fma2(acc2[1 * 4 + py], v, wa.y);
                    fma2(acc2[2 * 4 + py], v, wb.x);
                    fma2(acc2[3 * 4 + py], v, wb.y);
                    fma2(acc2[4 * 4 + py], v, wc.x);
                    fma2(acc2[5 * 4 + py], v, wc.y);
                    fma2(acc2[6 * 4 + py], v, wd.x);
                    fma2(acc2[7 * 4 + py], v, wd.y);
                }
            }
        }
    }

    float s[4] = {0.f, 0.f, 0.f, 0.f};
    float mm[4] = {0.f, 0.f, 0.f, 0.f};
    {
        const float* mb = sMk + (tq * 4) * IW + tx;
#pragma unroll 1
        for (int dy = 0; dy < K; dy++)
#pragma unroll
            for (int dx = 0; dx < K; dx++)
#pragma unroll
                for (int py = 0; py < 4; py++) {
                    float m = mb[(dy + py) * IW + dx];
                    s[py] += m;
                    mm[py] = fmaxf(mm[py], m);
                }
    }
    float inv[4];
#pragma unroll
    for (int py = 0; py < 4; py++) inv[py] = 1.0f / (s[py] + 1e-8f);

    const int gy = blockIdx.y * TY + tq * 4;
    const int gx = blockIdx.x * TX + tx;

    float* mo = outM + (long long)n * HW + gy * IMW + gx;
#pragma unroll
    for (int py = 0; py < 4; py++) mo[py * IMW] = mm[py];

    float* ho = outH + ((long long)n * 16) * HW + gy * IMW + gx;
    const int lane = tid & 31;
    const int warp = tid >> 5;
#pragma unroll
    for (int cp = 0; cp < 8; cp++) {
        float b0 = bias[2 * cp], b1 = bias[2 * cp + 1];
        float p1a = 0.f, p2a = 0.f, p1b = 0.f, p2b = 0.f;
#pragma unroll
        for (int py = 0; py < 4; py++) {
            float a0, a1;
            unpk(a0, a1, acc2[cp * 4 + py]);
            float y0v = fmaf(a0, inv[py], b0);
            float y1v = fmaf(a1, inv[py], b1);
            ho[(long long)(2 * cp) * HW + py * IMW] = y0v;
            ho[(long long)(2 * cp + 1) * HW + py * IMW] = y1v;
            p1a += y0v; p2a = fmaf(y0v, y0v, p2a);
            p1b += y1v; p2b = fmaf(y1v, y1v, p2b);
        }
#pragma unroll
        for (int o = 16; o; o >>= 1) {
            p1a += __shfl_xor_sync(0xffffffffu, p1a, o);
            p2a += __shfl_xor_sync(0xffffffffu, p2a, o);
            p1b += __shfl_xor_sync(0xffffffffu, p1b, o);
            p2b += __shfl_xor_sync(0xffffffffu, p2b, o);
        }
        if (lane == 0) {
            sR[(2 * cp * 2 + 0) * 4 + warp] = p1a;
            sR[(2 * cp * 2 + 1) * 4 + warp] = p2a;
            sR[((2 * cp + 1) * 2 + 0) * 4 + warp] = p1b;
            sR[((2 * cp + 1) * 2 + 1) * 4 + warp] = p2b;
        }
    }
    __syncthreads();
    if (tid < 32) {
        float v = sR[tid * 4 + 0] + sR[tid * 4 + 1] + sR[tid * 4 + 2] + sR[tid * 4 + 3];
        int co = tid >> 1, which = tid & 1;
        atomicAdd(&stats[which * 16 + co], (double)v);
    }
}

// ---------------------------------------------------------------------------
// Layer 6: 1x1 partial conv, 16 -> 1; float4 (4 px/thread); affine in-block.
// ---------------------------------------------------------------------------
__global__ void conv1x1_k(const float* __restrict__ h,
                          const float* __restrict__ mk,
                          const float* __restrict__ w6,
                          const float* __restrict__ b6,
                          const double* __restrict__ st5,
                          const float* __restrict__ g5,
                          const float* __restrict__ bt5,
                          float* __restrict__ y,
                          double* __restrict__ stats) {
    __shared__ float swv[16];
    __shared__ float2 sab[16];
    __shared__ float r1[8], r2[8];
    if (threadIdx.x < 16) {
        swv[threadIdx.x] = w6[threadIdx.x];
        double mean = st5[threadIdx.x] / (double)NPIX;
        double var  = st5[16 + threadIdx.x] / (double)NPIX - mean * mean;
        float inv = rsqrtf((float)var + 1e-5f);
        float a = g5[threadIdx.x] * inv;
        sab[threadIdx.x] = make_float2(a, bt5[threadIdx.x] - (float)mean * a);
    }
    __syncthreads();
    float bb = b6[0];
    float p1 = 0.f, p2 = 0.f;
    const float4* mk4 = (const float4*)mk;
    float4* y4 = (float4*)y;
    for (long long i = (long long)blockIdx.x * blockDim.x + threadIdx.x;
         i < 1LL * HW; i += (long long)gridDim.x * blockDim.x) {
        long long n = i >> 18;
        long long p4 = i & ((HW >> 2) - 1);
        float4 m = mk4[i];
        float4 acc = make_float4(0.f, 0.f, 0.f, 0.f);
        const float4* hb = (const float4*)(h + (n * 16) * HW) + p4;
#pragma unroll
        for (int c = 0; c < 16; c++) {
            float4 v = hb[(long long)c * (HW >> 2)];
            float2 ab = sab[c];
            float wv = swv[c];
            acc.x = fmaf(wv, fmaxf(fmaf(v.x, ab.x, ab.y), 0.f), acc.x);
            acc.y = fmaf(wv, fmaxf(fmaf(v.y, ab.x, ab.y), 0.f), acc.y);
            acc.z = fmaf(wv, fmaxf(fmaf(v.z, ab.x, ab.y), 0.f), acc.z);
            acc.w = fmaf(wv, fmaxf(fmaf(v.w, ab.x, ab.y), 0.f), acc.w);
        }
        float4 o;
        o.x = fmaf(acc.x * m.x, 1.0f / (m.x + 1e-8f), bb);
        o.y = fmaf(acc.y * m.y, 1.0f / (m.y + 1e-8f), bb);
        o.z = fmaf(acc.z * m.z, 1.0f / (m.z + 1e-8f), bb);
        o.w = fmaf(acc.w * m.w, 1.0f / (m.w + 1e-8f), bb);
        y4[i] = o;
        p1 += (o.x + o.y) + (o.z + o.w);
        p2 = fmaf(o.x, o.x, fmaf(o.y, o.y, fmaf(o.z, o.z, fmaf(o.w, o.w, p2))));
    }
#pragma unroll
    for (int o = 16; o; o >>= 1) {
        p1 += __shfl_xor_sync(0xffffffffu, p1, o);
        p2 += __shfl_xor_sync(0xffffffffu, p2, o);
    }
    int warp = threadIdx.x >> 5, lane = threadIdx.x & 31;
    if (lane == 0) { r1[warp] = p1; r2[warp] = p2; }
    __syncthreads();
    if (threadIdx.x == 0) {
        float a = 0.f, b = 0.f;
        for (int w = 0; w < (int)(blockDim.x >> 5); w++) { a += r1[w]; b += r2[w]; }
        atomicAdd(&stats[0], (double)a);
        atomicAdd(&stats[16], (double)b);
    }
}

// Final BN (no relu), float4; affine of layer 6 computed per block.
__global__ void final_k(const float* __restrict__ y,
                        const double* __restrict__ st6,
                        const float* __restrict__ g6,
                        const float* __restrict__ bt6,
                        float* __restrict__ o) {
    __shared__ float2 t;
    if (threadIdx.x == 0) {
        double mean = st6[0] / (double)NPIX;
        double var  = st6[16] / (double)NPIX - mean * mean;
        float inv = rsqrtf((float)var + 1e-5f);
        float a = g6[0] * inv;
        t = make_float2(a, bt6[0] - (float)mean * a);
    }
    __syncthreads();
    float2 tt = t;
    const float4* y4 = (const float4*)y;
    float4* o4 = (float4*)o;
    for (long long i = (long long)blockIdx.x * blockDim.x + threadIdx.x;
         i < 1LL * HW; i += (long long)gridDim.x * blockDim.x) {
        float4 v = y4[i];
        v.x = fmaf(v.x, tt.x, tt.y);
        v.y = fmaf(v.y, tt.x, tt.y);
        v.z = fmaf(v.z, tt.x, tt.y);
        v.w = fmaf(v.w, tt.x, tt.y);
        o4[i] = v;
    }
}

// ---------------------------------------------------------------------------
static constexpr int sconv_smem(int K) {
    int IW = 32 + K - 1, IH = 16 + K - 1;
    int IHP = IH | 1;
    int smn = IH * IW;
    int sxn = IW * IHP;
    int swoff = ((smn + sxn + 3) / 4) * 4;
    return (swoff + K * K * 16 + 128) * 4;
}
static constexpr int tmma_smem(int K) {
    int TY = 8, TILE = 64;
    int NPX = TILE + K - 1, NPXW = (NPX + 7) & ~7, R = K + TY - 1;
    int MK = 1024 + 128;
    int AH = ((MK + R * NPXW * 4 + 127) / 128) * 128;
    return AH + 2 * R * NPXW * 32;
}

extern "C" void kernel_launch(void* const* d_in, const int* in_sizes, int n_in,
                              void* d_out, int out_size) {
    (void)in_sizes; (void)n_in; (void)out_size;
    const float* x = (const float*)d_in[0];
    const float *wp[6], *bp[6], *gp[6], *btp[6];
    for (int i = 0; i < 6; i++) {
        wp[i]  = (const float*)d_in[1 + 4 * i];
        bp[i]  = (const float*)d_in[2 + 4 * i];
        gp[i]  = (const float*)d_in[3 + 4 * i];
        btp[i] = (const float*)d_in[4 + 4 * i];
    }

    float *h0, *h1, *m0, *m1;
    double* st;
    u32* bf;
    cudaGetSymbolAddress((void**)&h0, g_h0);
    cudaGetSymbolAddress((void**)&h1, g_h1);
    cudaGetSymbolAddress((void**)&m0, g_m0);
    cudaGetSymbolAddress((void**)&m1, g_m1);
    cudaGetSymbolAddress((void**)&st, g_stats);
    cudaGetSymbolAddress((void**)&bf, g_bfrag);

    cudaFuncSetAttribute(sconv_k<11>, cudaFuncAttributeMaxDynamicSharedMemorySize, sconv_smem(11));
    cudaFuncSetAttribute(tmma_conv_k<7, true>, cudaFuncAttributeMaxDynamicSharedMemorySize, tmma_smem(7));
    cudaFuncSetAttribute(tmma_conv_k<5, true>, cudaFuncAttributeMaxDynamicSharedMemorySize, tmma_smem(5));
    cudaFuncSetAttribute(tmma_conv_k<3, true>, cudaFuncAttributeMaxDynamicSharedMemorySize, tmma_smem(3));

    dim3 sgrid(1024 / 32, 1024 / 16, 4);
    dim3 tgrid(1024 / 64, 1024 / 8, 4);

    u32* bf2 = bf;
    u32* bf3 = bf + 49 * 256;
    u32* bf4p = bf + 74 * 256;
    u32* bf5 = bf + 83 * 256;

    prep_all_b<<<23, 256>>>(wp[1], wp[2], wp[3], wp[4], bf, st);

    sconv_k<11><<<sgrid, 128, sconv_smem(11)>>>(
        x, 2LL * HW, x + HW, 2LL * HW, wp[0], bp[0], h0, m0, st + 0);

    tmma_conv_k<7, true><<<tgrid, 128, tmma_smem(7)>>>(
        h0, 16LL * HW, m0, (long long)HW, bf2, bp[1],
        st + 0, gp[0], btp[0], h1, m1, st + 32);

    tmma_conv_k<5, true><<<tgrid, 128, tmma_smem(5)>>>(
        h1, 16LL * HW, m1, (long long)HW, bf3, bp[2],
        st + 32, gp[1], btp[1], h0, m0, st + 64);

    tmma_conv_k<3, true><<<tgrid, 128, tmma_smem(3)>>>(
        h0, 16LL * HW, m0, (long long)HW, bf4p, bp[3],
        st + 64, gp[2], btp[2], h1, m1, st + 96);

    tmma_conv_k<3, true><<<tgrid, 128, tmma_smem(3)>>>(
        h1, 16LL * HW, m1, (long long)HW, bf5, bp[4],
        st + 96, gp[3], btp[3], h0, m0, st + 128);

    conv1x1_k<<<1184, 256>>>(h0, m0, wp[5], bp[5],
                             st + 128, gp[4], btp[4], h1, st + 160);

    final_k<<<2048, 256>>>(h1, st + 160, gp[5], btp[5], (float*)d_out);
}

// round 13
// speedup vs baseline: 2.4271x; 1.0194x over previous
#include <cuda_runtime.h>
#include <cuda_bf16.h>
#include <math.h>

// ---------------------------------------------------------------------------
// SparseConvNet: 6 partial-conv layers. N=4, H=W=1024.
// Round 13: layer 1 (cin=1, K=11) moved to tensor cores by packing the 11 dx
// taps into the MMA K(channel) dim: 11 dy-taps x K=16 MMAs, A rows = 16
// contiguous xm values. Layers 2-5 unchanged from R12 (TY=8 row-major sweep).
// ---------------------------------------------------------------------------

#define HW   (1024 * 1024)
#define IMW  1024
#define NPIX (4LL * HW)

__device__ float  g_h0[4 * 16 * HW];
__device__ float  g_h1[4 * 16 * HW];
__device__ float  g_m0[4 * HW];
__device__ float  g_m1[4 * HW];
__device__ double g_stats[6 * 32];
__device__ unsigned int g_bfrag[103 * 2 * 32 * 4];  // 49+25+9+9 + 11 (L1) taps

typedef unsigned long long u64;
typedef unsigned int u32;
typedef unsigned short u16;

__device__ __forceinline__ u32 smem_u32(const void* p) {
    u32 a;
    asm("{ .reg .u64 t; cvta.to.shared.u64 t, %1; cvt.u32.u64 %0, t; }"
        : "=r"(a) : "l"(p));
    return a;
}
__device__ __forceinline__ void ldsm4(u32* r, u32 a) {
    asm volatile("ldmatrix.sync.aligned.m8n8.x4.shared.b16 {%0,%1,%2,%3}, [%4];"
                 : "=r"(r[0]), "=r"(r[1]), "=r"(r[2]), "=r"(r[3]) : "r"(a));
}
__device__ __forceinline__ void mma16816(float* d, const u32* a, u32 b0, u32 b1) {
    asm volatile(
        "mma.sync.aligned.m16n8k16.row.col.f32.bf16.bf16.f32 "
        "{%0,%1,%2,%3}, {%4,%5,%6,%7}, {%8,%9}, {%0,%1,%2,%3};"
        : "+f"(d[0]), "+f"(d[1]), "+f"(d[2]), "+f"(d[3])
        : "r"(a[0]), "r"(a[1]), "r"(a[2]), "r"(a[3]), "r"(b0), "r"(b1));
}
// truncation hi/lo split (scalar, used in prep): hi = top16, lo = RN(t - hi)
__device__ __forceinline__ void bsplit(float t, u16& h, u16& l) {
    u32 u = __float_as_uint(t);
    h = (u16)(u >> 16);
    float fh = __uint_as_float(u & 0xFFFF0000u);
    l = __bfloat16_as_ushort(__float2bfloat16(t - fh));
}
// packed pair split: h = hi16(v0)|hi16(v1)<<16 via PRMT; l = bf16x2 of residuals
__device__ __forceinline__ void bsplit2(float v0, float v1, u32& h, u32& l) {
    u32 u0 = __float_as_uint(v0), u1 = __float_as_uint(v1);
    asm("prmt.b32 %0, %1, %2, 0x7632;" : "=r"(h) : "r"(u0), "r"(u1));
    float f0 = __uint_as_float(u0 & 0xFFFF0000u);
    float f1 = __uint_as_float(u1 & 0xFFFF0000u);
    asm("cvt.rn.bf16x2.f32 %0, %1, %2;" : "=r"(l) : "f"(v1 - f1), "f"(v0 - f0));
}

// ---------------------------------------------------------------------------
// Combined prep: zero stats + B fragments.
// Taps 0..48: L2(K=7); 49..73: L3(K=5); 74..82: L4(K=3); 83..91: L5(K=3);
// 92..102: L1 (11 dy-taps, "ci" = dx of the 11-wide row, zero-padded to 16).
// ---------------------------------------------------------------------------
__global__ void prep_all_b(const float* __restrict__ w1, const float* __restrict__ w2,
                           const float* __restrict__ w3, const float* __restrict__ w4,
                           const float* __restrict__ w5,
                           u32* __restrict__ bf, double* __restrict__ st) {
    if (blockIdx.x == 0 && threadIdx.x < 192) st[threadIdx.x] = 0.0;
    const int total = 103 * 2 * 32;
    for (int i = blockIdx.x * blockDim.x + threadIdx.x; i < total;
         i += gridDim.x * blockDim.x) {
        int lane = i & 31;
        int half = (i >> 5) & 1;
        int gt = i >> 6;
        int k0 = (lane & 3) * 2, nn = lane >> 2;
        u32 out[4];
        if (gt >= 92) {
            // L1: tap = dy, k index = dx (0..10 real, 11..15 zero)
            int dy = gt - 92;
#pragma unroll
            for (int t = 0; t < 2; t++) {
#pragma unroll
                for (int kk = 0; kk < 2; kk++) {
                    int co = t * 8 + nn;
                    int dx = k0 + kk * 8;
                    float v0 = (dx < 11) ? w1[co * 121 + dy * 11 + dx] : 0.f;
                    float v1 = (dx + 1 < 11) ? w1[co * 121 + dy * 11 + dx + 1] : 0.f;
                    u16 h0, l0, h1, l1;
                    bsplit(v0, h0, l0);
                    bsplit(v1, h1, l1);
                    u16 a = half ? l0 : h0, b = half ? l1 : h1;
                    out[t * 2 + kk] = (u32)a | ((u32)b << 16);
                }
            }
        } else {
            const float* w;
            int K, tap;
            if (gt < 49)      { w = w2; K = 7; tap = gt; }
            else if (gt < 74) { w = w3; K = 5; tap = gt - 49; }
            else if (gt < 83) { w = w4; K = 3; tap = gt - 74; }
            else              { w = w5; K = 3; tap = gt - 83; }
            int dy = tap / K, dx = tap - dy * K;
#pragma unroll
            for (int t = 0; t < 2; t++) {
#pragma unroll
                for (int kk = 0; kk < 2; kk++) {
                    int co = t * 8 + nn;
                    int k = k0 + kk * 8;
                    float v0 = w[((co * 16 + k) * K + dy) * K + dx];
                    float v1 = w[((co * 16 + k + 1) * K + dy) * K + dx];
                    u16 h0, l0, h1, l1;
                    bsplit(v0, h0, l0);
                    bsplit(v1, h1, l1);
                    u16 a = half ? l0 : h0, b = half ? l1 : h1;
                    out[t * 2 + kk] = (u32)a | ((u32)b << 16);
                }
            }
        }
        ((uint4*)bf)[i] = make_uint4(out[0], out[1], out[2], out[3]);
    }
}

// ---------------------------------------------------------------------------
// Tensor-core partial-conv layer (cin=cout=16), layers 2-5. Unchanged R12.
// ---------------------------------------------------------------------------
template <int K, bool AFF>
__global__ void __launch_bounds__(128, (K <= 3) ? 4 : 3) tmma_conv_k(
    const float* __restrict__ in, long long inNS,
    const float* __restrict__ mk, long long mkNS,
    const u32* __restrict__ bfrag, const float* __restrict__ bias,
    const double* __restrict__ stPrev,
    const float* __restrict__ gamPrev, const float* __restrict__ betPrev,
    float* __restrict__ outH, float* __restrict__ outM,
    double* __restrict__ stats) {
    constexpr int TY = 8, P = K / 2, TILE = 64;
    constexpr int NPX = TILE + K - 1;
    constexpr int NPXW = (NPX + 7) & ~7;
    constexpr int R = K + TY - 1;
    constexpr int ROWB = NPXW * 32;
    constexpr int SR_OFF = 0;
    constexpr int AB_OFF = 1024;
    constexpr int MK_OFF = AB_OFF + 128;
    constexpr int AH_OFF = ((MK_OFF + R * NPXW * 4 + 127) / 128) * 128;
    constexpr int AL_OFF = AH_OFF + R * ROWB;

    extern __shared__ char smx[];
    float*  sR  = (float*)(smx + SR_OFF);
    float2* sAB = (float2*)(smx + AB_OFF);
    float*  sMk = (float*)(smx + MK_OFF);
    const u32 sb = smem_u32(smx);

    const int tid = threadIdx.x;
    const int wid = tid >> 5;
    const int lane = tid & 31;
    const int n  = blockIdx.z;
    const int x0 = blockIdx.x * TILE;
    const int y0 = blockIdx.y * TY;

    if (tid < 16) {
        if (AFF) {
            double mean = stPrev[tid] / (double)NPIX;
            double var  = stPrev[16 + tid] / (double)NPIX - mean * mean;
            float inv = rsqrtf((float)var + 1e-5f);
            float a = gamPrev[tid] * inv;
            sAB[tid] = make_float2(a, betPrev[tid] - (float)mean * a);
        } else {
            sAB[tid] = make_float2(1.f, 0.f);
        }
    }

    const float* mkn = mk + (long long)n * mkNS;
    for (int i = tid; i < R * NPXW; i += 128) {
        int r = i / NPXW, p = i - r * NPXW;
        int gy = y0 - P + r, gx = x0 - P + p;
        float m = 0.f;
        if ((unsigned)gy < 1024u && (unsigned)gx < 1024u) m = mkn[gy * IMW + gx];
        sMk[i] = m;
    }
    __syncthreads();

    float2 abr[16];
#pragma unroll
    for (int ci = 0; ci < 16; ci++) abr[ci] = sAB[ci];
    const float* inn = in + (long long)n * inNS;
    for (int i = tid; i < R * NPX; i += 128) {
        int r = i / NPX, p = i - r * NPX;
        int gy = y0 - P + r, gx = x0 - P + p;
        bool ok = (unsigned)gy < 1024u && (unsigned)gx < 1024u;
        float m = sMk[r * NPXW + p];
        const float* ip = inn + (long long)gy * IMW + gx;
        u32 hp[8], lp[8];
#pragma unroll
        for (int c2 = 0; c2 < 8; c2++) {
            float v0 = ok ? ip[(long long)(2 * c2) * HW] : 0.f;
            float v1 = ok ? ip[(long long)(2 * c2 + 1) * HW] : 0.f;
            if (AFF) {
                v0 = fmaxf(fmaf(v0, abr[2 * c2].x, abr[2 * c2].y), 0.f);
                v1 = fmaxf(fmaf(v1, abr[2 * c2 + 1].x, abr[2 * c2 + 1].y), 0.f);
            }
            v0 *= m;
            v1 *= m;
            bsplit2(v0, v1, hp[c2], lp[c2]);
        }
        u32 s = ((p >> 2) & 1) * 16;
        char* ah = smx + AH_OFF + r * ROWB + p * 32;
        char* al = smx + AL_OFF + r * ROWB + p * 32;
        *(uint4*)(ah + s)        = make_uint4(hp[0], hp[1], hp[2], hp[3]);
        *(uint4*)(ah + (16 ^ s)) = make_uint4(hp[4], hp[5], hp[6], hp[7]);
        *(uint4*)(al + s)        = make_uint4(lp[0], lp[1], lp[2], lp[3]);
        *(uint4*)(al + (16 ^ s)) = make_uint4(lp[4], lp[5], lp[6], lp[7]);
    }
    __syncthreads();

    const int seg = wid;
    float D[TY][2][4];
#pragma unroll
    for (int y = 0; y < TY; y++)
#pragma unroll
        for (int t = 0; t < 2; t++)
#pragma unroll
            for (int j = 0; j < 4; j++) D[y][t][j] = 0.f;

    const int l15 = lane & 15;
    const int kh = lane >> 4;
    const uint4* bf4 = (const uint4*)bfrag;

#pragma unroll 1
    for (int dx = 0; dx < K; dx++) {
        u32 sw = (u32)(((l15 + dx) >> 2) & 1);
        u32 apx = (u32)(seg * 16 + l15 + dx);
        u32 aoff = apx * 32 + (((u32)kh ^ sw) * 16);
        u32 aH = sb + AH_OFF + aoff;
        u32 aL = sb + AL_OFF + aoff;
        uint4 BH[K], BL[K];
#pragma unroll
        for (int dy = 0; dy < K; dy++) {
            BH[dy] = bf4[((dy * K + dx) * 2 + 0) * 32 + lane];
            BL[dy] = bf4[((dy * K + dx) * 2 + 1) * 32 + lane];
        }
#pragma unroll
        for (int r = 0; r < R; r++) {
            u32 Ah[4], Al[4];
            ldsm4(Ah, aH + r * ROWB);
            ldsm4(Al, aL + r * ROWB);
#pragma unroll
            for (int dy = 0; dy < K; dy++) {
                const int y = r - dy;
                if (y >= 0 && y < TY) {
                    mma16816(D[y][0], Ah, BH[dy].x, BH[dy].y);
                    mma16816(D[y][1], Ah, BH[dy].z, BH[dy].w);
                    mma16816(D[y][0], Al, BH[dy].x, BH[dy].y);
                    mma16816(D[y][1], Al, BH[dy].z, BH[dy].w);
                    mma16816(D[y][0], Ah, BL[dy].x, BL[dy].y);
                    mma16816(D[y][1], Ah, BL[dy].z, BL[dy].w);
                }
            }
        }
    }

    const int pxl = lane & 15, half = lane >> 4;
    float hsum[R], hmax[R];
    {
        const float* mb = sMk + seg * 16 + pxl;
#pragma unroll
        for (int r = 0; r < R; r++) {
            float s = 0.f, mx = 0.f;
#pragma unroll
            for (int dxm = 0; dxm < K; dxm++) {
                float m = mb[r * NPXW + dxm];
                s += m;
                mx = fmaxf(mx, m);
            }
            hsum[r] = s;
            hmax[r] = mx;
        }
    }
    float invv[4];
#pragma unroll
    for (int j = 0; j < 4; j++) {
        int y = half + 2 * j;
        float s = 0.f, mx = 0.f;
#pragma unroll
        for (int dy = 0; dy < K; dy++) {
            s += hsum[y + dy];
            mx = fmaxf(mx, hmax[y + dy]);
        }
        invv[j] = 1.0f / (s + 1e-8f);
        outM[(long long)n * HW + (long long)(y0 + y) * IMW + x0 + seg * 16 + pxl] = mx;
    }

    float bco[4];
#pragma unroll
    for (int t = 0; t < 2; t++)
#pragma unroll
        for (int j = 0; j < 2; j++)
            bco[t * 2 + j] = bias[t * 8 + (lane & 3) * 2 + j];
    float p1[4] = {0.f, 0.f, 0.f, 0.f}, p2[4] = {0.f, 0.f, 0.f, 0.f};
    const int pxa = seg * 16 + (lane >> 2);

#pragma unroll
    for (int y = 0; y < TY; y++) {
        float vsel = invv[y >> 1];
        float inva = __shfl_sync(0xffffffffu, vsel, ((y & 1) << 4) + (lane >> 2));
        float invb = __shfl_sync(0xffffffffu, vsel, ((y & 1) << 4) + (lane >> 2) + 8);
        int gy = y0 + y;
        float* hb = outH + (long long)n * 16 * HW + (long long)gy * IMW + x0;
#pragma unroll
        for (int t = 0; t < 2; t++) {
#pragma unroll
            for (int j = 0; j < 2; j++) {
                int co = t * 8 + (lane & 3) * 2 + j;
                float bc = bco[t * 2 + j];
                float v0 = fmaf(D[y][t][j], inva, bc);
                float v1 = fmaf(D[y][t][j + 2], invb, bc);
                hb[(long long)co * HW + pxa] = v0;
                hb[(long long)co * HW + pxa + 8] = v1;
                p1[t * 2 + j] += v0 + v1;
                p2[t * 2 + j] = fmaf(v0, v0, fmaf(v1, v1, p2[t * 2 + j]));
            }
        }
    }
#pragma unroll
    for (int k = 0; k < 4; k++) {
#pragma unroll
        for (int o = 4; o < 32; o <<= 1) {
            p1[k] += __shfl_xor_sync(0xffffffffu, p1[k], o);
            p2[k] += __shfl_xor_sync(0xffffffffu, p2[k], o);
        }
    }
    if (lane < 4) {
#pragma unroll
        for (int t = 0; t < 2; t++)
#pragma unroll
            for (int j = 0; j < 2; j++) {
                int co = t * 8 + lane * 2 + j;
                sR[(co * 2 + 0) * 4 + wid] = p1[t * 2 + j];
                sR[(co * 2 + 1) * 4 + wid] = p2[t * 2 + j];
            }
    }
    __syncthreads();
    if (tid < 32) {
        int co = tid >> 1, which = tid & 1;
        float v = sR[tid * 4 + 0] + sR[tid * 4 + 1] + sR[tid * 4 + 2] + sR[tid * 4 + 3];
        atomicAdd(&stats[which * 16 + co], (double)v);
    }
}

// ---------------------------------------------------------------------------
// Layer 1 tensor-core partial conv (cin=1, K=11): dx taps packed as MMA
// channels. Tile = 64 px * TY=4 rows, 128 threads / 4 warps.
// A[px][c] = xm[row, x0 - 5 + px + c]; 11 dy-taps, 3 MMAs each per n-tile.
// ---------------------------------------------------------------------------
__global__ void __launch_bounds__(128, 3) tmma_conv1_k(
    const float* __restrict__ in, long long inNS,
    const float* __restrict__ mk, long long mkNS,
    const u32* __restrict__ bfrag, const float* __restrict__ bias,
    float* __restrict__ outH, float* __restrict__ outM,
    double* __restrict__ stats) {
    constexpr int K = 11, TY = 4, P = 5, TILE = 64;
    constexpr int R = K + TY - 1;          // 14 window rows
    constexpr int MW = 80;                 // mask/xm row width (64+15 pad)
    constexpr int MUSE = TILE + K - 1;     // 74 meaningful columns
    constexpr int ROWB = TILE * 32;        // A row bytes (64 px * 32B)
    constexpr int SR_OFF = 0;
    constexpr int MK_OFF = 1024;
    constexpr int XM_OFF = MK_OFF + R * MW * 4;
    constexpr int AH_OFF = ((XM_OFF + R * MW * 4 + 127) / 128) * 128;
    constexpr int AL_OFF = AH_OFF + R * ROWB;

    extern __shared__ char smx[];
    float* sR  = (float*)(smx + SR_OFF);
    float* sMk = (float*)(smx + MK_OFF);
    float* sXm = (float*)(smx + XM_OFF);
    const u32 sb = smem_u32(smx);

    const int tid = threadIdx.x;
    const int wid = tid >> 5;
    const int lane = tid & 31;
    const int n  = blockIdx.z;
    const int x0 = blockIdx.x * TILE;
    const int y0 = blockIdx.y * TY;

    // ---- stage mask + xm = x*mask rows ----
    const float* mkn = mk + (long long)n * mkNS;
    const float* inn = in + (long long)n * inNS;
    for (int i = tid; i < R * MW; i += 128) {
        int r = i / MW, j = i - r * MW;
        int gy = y0 - P + r, gx = x0 - P + j;
        float m = 0.f, v = 0.f;
        if ((unsigned)gy < 1024u && (unsigned)gx < 1024u && j < MUSE) {
            m = mkn[gy * IMW + gx];
            v = inn[gy * IMW + gx];
        }
        sMk[i] = m;
        sXm[i] = v * m;
    }
    __syncthreads();

    // ---- stage A: A[r][px][c] = xm[r][px + c]  (c = dx tap, 0..15) ----
    for (int i = tid; i < R * TILE; i += 128) {
        int r = i >> 6, p = i & 63;
        const float* xr = sXm + r * MW + p;
        u32 hp[8], lp[8];
#pragma unroll
        for (int c2 = 0; c2 < 8; c2++)
            bsplit2(xr[2 * c2], xr[2 * c2 + 1], hp[c2], lp[c2]);
        u32 s = ((p >> 2) & 1) * 16;
        char* ah = smx + AH_OFF + r * ROWB + p * 32;
        char* al = smx + AL_OFF + r * ROWB + p * 32;
        *(uint4*)(ah + s)        = make_uint4(hp[0], hp[1], hp[2], hp[3]);
        *(uint4*)(ah + (16 ^ s)) = make_uint4(hp[4], hp[5], hp[6], hp[7]);
        *(uint4*)(al + s)        = make_uint4(lp[0], lp[1], lp[2], lp[3]);
        *(uint4*)(al + (16 ^ s)) = make_uint4(lp[4], lp[5], lp[6], lp[7]);
    }
    __syncthreads();

    // ---- MMA mainloop: r-sweep, B per (r,dy) from global (L1-resident) ----
    const int seg = wid;
    float D[TY][2][4];
#pragma unroll
    for (int y = 0; y < TY; y++)
#pragma unroll
        for (int t = 0; t < 2; t++)
#pragma unroll
            for (int j = 0; j < 4; j++) D[y][t][j] = 0.f;

    const int l15 = lane & 15;
    const int kh = lane >> 4;
    const uint4* bf4 = (const uint4*)bfrag;
    {
        u32 sw = (u32)((l15 >> 2) & 1);
        u32 aoff = (u32)(seg * 16 + l15) * 32 + (((u32)kh ^ sw) * 16);
        u32 aH = sb + AH_OFF + aoff;
        u32 aL = sb + AL_OFF + aoff;
#pragma unroll
        for (int r = 0; r < R; r++) {
            u32 Ah[4], Al[4];
            ldsm4(Ah, aH + r * ROWB);
            ldsm4(Al, aL + r * ROWB);
#pragma unroll
            for (int dy = 0; dy < K; dy++) {
                const int y = r - dy;
                if (y >= 0 && y < TY) {
                    uint4 BH = bf4[(dy * 2 + 0) * 32 + lane];
                    uint4 BL = bf4[(dy * 2 + 1) * 32 + lane];
                    mma16816(D[y][0], Ah, BH.x, BH.y);
                    mma16816(D[y][1], Ah, BH.z, BH.w);
                    mma16816(D[y][0], Al, BH.x, BH.y);
                    mma16816(D[y][1], Al, BH.z, BH.w);
                    mma16816(D[y][0], Ah, BL.x, BL.y);
                    mma16816(D[y][1], Ah, BL.z, BL.w);
                }
            }
        }
    }

    // ---- separable mask-sum conv + maxpool (lane owns rows half+2j) ----
    const int pxl = lane & 15, half = lane >> 4;
    float hsum[R], hmax[R];
    {
        const float* mb = sMk + seg * 16 + pxl;
#pragma unroll
        for (int r = 0; r < R; r++) {
            float s = 0.f, mx = 0.f;
#pragma unroll
            for (int dxm = 0; dxm < K; dxm++) {
                float m = mb[r * MW + dxm];
                s += m;
                mx = fmaxf(mx, m);
            }
            hsum[r] = s;
            hmax[r] = mx;
        }
    }
    float invv[2];
#pragma unroll
    for (int j = 0; j < 2; j++) {
        int y = half + 2 * j;
        float s = 0.f, mx = 0.f;
#pragma unroll
        for (int dy = 0; dy < K; dy++) {
            s += hsum[y + dy];
            mx = fmaxf(mx, hmax[y + dy]);
        }
        invv[j] = 1.0f / (s + 1e-8f);
        outM[(long long)n * HW + (long long)(y0 + y) * IMW + x0 + seg * 16 + pxl] = mx;
    }

    // ---- epilogue ----
    float bco[4];
#pragma unroll
    for (int t = 0; t < 2; t++)
#pragma unroll
        for (int j = 0; j < 2; j++)
            bco[t * 2 + j] = bias[t * 8 + (lane & 3) * 2 + j];
    float p1[4] = {0.f, 0.f, 0.f, 0.f}, p2[4] = {0.f, 0.f, 0.f, 0.f};
    const int pxa = seg * 16 + (lane >> 2);

#pragma unroll
    for (int y = 0; y < TY; y++) {
        float vsel = invv[y >> 1];
        float inva = __shfl_sync(0xffffffffu, vsel, ((y & 1) << 4) + (lane >> 2));
        float invb = __shfl_sync(0xffffffffu, vsel, ((y & 1) << 4) + (lane >> 2) + 8);
        int gy = y0 + y;
        float* hb = outH + (long long)n * 16 * HW + (long long)gy * IMW + x0;
#pragma unroll
        for (int t = 0; t < 2; t++) {
#pragma unroll
            for (int j = 0; j < 2; j++) {
                int co = t * 8 + (lane & 3) * 2 + j;
                float bc = bco[t * 2 + j];
                float v0 = fmaf(D[y][t][j], inva, bc);
                float v1 = fmaf(D[y][t][j + 2], invb, bc);
                hb[(long long)co * HW + pxa] = v0;
                hb[(long long)co * HW + pxa + 8] = v1;
                p1[t * 2 + j] += v0 + v1;
                p2[t * 2 + j] = fmaf(v0, v0, fmaf(v1, v1, p2[t * 2 + j]));
            }
        }
    }
#pragma unroll
    for (int k = 0; k < 4; k++) {
#pragma unroll
        for (int o = 4; o < 32; o <<= 1) {
            p1[k] += __shfl_xor_sync(0xffffffffu, p1[k], o);
            p2[k] += __shfl_xor_sync(0xffffffffu, p2[k], o);
        }
    }
    if (lane < 4) {
#pragma unroll
        for (int t = 0; t < 2; t++)
#pragma unroll
            for (int j = 0; j < 2; j++) {
                int co = t * 8 + lane * 2 + j;
                sR[(co * 2 + 0) * 4 + wid] = p1[t * 2 + j];
                sR[(co * 2 + 1) * 4 + wid] = p2[t * 2 + j];
            }
    }
    __syncthreads();
    if (tid < 32) {
        int co = tid >> 1, which = tid & 1;
        float v = sR[tid * 4 + 0] + sR[tid * 4 + 1] + sR[tid * 4 + 2] + sR[tid * 4 + 3];
        atomicAdd(&stats[which * 16 + co], (double)v);
    }
}

// ---------------------------------------------------------------------------
// Layer 6: 1x1 partial conv, 16 -> 1; float4 (4 px/thread); affine in-block.
// ---------------------------------------------------------------------------
__global__ void conv1x1_k(const float* __restrict__ h,
                          const float* __restrict__ mk,
                          const float* __restrict__ w6,
                          const float* __restrict__ b6,
                          const double* __restrict__ st5,
                          const float* __restrict__ g5,
                          const float* __restrict__ bt5,
                          float* __restrict__ y,
                          double* __restrict__ stats) {
    __shared__ float swv[16];
    __shared__ float2 sab[16];
    __shared__ float r1[8], r2[8];
    if (threadIdx.x < 16) {
        swv[threadIdx.x] = w6[threadIdx.x];
        double mean = st5[threadIdx.x] / (double)NPIX;
        double var  = st5[16 + threadIdx.x] / (double)NPIX - mean * mean;
        float inv = rsqrtf((float)var + 1e-5f);
        float a = g5[threadIdx.x] * inv;
        sab[threadIdx.x] = make_float2(a, bt5[threadIdx.x] - (float)mean * a);
    }
    __syncthreads();
    float bb = b6[0];
    float p1 = 0.f, p2 = 0.f;
    const float4* mk4 = (const float4*)mk;
    float4* y4 = (float4*)y;
    for (long long i = (long long)blockIdx.x * blockDim.x + threadIdx.x;
         i < 1LL * HW; i += (long long)gridDim.x * blockDim.x) {
        long long n = i >> 18;
        long long p4 = i & ((HW >> 2) - 1);
        float4 m = mk4[i];
        float4 acc = make_float4(0.f, 0.f, 0.f, 0.f);
        const float4* hb = (const float4*)(h + (n * 16) * HW) + p4;
#pragma unroll
        for (int c = 0; c < 16; c++) {
            float4 v = hb[(long long)c * (HW >> 2)];
            float2 ab = sab[c];
            float wv = swv[c];
            acc.x = fmaf(wv, fmaxf(fmaf(v.x, ab.x, ab.y), 0.f), acc.x);
            acc.y = fmaf(wv, fmaxf(fmaf(v.y, ab.x, ab.y), 0.f), acc.y);
            acc.z = fmaf(wv, fmaxf(fmaf(v.z, ab.x, ab.y), 0.f), acc.z);
            acc.w = fmaf(wv, fmaxf(fmaf(v.w, ab.x, ab.y), 0.f), acc.w);
        }
        float4 o;
        o.x = fmaf(acc.x * m.x, 1.0f / (m.x + 1e-8f), bb);
        o.y = fmaf(acc.y * m.y, 1.0f / (m.y + 1e-8f), bb);
        o.z = fmaf(acc.z * m.z, 1.0f / (m.z + 1e-8f), bb);
        o.w = fmaf(acc.w * m.w, 1.0f / (m.w + 1e-8f), bb);
        y4[i] = o;
        p1 += (o.x + o.y) + (o.z + o.w);
        p2 = fmaf(o.x, o.x, fmaf(o.y, o.y, fmaf(o.z, o.z, fmaf(o.w, o.w, p2))));
    }
#pragma unroll
    for (int o = 16; o; o >>= 1) {
        p1 += __shfl_xor_sync(0xffffffffu, p1, o);
        p2 += __shfl_xor_sync(0xffffffffu, p2, o);
    }
    int warp = threadIdx.x >> 5, lane = threadIdx.x & 31;
    if (lane == 0) { r1[warp] = p1; r2[warp] = p2; }
    __syncthreads();
    if (threadIdx.x == 0) {
        float a = 0.f, b = 0.f;
        for (int w = 0; w < (int)(blockDim.x >> 5); w++) { a += r1[w]; b += r2[w]; }
        atomicAdd(&stats[0], (double)a);
        atomicAdd(&stats[16], (double)b);
    }
}

// Final BN (no relu), float4; affine of layer 6 computed per block.
__global__ void final_k(const float* __restrict__ y,
                        const double* __restrict__ st6,
                        const float* __restrict__ g6,
                        const float* __restrict__ bt6,
                        float* __restrict__ o) {
    __shared__ float2 t;
    if (threadIdx.x == 0) {
        double mean = st6[0] / (double)NPIX;
        double var  = st6[16] / (double)NPIX - mean * mean;
        float inv = rsqrtf((float)var + 1e-5f);
        float a = g6[0] * inv;
        t = make_float2(a, bt6[0] - (float)mean * a);
    }
    __syncthreads();
    float2 tt = t;
    const float4* y4 = (const float4*)y;
    float4* o4 = (float4*)o;
    for (long long i = (long long)blockIdx.x * blockDim.x + threadIdx.x;
         i < 1LL * HW; i += (long long)gridDim.x * blockDim.x) {
        float4 v = y4[i];
        v.x = fmaf(v.x, tt.x, tt.y);
        v.y = fmaf(v.y, tt.x, tt.y);
        v.z = fmaf(v.z, tt.x, tt.y);
        v.w = fmaf(v.w, tt.x, tt.y);
        o4[i] = v;
    }
}

// ---------------------------------------------------------------------------
static constexpr int tmma_smem(int K) {
    int TY = 8, TILE = 64;
    int NPX = TILE + K - 1, NPXW = (NPX + 7) & ~7, R = K + TY - 1;
    int MK = 1024 + 128;
    int AH = ((MK + R * NPXW * 4 + 127) / 128) * 128;
    return AH + 2 * R * NPXW * 32;
}
static constexpr int tmma1_smem() {
    int R = 14, MW = 80, ROWB = 64 * 32;
    int XM = 1024 + R * MW * 4;
    int AH = ((XM + R * MW * 4 + 127) / 128) * 128;
    return AH + 2 * R * ROWB;
}

extern "C" void kernel_launch(void* const* d_in, const int* in_sizes, int n_in,
                              void* d_out, int out_size) {
    (void)in_sizes; (void)n_in; (void)out_size;
    const float* x = (const float*)d_in[0];
    const float *wp[6], *bp[6], *gp[6], *btp[6];
    for (int i = 0; i < 6; i++) {
        wp[i]  = (const float*)d_in[1 + 4 * i];
        bp[i]  = (const float*)d_in[2 + 4 * i];
        gp[i]  = (const float*)d_in[3 + 4 * i];
        btp[i] = (const float*)d_in[4 + 4 * i];
    }

    float *h0, *h1, *m0, *m1;
    double* st;
    u32* bf;
    cudaGetSymbolAddress((void**)&h0, g_h0);
    cudaGetSymbolAddress((void**)&h1, g_h1);
    cudaGetSymbolAddress((void**)&m0, g_m0);
    cudaGetSymbolAddress((void**)&m1, g_m1);
    cudaGetSymbolAddress((void**)&st, g_stats);
    cudaGetSymbolAddress((void**)&bf, g_bfrag);

    cudaFuncSetAttribute(tmma_conv1_k, cudaFuncAttributeMaxDynamicSharedMemorySize, tmma1_smem());
    cudaFuncSetAttribute(tmma_conv_k<7, true>, cudaFuncAttributeMaxDynamicSharedMemorySize, tmma_smem(7));
    cudaFuncSetAttribute(tmma_conv_k<5, true>, cudaFuncAttributeMaxDynamicSharedMemorySize, tmma_smem(5));
    cudaFuncSetAttribute(tmma_conv_k<3, true>, cudaFuncAttributeMaxDynamicSharedMemorySize, tmma_smem(3));

    dim3 t1grid(1024 / 64, 1024 / 4, 4);
    dim3 tgrid(1024 / 64, 1024 / 8, 4);

    u32* bf2 = bf;
    u32* bf3 = bf + 49 * 256;
    u32* bf4p = bf + 74 * 256;
    u32* bf5 = bf + 83 * 256;
    u32* bf1 = bf + 92 * 256;

    prep_all_b<<<26, 256>>>(wp[0], wp[1], wp[2], wp[3], wp[4], bf, st);

    tmma_conv1_k<<<t1grid, 128, tmma1_smem()>>>(
        x, 2LL * HW, x + HW, 2LL * HW, bf1, bp[0], h0, m0, st + 0);

    tmma_conv_k<7, true><<<tgrid, 128, tmma_smem(7)>>>(
        h0, 16LL * HW, m0, (long long)HW, bf2, bp[1],
        st + 0, gp[0], btp[0], h1, m1, st + 32);

    tmma_conv_k<5, true><<<tgrid, 128, tmma_smem(5)>>>(
        h1, 16LL * HW, m1, (long long)HW, bf3, bp[2],
        st + 32, gp[1], btp[1], h0, m0, st + 64);

    tmma_conv_k<3, true><<<tgrid, 128, tmma_smem(3)>>>(
        h0, 16LL * HW, m0, (long long)HW, bf4p, bp[3],
        st + 64, gp[2], btp[2], h1, m1, st + 96);

    tmma_conv_k<3, true><<<tgrid, 128, tmma_smem(3)>>>(
        h1, 16LL * HW, m1, (long long)HW, bf5, bp[4],
        st + 96, gp[3], btp[3], h0, m0, st + 128);

    conv1x1_k<<<1184, 256>>>(h0, m0, wp[5], bp[5],
                             st + 128, gp[4], btp[4], h1, st + 160);

    final_k<<<2048, 256>>>(h1, st + 160, gp[5], btp[5], (float*)d_out);
}

// round 14
// speedup vs baseline: 2.4775x; 1.0208x over previous
#include <cuda_runtime.h>
#include <cuda_bf16.h>
#include <math.h>

// ---------------------------------------------------------------------------
// SparseConvNet: 6 partial-conv layers. N=4, H=W=1024.
// Round 14: fused mask+A staging (one loop, no smem mask re-read) in all
// tensor-core layers; L1 moved to TY=8 (staging redundancy 3.5x -> 2.25x).
// MMA core (row-major r-sweep, 3-term bf16 split) unchanged from R12/R13.
// ---------------------------------------------------------------------------

#define HW   (1024 * 1024)
#define IMW  1024
#define NPIX (4LL * HW)

__device__ float  g_h0[4 * 16 * HW];
__device__ float  g_h1[4 * 16 * HW];
__device__ float  g_m0[4 * HW];
__device__ float  g_m1[4 * HW];
__device__ double g_stats[6 * 32];
__device__ unsigned int g_bfrag[103 * 2 * 32 * 4];  // 49+25+9+9 + 11 (L1) taps

typedef unsigned long long u64;
typedef unsigned int u32;
typedef unsigned short u16;

__device__ __forceinline__ u32 smem_u32(const void* p) {
    u32 a;
    asm("{ .reg .u64 t; cvta.to.shared.u64 t, %1; cvt.u32.u64 %0, t; }"
        : "=r"(a) : "l"(p));
    return a;
}
__device__ __forceinline__ void ldsm4(u32* r, u32 a) {
    asm volatile("ldmatrix.sync.aligned.m8n8.x4.shared.b16 {%0,%1,%2,%3}, [%4];"
                 : "=r"(r[0]), "=r"(r[1]), "=r"(r[2]), "=r"(r[3]) : "r"(a));
}
__device__ __forceinline__ void mma16816(float* d, const u32* a, u32 b0, u32 b1) {
    asm volatile(
        "mma.sync.aligned.m16n8k16.row.col.f32.bf16.bf16.f32 "
        "{%0,%1,%2,%3}, {%4,%5,%6,%7}, {%8,%9}, {%0,%1,%2,%3};"
        : "+f"(d[0]), "+f"(d[1]), "+f"(d[2]), "+f"(d[3])
        : "r"(a[0]), "r"(a[1]), "r"(a[2]), "r"(a[3]), "r"(b0), "r"(b1));
}
// truncation hi/lo split (scalar, used in prep): hi = top16, lo = RN(t - hi)
__device__ __forceinline__ void bsplit(float t, u16& h, u16& l) {
    u32 u = __float_as_uint(t);
    h = (u16)(u >> 16);
    float fh = __uint_as_float(u & 0xFFFF0000u);
    l = __bfloat16_as_ushort(__float2bfloat16(t - fh));
}
// packed pair split: h = hi16(v0)|hi16(v1)<<16 via PRMT; l = bf16x2 of residuals
__device__ __forceinline__ void bsplit2(float v0, float v1, u32& h, u32& l) {
    u32 u0 = __float_as_uint(v0), u1 = __float_as_uint(v1);
    asm("prmt.b32 %0, %1, %2, 0x7632;" : "=r"(h) : "r"(u0), "r"(u1));
    float f0 = __uint_as_float(u0 & 0xFFFF0000u);
    float f1 = __uint_as_float(u1 & 0xFFFF0000u);
    asm("cvt.rn.bf16x2.f32 %0, %1, %2;" : "=r"(l) : "f"(v1 - f1), "f"(v0 - f0));
}

// ---------------------------------------------------------------------------
// Combined prep: zero stats + B fragments.
// Taps 0..48: L2(K=7); 49..73: L3(K=5); 74..82: L4(K=3); 83..91: L5(K=3);
// 92..102: L1 (11 dy-taps, "ci" = dx of the 11-wide row, zero-padded to 16).
// ---------------------------------------------------------------------------
__global__ void prep_all_b(const float* __restrict__ w1, const float* __restrict__ w2,
                           const float* __restrict__ w3, const float* __restrict__ w4,
                           const float* __restrict__ w5,
                           u32* __restrict__ bf, double* __restrict__ st) {
    if (blockIdx.x == 0 && threadIdx.x < 192) st[threadIdx.x] = 0.0;
    const int total = 103 * 2 * 32;
    for (int i = blockIdx.x * blockDim.x + threadIdx.x; i < total;
         i += gridDim.x * blockDim.x) {
        int lane = i & 31;
        int half = (i >> 5) & 1;
        int gt = i >> 6;
        int k0 = (lane & 3) * 2, nn = lane >> 2;
        u32 out[4];
        if (gt >= 92) {
            int dy = gt - 92;
#pragma unroll
            for (int t = 0; t < 2; t++) {
#pragma unroll
                for (int kk = 0; kk < 2; kk++) {
                    int co = t * 8 + nn;
                    int dx = k0 + kk * 8;
                    float v0 = (dx < 11) ? w1[co * 121 + dy * 11 + dx] : 0.f;
                    float v1 = (dx + 1 < 11) ? w1[co * 121 + dy * 11 + dx + 1] : 0.f;
                    u16 h0, l0, h1, l1;
                    bsplit(v0, h0, l0);
                    bsplit(v1, h1, l1);
                    u16 a = half ? l0 : h0, b = half ? l1 : h1;
                    out[t * 2 + kk] = (u32)a | ((u32)b << 16);
                }
            }
        } else {
            const float* w;
            int K, tap;
            if (gt < 49)      { w = w2; K = 7; tap = gt; }
            else if (gt < 74) { w = w3; K = 5; tap = gt - 49; }
            else if (gt < 83) { w = w4; K = 3; tap = gt - 74; }
            else              { w = w5; K = 3; tap = gt - 83; }
            int dy = tap / K, dx = tap - dy * K;
#pragma unroll
            for (int t = 0; t < 2; t++) {
#pragma unroll
                for (int kk = 0; kk < 2; kk++) {
                    int co = t * 8 + nn;
                    int k = k0 + kk * 8;
                    float v0 = w[((co * 16 + k) * K + dy) * K + dx];
                    float v1 = w[((co * 16 + k + 1) * K + dy) * K + dx];
                    u16 h0, l0, h1, l1;
                    bsplit(v0, h0, l0);
                    bsplit(v1, h1, l1);
                    u16 a = half ? l0 : h0, b = half ? l1 : h1;
                    out[t * 2 + kk] = (u32)a | ((u32)b << 16);
                }
            }
        }
        ((uint4*)bf)[i] = make_uint4(out[0], out[1], out[2], out[3]);
    }
}

// ---------------------------------------------------------------------------
// Tensor-core partial-conv layer (cin=cout=16), layers 2-5. TY=8, fused
// mask+A staging (single loop; sMk pad columns never read downstream).
// ---------------------------------------------------------------------------
template <int K, bool AFF>
__global__ void __launch_bounds__(128, (K <= 3) ? 4 : 3) tmma_conv_k(
    const float* __restrict__ in, long long inNS,
    const float* __restrict__ mk, long long mkNS,
    const u32* __restrict__ bfrag, const float* __restrict__ bias,
    const double* __restrict__ stPrev,
    const float* __restrict__ gamPrev, const float* __restrict__ betPrev,
    float* __restrict__ outH, float* __restrict__ outM,
    double* __restrict__ stats) {
    constexpr int TY = 8, P = K / 2, TILE = 64;
    constexpr int NPX = TILE + K - 1;
    constexpr int NPXW = (NPX + 7) & ~7;
    constexpr int R = K + TY - 1;
    constexpr int ROWB = NPXW * 32;
    constexpr int SR_OFF = 0;
    constexpr int AB_OFF = 1024;
    constexpr int MK_OFF = AB_OFF + 128;
    constexpr int AH_OFF = ((MK_OFF + R * NPXW * 4 + 127) / 128) * 128;
    constexpr int AL_OFF = AH_OFF + R * ROWB;

    extern __shared__ char smx[];
    float*  sR  = (float*)(smx + SR_OFF);
    float2* sAB = (float2*)(smx + AB_OFF);
    float*  sMk = (float*)(smx + MK_OFF);
    const u32 sb = smem_u32(smx);

    const int tid = threadIdx.x;
    const int wid = tid >> 5;
    const int lane = tid & 31;
    const int n  = blockIdx.z;
    const int x0 = blockIdx.x * TILE;
    const int y0 = blockIdx.y * TY;

    if (tid < 16) {
        if (AFF) {
            double mean = stPrev[tid] / (double)NPIX;
            double var  = stPrev[16 + tid] / (double)NPIX - mean * mean;
            float inv = rsqrtf((float)var + 1e-5f);
            float a = gamPrev[tid] * inv;
            sAB[tid] = make_float2(a, betPrev[tid] - (float)mean * a);
        } else {
            sAB[tid] = make_float2(1.f, 0.f);
        }
    }
    __syncthreads();

    float2 abr[16];
#pragma unroll
    for (int ci = 0; ci < 16; ci++) abr[ci] = sAB[ci];

    // ---- fused mask + A staging (single loop) ----
    const float* mkn = mk + (long long)n * mkNS;
    const float* inn = in + (long long)n * inNS;
    for (int i = tid; i < R * NPX; i += 128) {
        int r = i / NPX, p = i - r * NPX;
        int gy = y0 - P + r, gx = x0 - P + p;
        bool ok = (unsigned)gy < 1024u && (unsigned)gx < 1024u;
        long long goff = (long long)gy * IMW + gx;
        float m = ok ? mkn[goff] : 0.f;
        sMk[r * NPXW + p] = m;
        const float* ip = inn + goff;
        u32 hp[8], lp[8];
#pragma unroll
        for (int c2 = 0; c2 < 8; c2++) {
            float v0 = ok ? ip[(long long)(2 * c2) * HW] : 0.f;
            float v1 = ok ? ip[(long long)(2 * c2 + 1) * HW] : 0.f;
            if (AFF) {
                v0 = fmaxf(fmaf(v0, abr[2 * c2].x, abr[2 * c2].y), 0.f);
                v1 = fmaxf(fmaf(v1, abr[2 * c2 + 1].x, abr[2 * c2 + 1].y), 0.f);
            }
            v0 *= m;
            v1 *= m;
            bsplit2(v0, v1, hp[c2], lp[c2]);
        }
        u32 s = ((p >> 2) & 1) * 16;
        char* ah = smx + AH_OFF + r * ROWB + p * 32;
        char* al = smx + AL_OFF + r * ROWB + p * 32;
        *(uint4*)(ah + s)        = make_uint4(hp[0], hp[1], hp[2], hp[3]);
        *(uint4*)(ah + (16 ^ s)) = make_uint4(hp[4], hp[5], hp[6], hp[7]);
        *(uint4*)(al + s)        = make_uint4(lp[0], lp[1], lp[2], lp[3]);
        *(uint4*)(al + (16 ^ s)) = make_uint4(lp[4], lp[5], lp[6], lp[7]);
    }
    __syncthreads();

    const int seg = wid;
    float D[TY][2][4];
#pragma unroll
    for (int y = 0; y < TY; y++)
#pragma unroll
        for (int t = 0; t < 2; t++)
#pragma unroll
            for (int j = 0; j < 4; j++) D[y][t][j] = 0.f;

    const int l15 = lane & 15;
    const int kh = lane >> 4;
    const uint4* bf4 = (const uint4*)bfrag;

#pragma unroll 1
    for (int dx = 0; dx < K; dx++) {
        u32 sw = (u32)(((l15 + dx) >> 2) & 1);
        u32 apx = (u32)(seg * 16 + l15 + dx);
        u32 aoff = apx * 32 + (((u32)kh ^ sw) * 16);
        u32 aH = sb + AH_OFF + aoff;
        u32 aL = sb + AL_OFF + aoff;
        uint4 BH[K], BL[K];
#pragma unroll
        for (int dy = 0; dy < K; dy++) {
            BH[dy] = bf4[((dy * K + dx) * 2 + 0) * 32 + lane];
            BL[dy] = bf4[((dy * K + dx) * 2 + 1) * 32 + lane];
        }
#pragma unroll
        for (int r = 0; r < R; r++) {
            u32 Ah[4], Al[4];
            ldsm4(Ah, aH + r * ROWB);
            ldsm4(Al, aL + r * ROWB);
#pragma unroll
            for (int dy = 0; dy < K; dy++) {
                const int y = r - dy;
                if (y >= 0 && y < TY) {
                    mma16816(D[y][0], Ah, BH[dy].x, BH[dy].y);
                    mma16816(D[y][1], Ah, BH[dy].z, BH[dy].w);
                    mma16816(D[y][0], Al, BH[dy].x, BH[dy].y);
                    mma16816(D[y][1], Al, BH[dy].z, BH[dy].w);
                    mma16816(D[y][0], Ah, BL[dy].x, BL[dy].y);
                    mma16816(D[y][1], Ah, BL[dy].z, BL[dy].w);
                }
            }
        }
    }

    const int pxl = lane & 15, half = lane >> 4;
    float hsum[R], hmax[R];
    {
        const float* mb = sMk + seg * 16 + pxl;
#pragma unroll
        for (int r = 0; r < R; r++) {
            float s = 0.f, mx = 0.f;
#pragma unroll
            for (int dxm = 0; dxm < K; dxm++) {
                float m = mb[r * NPXW + dxm];
                s += m;
                mx = fmaxf(mx, m);
            }
            hsum[r] = s;
            hmax[r] = mx;
        }
    }
    float invv[4];
#pragma unroll
    for (int j = 0; j < 4; j++) {
        int y = half + 2 * j;
        float s = 0.f, mx = 0.f;
#pragma unroll
        for (int dy = 0; dy < K; dy++) {
            s += hsum[y + dy];
            mx = fmaxf(mx, hmax[y + dy]);
        }
        invv[j] = 1.0f / (s + 1e-8f);
        outM[(long long)n * HW + (long long)(y0 + y) * IMW + x0 + seg * 16 + pxl] = mx;
    }

    float bco[4];
#pragma unroll
    for (int t = 0; t < 2; t++)
#pragma unroll
        for (int j = 0; j < 2; j++)
            bco[t * 2 + j] = bias[t * 8 + (lane & 3) * 2 + j];
    float p1[4] = {0.f, 0.f, 0.f, 0.f}, p2[4] = {0.f, 0.f, 0.f, 0.f};
    const int pxa = seg * 16 + (lane >> 2);

#pragma unroll
    for (int y = 0; y < TY; y++) {
        float vsel = invv[y >> 1];
        float inva = __shfl_sync(0xffffffffu, vsel, ((y & 1) << 4) + (lane >> 2));
        float invb = __shfl_sync(0xffffffffu, vsel, ((y & 1) << 4) + (lane >> 2) + 8);
        int gy = y0 + y;
        float* hb = outH + (long long)n * 16 * HW + (long long)gy * IMW + x0;
#pragma unroll
        for (int t = 0; t < 2; t++) {
#pragma unroll
            for (int j = 0; j < 2; j++) {
                int co = t * 8 + (lane & 3) * 2 + j;
                float bc = bco[t * 2 + j];
                float v0 = fmaf(D[y][t][j], inva, bc);
                float v1 = fmaf(D[y][t][j + 2], invb, bc);
                hb[(long long)co * HW + pxa] = v0;
                hb[(long long)co * HW + pxa + 8] = v1;
                p1[t * 2 + j] += v0 + v1;
                p2[t * 2 + j] = fmaf(v0, v0, fmaf(v1, v1, p2[t * 2 + j]));
            }
        }
    }
#pragma unroll
    for (int k = 0; k < 4; k++) {
#pragma unroll
        for (int o = 4; o < 32; o <<= 1) {
            p1[k] += __shfl_xor_sync(0xffffffffu, p1[k], o);
            p2[k] += __shfl_xor_sync(0xffffffffu, p2[k], o);
        }
    }
    if (lane < 4) {
#pragma unroll
        for (int t = 0; t < 2; t++)
#pragma unroll
            for (int j = 0; j < 2; j++) {
                int co = t * 8 + lane * 2 + j;
                sR[(co * 2 + 0) * 4 + wid] = p1[t * 2 + j];
                sR[(co * 2 + 1) * 4 + wid] = p2[t * 2 + j];
            }
    }
    __syncthreads();
    if (tid < 32) {
        int co = tid >> 1, which = tid & 1;
        float v = sR[tid * 4 + 0] + sR[tid * 4 + 1] + sR[tid * 4 + 2] + sR[tid * 4 + 3];
        atomicAdd(&stats[which * 16 + co], (double)v);
    }
}

// ---------------------------------------------------------------------------
// Layer 1 tensor-core partial conv (cin=1, K=11), TY=8: dx taps packed as MMA
// channels. Tile = 64 px * 8 rows, 128 threads / 4 warps, 2 blocks/SM.
// ---------------------------------------------------------------------------
__global__ void __launch_bounds__(128, 2) tmma_conv1_k(
    const float* __restrict__ in, long long inNS,
    const float* __restrict__ mk, long long mkNS,
    const u32* __restrict__ bfrag, const float* __restrict__ bias,
    float* __restrict__ outH, float* __restrict__ outM,
    double* __restrict__ stats) {
    constexpr int K = 11, TY = 8, P = 5, TILE = 64;
    constexpr int R = K + TY - 1;          // 18 window rows
    constexpr int MW = 80;                 // mask/xm row width (64+15 pad)
    constexpr int MUSE = TILE + K - 1;     // 74 meaningful columns
    constexpr int ROWB = TILE * 32;        // A row bytes (64 px * 32B)
    constexpr int SR_OFF = 0;
    constexpr int MK_OFF = 1024;
    constexpr int XM_OFF = MK_OFF + R * MW * 4;
    constexpr int AH_OFF = ((XM_OFF + R * MW * 4 + 127) / 128) * 128;
    constexpr int AL_OFF = AH_OFF + R * ROWB;

    extern __shared__ char smx[];
    float* sR  = (float*)(smx + SR_OFF);
    float* sMk = (float*)(smx + MK_OFF);
    float* sXm = (float*)(smx + XM_OFF);
    const u32 sb = smem_u32(smx);

    const int tid = threadIdx.x;
    const int wid = tid >> 5;
    const int lane = tid & 31;
    const int n  = blockIdx.z;
    const int x0 = blockIdx.x * TILE;
    const int y0 = blockIdx.y * TY;

    // ---- stage mask + xm rows ----
    const float* mkn = mk + (long long)n * mkNS;
    const float* inn = in + (long long)n * inNS;
    for (int i = tid; i < R * MW; i += 128) {
        int r = i / MW, j = i - r * MW;
        int gy = y0 - P + r, gx = x0 - P + j;
        float m = 0.f, v = 0.f;
        if ((unsigned)gy < 1024u && (unsigned)gx < 1024u && j < MUSE) {
            m = mkn[gy * IMW + gx];
            v = inn[gy * IMW + gx];
        }
        sMk[i] = m;
        sXm[i] = v * m;
    }
    __syncthreads();

    // ---- stage A: A[r][px][c] = xm[r][px + c]  (c = dx tap, 0..15) ----
    for (int i = tid; i < R * TILE; i += 128) {
        int r = i >> 6, p = i & 63;
        const float* xr = sXm + r * MW + p;
        u32 hp[8], lp[8];
#pragma unroll
        for (int c2 = 0; c2 < 8; c2++)
            bsplit2(xr[2 * c2], xr[2 * c2 + 1], hp[c2], lp[c2]);
        u32 s = ((p >> 2) & 1) * 16;
        char* ah = smx + AH_OFF + r * ROWB + p * 32;
        char* al = smx + AL_OFF + r * ROWB + p * 32;
        *(uint4*)(ah + s)        = make_uint4(hp[0], hp[1], hp[2], hp[3]);
        *(uint4*)(ah + (16 ^ s)) = make_uint4(hp[4], hp[5], hp[6], hp[7]);
        *(uint4*)(al + s)        = make_uint4(lp[0], lp[1], lp[2], lp[3]);
        *(uint4*)(al + (16 ^ s)) = make_uint4(lp[4], lp[5], lp[6], lp[7]);
    }
    __syncthreads();

    // ---- MMA mainloop: r-sweep, B per dy from global (L1-resident) ----
    const int seg = wid;
    float D[TY][2][4];
#pragma unroll
    for (int y = 0; y < TY; y++)
#pragma unroll
        for (int t = 0; t < 2; t++)
#pragma unroll
            for (int j = 0; j < 4; j++) D[y][t][j] = 0.f;

    const int l15 = lane & 15;
    const int kh = lane >> 4;
    const uint4* bf4 = (const uint4*)bfrag;
    {
        u32 sw = (u32)((l15 >> 2) & 1);
        u32 aoff = (u32)(seg * 16 + l15) * 32 + (((u32)kh ^ sw) * 16);
        u32 aH = sb + AH_OFF + aoff;
        u32 aL = sb + AL_OFF + aoff;
#pragma unroll
        for (int r = 0; r < R; r++) {
            u32 Ah[4], Al[4];
            ldsm4(Ah, aH + r * ROWB);
            ldsm4(Al, aL + r * ROWB);
#pragma unroll
            for (int dy = 0; dy < K; dy++) {
                const int y = r - dy;
                if (y >= 0 && y < TY) {
                    uint4 BH = bf4[(dy * 2 + 0) * 32 + lane];
                    uint4 BL = bf4[(dy * 2 + 1) * 32 + lane];
                    mma16816(D[y][0], Ah, BH.x, BH.y);
                    mma16816(D[y][1], Ah, BH.z, BH.w);
                    mma16816(D[y][0], Al, BH.x, BH.y);
                    mma16816(D[y][1], Al, BH.z, BH.w);
                    mma16816(D[y][0], Ah, BL.x, BL.y);
                    mma16816(D[y][1], Ah, BL.z, BL.w);
                }
            }
        }
    }

    // ---- separable mask-sum conv + maxpool (lane owns rows half+2j) ----
    const int pxl = lane & 15, half = lane >> 4;
    float hsum[R], hmax[R];
    {
        const float* mb = sMk + seg * 16 + pxl;
#pragma unroll
        for (int r = 0; r < R; r++) {
            float s = 0.f, mx = 0.f;
#pragma unroll
            for (int dxm = 0; dxm < K; dxm++) {
                float m = mb[r * MW + dxm];
                s += m;
                mx = fmaxf(mx, m);
            }
            hsum[r] = s;
            hmax[r] = mx;
        }
    }
    float invv[4];
#pragma unroll
    for (int j = 0; j < 4; j++) {
        int y = half + 2 * j;
        float s = 0.f, mx = 0.f;
#pragma unroll
        for (int dy = 0; dy < K; dy++) {
            s += hsum[y + dy];
            mx = fmaxf(mx, hmax[y + dy]);
        }
        invv[j] = 1.0f / (s + 1e-8f);
        outM[(long long)n * HW + (long long)(y0 + y) * IMW + x0 + seg * 16 + pxl] = mx;
    }

    // ---- epilogue ----
    float bco[4];
#pragma unroll
    for (int t = 0; t < 2; t++)
#pragma unroll
        for (int j = 0; j < 2; j++)
            bco[t * 2 + j] = bias[t * 8 + (lane & 3) * 2 + j];
    float p1[4] = {0.f, 0.f, 0.f, 0.f}, p2[4] = {0.f, 0.f, 0.f, 0.f};
    const int pxa = seg * 16 + (lane >> 2);

#pragma unroll
    for (int y = 0; y < TY; y++) {
        float vsel = invv[y >> 1];
        float inva = __shfl_sync(0xffffffffu, vsel, ((y & 1) << 4) + (lane >> 2));
        float invb = __shfl_sync(0xffffffffu, vsel, ((y & 1) << 4) + (lane >> 2) + 8);
        int gy = y0 + y;
        float* hb = outH + (long long)n * 16 * HW + (long long)gy * IMW + x0;
#pragma unroll
        for (int t = 0; t < 2; t++) {
#pragma unroll
            for (int j = 0; j < 2; j++) {
                int co = t * 8 + (lane & 3) * 2 + j;
                float bc = bco[t * 2 + j];
                float v0 = fmaf(D[y][t][j], inva, bc);
                float v1 = fmaf(D[y][t][j + 2], invb, bc);
                hb[(long long)co * HW + pxa] = v0;
                hb[(long long)co * HW + pxa + 8] = v1;
                p1[t * 2 + j] += v0 + v1;
                p2[t * 2 + j] = fmaf(v0, v0, fmaf(v1, v1, p2[t * 2 + j]));
            }
        }
    }
#pragma unroll
    for (int k = 0; k < 4; k++) {
#pragma unroll
        for (int o = 4; o < 32; o <<= 1) {
            p1[k] += __shfl_xor_sync(0xffffffffu, p1[k], o);
            p2[k] += __shfl_xor_sync(0xffffffffu, p2[k], o);
        }
    }
    if (lane < 4) {
#pragma unroll
        for (int t = 0; t < 2; t++)
#pragma unroll
            for (int j = 0; j < 2; j++) {
                int co = t * 8 + lane * 2 + j;
                sR[(co * 2 + 0) * 4 + wid] = p1[t * 2 + j];
                sR[(co * 2 + 1) * 4 + wid] = p2[t * 2 + j];
            }
    }
    __syncthreads();
    if (tid < 32) {
        int co = tid >> 1, which = tid & 1;
        float v = sR[tid * 4 + 0] + sR[tid * 4 + 1] + sR[tid * 4 + 2] + sR[tid * 4 + 3];
        atomicAdd(&stats[which * 16 + co], (double)v);
    }
}

// ---------------------------------------------------------------------------
// Layer 6: 1x1 partial conv, 16 -> 1; float4 (4 px/thread); affine in-block.
// ---------------------------------------------------------------------------
__global__ void conv1x1_k(const float* __restrict__ h,
                          const float* __restrict__ mk,
                          const float* __restrict__ w6,
                          const float* __restrict__ b6,
                          const double* __restrict__ st5,
                          const float* __restrict__ g5,
                          const float* __restrict__ bt5,
                          float* __restrict__ y,
                          double* __restrict__ stats) {
    __shared__ float swv[16];
    __shared__ float2 sab[16];
    __shared__ float r1[8], r2[8];
    if (threadIdx.x < 16) {
        swv[threadIdx.x] = w6[threadIdx.x];
        double mean = st5[threadIdx.x] / (double)NPIX;
        double var  = st5[16 + threadIdx.x] / (double)NPIX - mean * mean;
        float inv = rsqrtf((float)var + 1e-5f);
        float a = g5[threadIdx.x] * inv;
        sab[threadIdx.x] = make_float2(a, bt5[threadIdx.x] - (float)mean * a);
    }
    __syncthreads();
    float bb = b6[0];
    float p1 = 0.f, p2 = 0.f;
    const float4* mk4 = (const float4*)mk;
    float4* y4 = (float4*)y;
    for (long long i = (long long)blockIdx.x * blockDim.x + threadIdx.x;
         i < 1LL * HW; i += (long long)gridDim.x * blockDim.x) {
        long long n = i >> 18;
        long long p4 = i & ((HW >> 2) - 1);
        float4 m = mk4[i];
        float4 acc = make_float4(0.f, 0.f, 0.f, 0.f);
        const float4* hb = (const float4*)(h + (n * 16) * HW) + p4;
#pragma unroll
        for (int c = 0; c < 16; c++) {
            float4 v = hb[(long long)c * (HW >> 2)];
            float2 ab = sab[c];
            float wv = swv[c];
            acc.x = fmaf(wv, fmaxf(fmaf(v.x, ab.x, ab.y), 0.f), acc.x);
            acc.y = fmaf(wv, fmaxf(fmaf(v.y, ab.x, ab.y), 0.f), acc.y);
            acc.z = fmaf(wv, fmaxf(fmaf(v.z, ab.x, ab.y), 0.f), acc.z);
            acc.w = fmaf(wv, fmaxf(fmaf(v.w, ab.x, ab.y), 0.f), acc.w);
        }
        float4 o;
        o.x = fmaf(acc.x * m.x, 1.0f / (m.x + 1e-8f), bb);
        o.y = fmaf(acc.y * m.y, 1.0f / (m.y + 1e-8f), bb);
        o.z = fmaf(acc.z * m.z, 1.0f / (m.z + 1e-8f), bb);
        o.w = fmaf(acc.w * m.w, 1.0f / (m.w + 1e-8f), bb);
        y4[i] = o;
        p1 += (o.x + o.y) + (o.z + o.w);
        p2 = fmaf(o.x, o.x, fmaf(o.y, o.y, fmaf(o.z, o.z, fmaf(o.w, o.w, p2))));
    }
#pragma unroll
    for (int o = 16; o; o >>= 1) {
        p1 += __shfl_xor_sync(0xffffffffu, p1, o);
        p2 += __shfl_xor_sync(0xffffffffu, p2, o);
    }
    int warp = threadIdx.x >> 5, lane = threadIdx.x & 31;
    if (lane == 0) { r1[warp] = p1; r2[warp] = p2; }
    __syncthreads();
    if (threadIdx.x == 0) {
        float a = 0.f, b = 0.f;
        for (int w = 0; w < (int)(blockDim.x >> 5); w++) { a += r1[w]; b += r2[w]; }
        atomicAdd(&stats[0], (double)a);
        atomicAdd(&stats[16], (double)b);
    }
}

// Final BN (no relu), float4; affine of layer 6 computed per block.
__global__ void final_k(const float* __restrict__ y,
                        const double* __restrict__ st6,
                        const float* __restrict__ g6,
                        const float* __restrict__ bt6,
                        float* __restrict__ o) {
    __shared__ float2 t;
    if (threadIdx.x == 0) {
        double mean = st6[0] / (double)NPIX;
        double var  = st6[16] / (double)NPIX - mean * mean;
        float inv = rsqrtf((float)var + 1e-5f);
        float a = g6[0] * inv;
        t = make_float2(a, bt6[0] - (float)mean * a);
    }
    __syncthreads();
    float2 tt = t;
    const float4* y4 = (const float4*)y;
    float4* o4 = (float4*)o;
    for (long long i = (long long)blockIdx.x * blockDim.x + threadIdx.x;
         i < 1LL * HW; i += (long long)gridDim.x * blockDim.x) {
        float4 v = y4[i];
        v.x = fmaf(v.x, tt.x, tt.y);
        v.y = fmaf(v.y, tt.x, tt.y);
        v.z = fmaf(v.z, tt.x, tt.y);
        v.w = fmaf(v.w, tt.x, tt.y);
        o4[i] = v;
    }
}

// ---------------------------------------------------------------------------
static constexpr int tmma_smem(int K) {
    int TY = 8, TILE = 64;
    int NPX = TILE + K - 1, NPXW = (NPX + 7) & ~7, R = K + TY - 1;
    int MK = 1024 + 128;
    int AH = ((MK + R * NPXW * 4 + 127) / 128) * 128;
    return AH + 2 * R * NPXW * 32;
}
static constexpr int tmma1_smem() {
    int R = 18, MW = 80, ROWB = 64 * 32;
    int XM = 1024 + R * MW * 4;
    int AH = ((XM + R * MW * 4 + 127) / 128) * 128;
    return AH + 2 * R * ROWB;
}

extern "C" void kernel_launch(void* const* d_in, const int* in_sizes, int n_in,
                              void* d_out, int out_size) {
    (void)in_sizes; (void)n_in; (void)out_size;
    const float* x = (const float*)d_in[0];
    const float *wp[6], *bp[6], *gp[6], *btp[6];
    for (int i = 0; i < 6; i++) {
        wp[i]  = (const float*)d_in[1 + 4 * i];
        bp[i]  = (const float*)d_in[2 + 4 * i];
        gp[i]  = (const float*)d_in[3 + 4 * i];
        btp[i] = (const float*)d_in[4 + 4 * i];
    }

    float *h0, *h1, *m0, *m1;
    double* st;
    u32* bf;
    cudaGetSymbolAddress((void**)&h0, g_h0);
    cudaGetSymbolAddress((void**)&h1, g_h1);
    cudaGetSymbolAddress((void**)&m0, g_m0);
    cudaGetSymbolAddress((void**)&m1, g_m1);
    cudaGetSymbolAddress((void**)&st, g_stats);
    cudaGetSymbolAddress((void**)&bf, g_bfrag);

    cudaFuncSetAttribute(tmma_conv1_k, cudaFuncAttributeMaxDynamicSharedMemorySize, tmma1_smem());
    cudaFuncSetAttribute(tmma_conv_k<7, true>, cudaFuncAttributeMaxDynamicSharedMemorySize, tmma_smem(7));
    cudaFuncSetAttribute(tmma_conv_k<5, true>, cudaFuncAttributeMaxDynamicSharedMemorySize, tmma_smem(5));
    cudaFuncSetAttribute(tmma_conv_k<3, true>, cudaFuncAttributeMaxDynamicSharedMemorySize, tmma_smem(3));

    dim3 t1grid(1024 / 64, 1024 / 8, 4);
    dim3 tgrid(1024 / 64, 1024 / 8, 4);

    u32* bf2 = bf;
    u32* bf3 = bf + 49 * 256;
    u32* bf4p = bf + 74 * 256;
    u32* bf5 = bf + 83 * 256;
    u32* bf1 = bf + 92 * 256;

    prep_all_b<<<26, 256>>>(wp[0], wp[1], wp[2], wp[3], wp[4], bf, st);

    tmma_conv1_k<<<t1grid, 128, tmma1_smem()>>>(
        x, 2LL * HW, x + HW, 2LL * HW, bf1, bp[0], h0, m0, st + 0);

    tmma_conv_k<7, true><<<tgrid, 128, tmma_smem(7)>>>(
        h0, 16LL * HW, m0, (long long)HW, bf2, bp[1],
        st + 0, gp[0], btp[0], h1, m1, st + 32);

    tmma_conv_k<5, true><<<tgrid, 128, tmma_smem(5)>>>(
        h1, 16LL * HW, m1, (long long)HW, bf3, bp[2],
        st + 32, gp[1], btp[1], h0, m0, st + 64);

    tmma_conv_k<3, true><<<tgrid, 128, tmma_smem(3)>>>(
        h0, 16LL * HW, m0, (long long)HW, bf4p, bp[3],
        st + 64, gp[2], btp[2], h1, m1, st + 96);

    tmma_conv_k<3, true><<<tgrid, 128, tmma_smem(3)>>>(
        h1, 16LL * HW, m1, (long long)HW, bf5, bp[4],
        st + 96, gp[3], btp[3], h0, m0, st + 128);

    conv1x1_k<<<1184, 256>>>(h0, m0, wp[5], bp[5],
                             st + 128, gp[4], btp[4], h1, st + 160);

    final_k<<<2048, 256>>>(h1, st + 160, gp[5], btp[5], (float*)d_out);
}